// round 3
// baseline (speedup 1.0000x reference)
#include <cuda_runtime.h>
#include <math.h>

// Problem constants
#define Bz 64
#define Tz 512
#define Dz 512
#define Hz 512
#define G4 (4*Hz)        // 2048 gates per direction
#define NG (2*G4)        // 4096 gates both directions (fused GEMM N)
#define NCTA 128         // persistent recurrence CTAs (2 dirs x 64 n-chunks)
#define XOUT ((size_t)Bz*Tz*2*Hz)   // 33,554,432 floats in x output section

// Scratch (static device globals — no allocation)
__device__ float g_xg[(size_t)Tz*Bz*NG];       // [t][b][dir*2048 + gate*512 + n]
__device__ float g_y0[(size_t)Bz*Tz*2*Hz];     // layer0 output, [b][t][dir*512+n]
__device__ float g_h[2][2*Bz*Hz];              // ping-pong h: [par][dir][b][n]
__device__ float g_c[2*Bz*Hz];                 // c: [dir][b][n]
__device__ unsigned g_bar;                     // grid barrier counter (self-resetting)
__device__ unsigned g_done;                    // exit counter (self-resetting)

// ---------------------------------------------------------------------------
// Input projection GEMM: xg[m][j] = sum_k X[b][t][k] * W[j][k] + bias[j]
// m = t*B + b. j < 2048 -> forward weights, j >= 2048 -> backward.
// 128x128 tile, 8x8 per thread, K-step 8.
// ---------------------------------------------------------------------------
__global__ void __launch_bounds__(256)
gemm_xg(const float* __restrict__ X, int K,
        const float* __restrict__ Wf, const float* __restrict__ Wb,
        const float* __restrict__ bf, const float* __restrict__ bb)
{
    __shared__ float As[8][128];
    __shared__ float Bs[8][128];

    const int tid = threadIdx.x;
    const int tx  = tid & 15;
    const int ty  = tid >> 4;
    const int m0  = blockIdx.y * 128;
    const int n0  = blockIdx.x * 128;

    const int a_m = tid >> 1;
    const int a_k = (tid & 1) * 4;
    const int b_n = tid >> 1;
    const int b_k = (tid & 1) * 4;

    const int m_ld = m0 + a_m;
    const float* Arow = X + (size_t)(m_ld & 63) * Tz * K + (size_t)(m_ld >> 6) * K;
    const int n_ld = n0 + b_n;
    const float* Brow = (n_ld < G4) ? (Wf + (size_t)n_ld * K)
                                    : (Wb + (size_t)(n_ld - G4) * K);

    float acc[8][8];
#pragma unroll
    for (int i = 0; i < 8; i++)
#pragma unroll
        for (int j = 0; j < 8; j++) acc[i][j] = 0.f;

    for (int k0 = 0; k0 < K; k0 += 8) {
        float4 av = *(const float4*)(Arow + k0 + a_k);
        float4 bv = *(const float4*)(Brow + k0 + b_k);
        __syncthreads();
        As[a_k + 0][a_m] = av.x;
        As[a_k + 1][a_m] = av.y;
        As[a_k + 2][a_m] = av.z;
        As[a_k + 3][a_m] = av.w;
        Bs[b_k + 0][b_n] = bv.x;
        Bs[b_k + 1][b_n] = bv.y;
        Bs[b_k + 2][b_n] = bv.z;
        Bs[b_k + 3][b_n] = bv.w;
        __syncthreads();
#pragma unroll
        for (int kk = 0; kk < 8; kk++) {
            float a[8], b[8];
            *(float4*)(a)     = *(const float4*)&As[kk][ty * 8];
            *(float4*)(a + 4) = *(const float4*)&As[kk][ty * 8 + 4];
            *(float4*)(b)     = *(const float4*)&Bs[kk][tx * 8];
            *(float4*)(b + 4) = *(const float4*)&Bs[kk][tx * 8 + 4];
#pragma unroll
            for (int i = 0; i < 8; i++)
#pragma unroll
                for (int j = 0; j < 8; j++)
                    acc[i][j] += a[i] * b[j];
        }
    }

    float bias[8];
#pragma unroll
    for (int j = 0; j < 8; j++) {
        int n = n0 + tx * 8 + j;
        bias[j] = (n < G4) ? bf[n] : bb[n - G4];
    }
#pragma unroll
    for (int i = 0; i < 8; i++) {
        int m = m0 + ty * 8 + i;
        float* dst = &g_xg[(size_t)m * NG + n0 + tx * 8];
        float4 v0 = make_float4(acc[i][0] + bias[0], acc[i][1] + bias[1],
                                acc[i][2] + bias[2], acc[i][3] + bias[3]);
        float4 v1 = make_float4(acc[i][4] + bias[4], acc[i][5] + bias[5],
                                acc[i][6] + bias[6], acc[i][7] + bias[7]);
        *(float4*)(dst)     = v0;
        *(float4*)(dst + 4) = v1;
    }
}

// ---------------------------------------------------------------------------
// Persistent recurrence kernel: one launch runs all 512 steps for both
// directions of one layer. 128 CTAs (dir = bid>>6, n-chunk of 8 = bid&63),
// all co-resident (1 CTA/SM, 97.7KB smem). Wh slice (32 rows x 512 K = 64KB)
// loaded to smem ONCE, reused for all steps. Steps separated by a software
// grid barrier (atomic counter, monotonic targets, self-reset at exit).
// ---------------------------------------------------------------------------

// smem layout (floats)
#define WS_OFF 0
#define WS_SZ  (512*34)          // [k][r] stride 34 (8B-aligned float2 rows)
#define HS_OFF (WS_OFF + WS_SZ)
#define HS_SZ  (64*68)           // [kk][b] stride 68 (16B-aligned float4 rows)
#define GS_OFF (HS_OFF + HS_SZ)
#define GS_SZ  (32*65)           // [r][b] exchange
#define CS_OFF (GS_OFF + GS_SZ)
#define CS_SZ  (512)             // c state [b*8+nl]
#define LS_OFF (CS_OFF + CS_SZ)
#define LS_SZ  (64)              // lengths cache
#define SMEM_FLOATS (LS_OFF + LS_SZ)
#define SMEM_BYTES  (SMEM_FLOATS * 4)

__device__ __forceinline__ void grid_barrier(unsigned target)
{
    __syncthreads();
    if (threadIdx.x == 0) {
        __threadfence();
        atomicAdd(&g_bar, 1u);
        int backoff = 32;
        for (;;) {
            unsigned v;
            asm volatile("ld.acquire.gpu.global.u32 %0, [%1];"
                         : "=r"(v) : "l"(&g_bar));
            if (v >= target) break;
            __nanosleep(backoff);
            if (backoff < 256) backoff <<= 1;
        }
    }
    __syncthreads();
}

__global__ void __launch_bounds__(256)
lstm_layer(const float* __restrict__ Whf, const float* __restrict__ Whb,
           const int* __restrict__ lengths, float* __restrict__ Y)
{
    extern __shared__ float smem[];
    float* ws = smem + WS_OFF;
    float* hs = smem + HS_OFF;
    float* gs = smem + GS_OFF;
    float* cs = smem + CS_OFF;
    int*   ls = (int*)(smem + LS_OFF);

    const int bid = blockIdx.x;
    const int dir = bid >> 6;
    const int n0  = (bid & 63) * 8;
    const float* Wh = dir ? Whb : Whf;

    const int tid = threadIdx.x;
    const int tb  = tid & 15;   // b block: b = tb*4 + i
    const int tr  = tid >> 4;   // r pair : r = tr*2 + j

    // one-time loads: Wh slice -> ws[k*34 + r], r = gate*8 + nl
    for (int idx = tid; idx < 32 * 512; idx += 256) {
        int r = idx >> 9;
        int k = idx & 511;
        int j = (r >> 3) * Hz + n0 + (r & 7);
        ws[k * 34 + r] = Wh[(size_t)j * Hz + k];
    }
    for (int i = tid; i < 512; i += 256) cs[i] = 0.f;
    if (tid < 64) ls[tid] = lengths[tid];
    __syncthreads();

    for (int s = 0; s < Tz; s++) {
        const int t = dir ? (Tz - 1 - s) : s;
        const float* hin  = g_h[s & 1]       + dir * Bz * Hz;
        float*       hout = g_h[(s & 1) ^ 1] + dir * Bz * Hz;

        float acc[4][2];
#pragma unroll
        for (int i = 0; i < 4; i++) { acc[i][0] = 0.f; acc[i][1] = 0.f; }

        for (int kt = 0; kt < 8; kt++) {
            __syncthreads();
            // load h tile [64 k][64 b]
            {
                int lb = tid >> 2;
                int lk = (tid & 3) * 16;
                const float* src = hin + lb * Hz + kt * 64 + lk;
#pragma unroll
                for (int q = 0; q < 4; q++) {
                    float4 v = *(const float4*)(src + q * 4);
                    hs[(lk + q * 4 + 0) * 68 + lb] = v.x;
                    hs[(lk + q * 4 + 1) * 68 + lb] = v.y;
                    hs[(lk + q * 4 + 2) * 68 + lb] = v.z;
                    hs[(lk + q * 4 + 3) * 68 + lb] = v.w;
                }
            }
            __syncthreads();
            const float* wsk = ws + (kt * 64) * 34;
#pragma unroll 16
            for (int kk = 0; kk < 64; kk++) {
                float4 a = *(const float4*)&hs[kk * 68 + tb * 4];
                float2 w = *(const float2*)&wsk[kk * 34 + tr * 2];
                acc[0][0] += a.x * w.x;  acc[0][1] += a.x * w.y;
                acc[1][0] += a.y * w.x;  acc[1][1] += a.y * w.y;
                acc[2][0] += a.z * w.x;  acc[2][1] += a.z * w.y;
                acc[3][0] += a.w * w.x;  acc[3][1] += a.w * w.y;
            }
        }
        __syncthreads();
#pragma unroll
        for (int j = 0; j < 2; j++)
#pragma unroll
            for (int i = 0; i < 4; i++)
                gs[(tr * 2 + j) * 65 + tb * 4 + i] = acc[i][j];
        __syncthreads();

        // output phase: 512 (b,nl) outputs, 2 per thread
#pragma unroll
        for (int o = tid; o < 512; o += 256) {
            int nl = o & 7;
            int b  = o >> 3;
            int n  = n0 + nl;
            const float* xgp = g_xg + ((size_t)t * Bz + b) * NG + (size_t)dir * G4;
            float gi = gs[(0 * 8 + nl) * 65 + b] + xgp[0 * Hz + n];
            float gf = gs[(1 * 8 + nl) * 65 + b] + xgp[1 * Hz + n];
            float gg = gs[(2 * 8 + nl) * 65 + b] + xgp[2 * Hz + n];
            float go = gs[(3 * 8 + nl) * 65 + b] + xgp[3 * Hz + n];
            float iv = 1.f / (1.f + expf(-gi));
            float fv = 1.f / (1.f + expf(-gf));
            float gv = tanhf(gg);
            float ov = 1.f / (1.f + expf(-go));
            float cold = cs[o];
            float hold = hin[b * Hz + n];
            float cn = fv * cold + iv * gv;
            float hn = ov * tanhf(cn);
            bool m = (t < ls[b]);
            hout[b * Hz + n] = m ? hn : hold;
            cs[o]            = m ? cn : cold;
            Y[((size_t)b * Tz + t) * (2 * Hz) + (size_t)dir * Hz + n] = m ? hn : 0.f;
        }

        if (s < Tz - 1) grid_barrier((unsigned)(s + 1) * NCTA);
    }

    // write final c state to global for copy_states
    __syncthreads();
    for (int o = tid; o < 512; o += 256)
        g_c[dir * Bz * Hz + (o >> 3) * Hz + n0 + (o & 7)] = cs[o];

    // self-resetting exit: last CTA zeroes the barrier counters so the next
    // launch (and every graph replay) starts from a clean state.
    __threadfence();
    __syncthreads();
    if (tid == 0) {
        unsigned d = atomicAdd(&g_done, 1u);
        if (d == NCTA - 1) {
            atomicExch(&g_bar, 0u);
            atomicExch(&g_done, 0u);
            __threadfence();
        }
    }
}

// copy final states (in g_h[0] after 512 steps) into d_out hN/cN sections
__global__ void copy_states(float* __restrict__ out_h, float* __restrict__ out_c)
{
    int i = blockIdx.x * blockDim.x + threadIdx.x;
    if (i < 2 * Bz * Hz) {
        out_h[i] = g_h[0][i];
        out_c[i] = g_c[i];
    }
}

extern "C" void kernel_launch(void* const* d_in, const int* in_sizes, int n_in,
                              void* d_out, int out_size)
{
    const float* x      = (const float*)d_in[0];
    const int*  lengths = (const int*)  d_in[1];
    const float* Wi_f0 = (const float*)d_in[2];
    const float* Wh_f0 = (const float*)d_in[3];
    const float* b_f0  = (const float*)d_in[4];
    const float* Wi_b0 = (const float*)d_in[5];
    const float* Wh_b0 = (const float*)d_in[6];
    const float* b_b0  = (const float*)d_in[7];
    const float* Wi_f1 = (const float*)d_in[8];
    const float* Wh_f1 = (const float*)d_in[9];
    const float* b_f1  = (const float*)d_in[10];
    const float* Wi_b1 = (const float*)d_in[11];
    const float* Wh_b1 = (const float*)d_in[12];
    const float* b_b1  = (const float*)d_in[13];
    float* out = (float*)d_out;

    cudaFuncSetAttribute(lstm_layer,
                         cudaFuncAttributeMaxDynamicSharedMemorySize, SMEM_BYTES);

    float *hptr, *cptr, *y0p;
    cudaGetSymbolAddress((void**)&hptr, g_h);
    cudaGetSymbolAddress((void**)&cptr, g_c);
    cudaGetSymbolAddress((void**)&y0p,  g_y0);

    const dim3 gemm_grid(NG / 128, (Bz * Tz) / 128);
    const int  copy_blocks = (2 * Bz * Hz + 255) / 256;

    // ---- layer 0 ----
    cudaMemsetAsync(hptr, 0, sizeof(float) * 2 * 2 * Bz * Hz);  // both ping buffers
    gemm_xg<<<gemm_grid, 256>>>(x, Dz, Wi_f0, Wi_b0, b_f0, b_b0);
    lstm_layer<<<NCTA, 256, SMEM_BYTES>>>(Wh_f0, Wh_b0, lengths, y0p);
    copy_states<<<copy_blocks, 256>>>(out + XOUT,
                                      out + XOUT + 4 * Bz * Hz);

    // ---- layer 1 ----
    cudaMemsetAsync(hptr, 0, sizeof(float) * 2 * 2 * Bz * Hz);
    gemm_xg<<<gemm_grid, 256>>>(y0p, 2 * Hz, Wi_f1, Wi_b1, b_f1, b_b1);
    lstm_layer<<<NCTA, 256, SMEM_BYTES>>>(Wh_f1, Wh_b1, lengths, out);
    copy_states<<<copy_blocks, 256>>>(out + XOUT + 2 * Bz * Hz,
                                      out + XOUT + 4 * Bz * Hz + 2 * Bz * Hz);
}

// round 5
// speedup vs baseline: 1.2483x; 1.2483x over previous
#include <cuda_runtime.h>
#include <cuda_bf16.h>
#include <math.h>
#include <stdint.h>

// Problem constants
#define Bz 64
#define Tz 512
#define Dz 512
#define Hz 512
#define G4 (4*Hz)        // 2048 gates per direction
#define NG (2*G4)        // 4096 gates both directions (fused GEMM N)
#define Mz (Bz*Tz)       // 32768 GEMM rows
#define NCTA 128         // persistent recurrence CTAs
#define XOUT ((size_t)Bz*Tz*2*Hz)

// Scratch (static device globals — no allocation)
__device__ float g_xg[(size_t)Tz*Bz*NG];       // [t*B+b][dir*2048 + gate*512 + n]
__device__ float g_y0[(size_t)Bz*Tz*2*Hz];     // layer0 output, [b][t][dir*512+n]
__device__ float g_h[2][2*Bz*Hz];              // ping-pong h
__device__ float g_c[2*Bz*Hz];                 // c
__device__ unsigned g_bar;
__device__ unsigned g_done;
// bf16 hi/lo split operands for tensor-core GEMM (K-major rows)
__device__ __align__(16) __nv_bfloat16 g_Ah[(size_t)Mz*1024];
__device__ __align__(16) __nv_bfloat16 g_Al[(size_t)Mz*1024];
__device__ __align__(16) __nv_bfloat16 g_Bh[(size_t)NG*1024];
__device__ __align__(16) __nv_bfloat16 g_Bl[(size_t)NG*1024];

// ===========================================================================
// PTX helpers — only baseline (non-'a') features: mma.sync, ldmatrix, cp.async
// ===========================================================================
__device__ __forceinline__ uint32_t smem_u32(const void* p) {
    uint32_t a;
    asm("{ .reg .u64 t; cvta.to.shared.u64 t, %1; cvt.u32.u64 %0, t; }"
        : "=r"(a) : "l"(p));
    return a;
}
__device__ __forceinline__ void ldsm4(uint32_t* r, uint32_t addr) {
    asm volatile("ldmatrix.sync.aligned.m8n8.x4.shared.b16 {%0,%1,%2,%3}, [%4];"
                 : "=r"(r[0]), "=r"(r[1]), "=r"(r[2]), "=r"(r[3]) : "r"(addr));
}
__device__ __forceinline__ void mma16816(float* c, const uint32_t* a, const uint32_t* b) {
    asm volatile("mma.sync.aligned.m16n8k16.row.col.f32.bf16.bf16.f32 "
                 "{%0,%1,%2,%3}, {%4,%5,%6,%7}, {%8,%9}, {%0,%1,%2,%3};"
                 : "+f"(c[0]), "+f"(c[1]), "+f"(c[2]), "+f"(c[3])
                 : "r"(a[0]), "r"(a[1]), "r"(a[2]), "r"(a[3]),
                   "r"(b[0]), "r"(b[1]));
}
#define CP_ASYNC16(dst, src) \
    asm volatile("cp.async.cg.shared.global [%0], [%1], 16;" :: "r"(dst), "l"(src))
#define CP_COMMIT() asm volatile("cp.async.commit_group;" ::: "memory")
#define CP_WAIT1()  asm volatile("cp.async.wait_group 1;" ::: "memory")
#define CP_WAIT0()  asm volatile("cp.async.wait_group 0;" ::: "memory")

// ===========================================================================
// Conversion: fp32 -> bf16 hi + bf16 lo, with [b][t] -> m=t*B+b transpose.
// ===========================================================================
__global__ void __launch_bounds__(128)
split_x(const float* __restrict__ src, int K,
        __nv_bfloat16* __restrict__ dh, __nv_bfloat16* __restrict__ dl)
{
    const int m = blockIdx.x;
    const int k = blockIdx.y * 512 + threadIdx.x * 4;
    const int srow = (m & 63) * Tz + (m >> 6);
    float4 v = *(const float4*)(src + (size_t)srow * K + k);
    __nv_bfloat16 h0 = __float2bfloat16(v.x);
    __nv_bfloat16 h1 = __float2bfloat16(v.y);
    __nv_bfloat16 h2 = __float2bfloat16(v.z);
    __nv_bfloat16 h3 = __float2bfloat16(v.w);
    __nv_bfloat16 l0 = __float2bfloat16(v.x - __bfloat162float(h0));
    __nv_bfloat16 l1 = __float2bfloat16(v.y - __bfloat162float(h1));
    __nv_bfloat16 l2 = __float2bfloat16(v.z - __bfloat162float(h2));
    __nv_bfloat16 l3 = __float2bfloat16(v.w - __bfloat162float(h3));
    size_t o = (size_t)m * K + k;
    *(__nv_bfloat162*)(dh + o)     = __halves2bfloat162(h0, h1);
    *(__nv_bfloat162*)(dh + o + 2) = __halves2bfloat162(h2, h3);
    *(__nv_bfloat162*)(dl + o)     = __halves2bfloat162(l0, l1);
    *(__nv_bfloat162*)(dl + o + 2) = __halves2bfloat162(l2, l3);
}

__global__ void __launch_bounds__(128)
split_w(const float* __restrict__ Wf, const float* __restrict__ Wb, int K)
{
    const int n = blockIdx.x;
    const int k = blockIdx.y * 512 + threadIdx.x * 4;
    const float* src = (n < G4) ? (Wf + (size_t)n * K) : (Wb + (size_t)(n - G4) * K);
    float4 v = *(const float4*)(src + k);
    __nv_bfloat16 h0 = __float2bfloat16(v.x);
    __nv_bfloat16 h1 = __float2bfloat16(v.y);
    __nv_bfloat16 h2 = __float2bfloat16(v.z);
    __nv_bfloat16 h3 = __float2bfloat16(v.w);
    __nv_bfloat16 l0 = __float2bfloat16(v.x - __bfloat162float(h0));
    __nv_bfloat16 l1 = __float2bfloat16(v.y - __bfloat162float(h1));
    __nv_bfloat16 l2 = __float2bfloat16(v.z - __bfloat162float(h2));
    __nv_bfloat16 l3 = __float2bfloat16(v.w - __bfloat162float(h3));
    size_t o = (size_t)n * K + k;
    *(__nv_bfloat162*)(g_Bh + o)     = __halves2bfloat162(h0, h1);
    *(__nv_bfloat162*)(g_Bh + o + 2) = __halves2bfloat162(h2, h3);
    *(__nv_bfloat162*)(g_Bl + o)     = __halves2bfloat162(l0, l1);
    *(__nv_bfloat162*)(g_Bl + o + 2) = __halves2bfloat162(l2, l3);
}

// ===========================================================================
// bf16 mma.sync GEMM with 3-term compensation:
//   xg[m][n] = sum_k (Ah+Al)[m][k]*(Bh+Bl)[n][k] + bias[n]   (drop Al*Bl)
// CTA tile 128x128, 8 warps (2x4), warp tile 64x32, K-chunks of 64.
// Double-buffered cp.async pipeline.
// Smem tile layout: rows of 128B (64 bf16), SW128 swizzle -> XOR (row&7)<<4.
// ===========================================================================
#define TILE_B  16384                    // one 128x64 bf16 tile
#define BUF_B   (4*TILE_B)               // Ah, Al, Bh, Bl
#define BIAS_OFF (2*BUF_B)               // 131072
#define SMEM_TC  (BIAS_OFF + 512)        // 131584 bytes

__global__ void __launch_bounds__(256, 1)
gemm_mma(int K, const float* __restrict__ bfp, const float* __restrict__ bbp)
{
    extern __shared__ char smem[];
    const uint32_t sbase = smem_u32(smem);
    const int tid  = threadIdx.x;
    const int wid  = tid >> 5;
    const int lane = tid & 31;
    const int n0 = blockIdx.x * 128;
    const int m0 = blockIdx.y * 128;
    const int nchunks = K / 64;

    float* bias_s = (float*)(smem + BIAS_OFF);
    if (tid < 128) {
        int n = n0 + tid;
        bias_s[tid] = (n < G4) ? bfp[n] : bbp[n - G4];
    }

    // gmem tile sources (row-major, K-contiguous)
    const char* tsrc[4];
    tsrc[0] = (const char*)(g_Ah + (size_t)m0 * K);
    tsrc[1] = (const char*)(g_Al + (size_t)m0 * K);
    tsrc[2] = (const char*)(g_Bh + (size_t)n0 * K);
    tsrc[3] = (const char*)(g_Bl + (size_t)n0 * K);

    // loader assignment: 4 iters x 256 threads cover 1024 x 16B per tile
    const int l_row = tid >> 3;          // 0..31 (+32 per iter)
    const int l_g   = tid & 7;           // 16B group within 128B row

    // issue cp.async for one chunk into buffer b
    auto load_chunk = [&](int c, int b) {
#pragma unroll
        for (int t4 = 0; t4 < 4; t4++) {
            const char* src0 = tsrc[t4] + (size_t)c * 128;
            uint32_t dst0 = sbase + b * BUF_B + t4 * TILE_B;
#pragma unroll
            for (int i = 0; i < 4; i++) {
                int row = l_row + i * 32;
                uint32_t dst = dst0 + row * 128 + ((l_g * 16) ^ ((row & 7) << 4));
                CP_ASYNC16(dst, src0 + (size_t)row * K * 2 + l_g * 16);
            }
        }
    };

    // warp tiling: warp_m in {0,1} (64 rows), warp_n in {0..3} (32 cols)
    const int m0w = (wid & 1) * 64;
    const int n0w = (wid >> 1) * 32;

    // ldmatrix per-thread base addresses (swizzle folded in; k via XOR)
    // A: mats (rows0-7,k0)(rows8-15,k0)(rows0-7,k8)(rows8-15,k8)
    uint32_t aBase[4];
    const int a_row_l = (lane & 15);
    const uint32_t a_klane = (lane >> 4) * 16;
#pragma unroll
    for (int mi = 0; mi < 4; mi++) {
        int row = m0w + mi * 16 + a_row_l;
        aBase[mi] = row * 128 + ((row & 7) << 4);
    }
    // B: mats (n0-7,k0)(n0-7,k8)(n8-15,k0)(n8-15,k8)
    uint32_t bBase[2];
    const int b_row_l = ((lane >> 4) * 8) + (lane & 7);
    const uint32_t b_klane = ((lane >> 3) & 1) * 16;
#pragma unroll
    for (int nj = 0; nj < 2; nj++) {
        int row = n0w + nj * 16 + b_row_l;
        bBase[nj] = row * 128 + ((row & 7) << 4);
    }

    float c[4][4][4];
#pragma unroll
    for (int mi = 0; mi < 4; mi++)
#pragma unroll
        for (int ni = 0; ni < 4; ni++)
#pragma unroll
            for (int q = 0; q < 4; q++) c[mi][ni][q] = 0.f;

    // pipeline prologue
    load_chunk(0, 0); CP_COMMIT();
    if (nchunks > 1) { load_chunk(1, 1); CP_COMMIT(); }

    for (int ch = 0; ch < nchunks; ch++) {
        if (ch == nchunks - 1) CP_WAIT0(); else CP_WAIT1();
        __syncthreads();

        const uint32_t bufA_h = sbase + (ch & 1) * BUF_B;
        const uint32_t bufA_l = bufA_h + TILE_B;
        const uint32_t bufB_h = bufA_h + 2 * TILE_B;
        const uint32_t bufB_l = bufA_h + 3 * TILE_B;

#pragma unroll
        for (int ks = 0; ks < 4; ks++) {
            const uint32_t kbA = ks * 32 + a_klane;
            const uint32_t kbB = ks * 32 + b_klane;
            uint32_t ah[4][4], al[4][4], bh[4][2], bl[4][2];
#pragma unroll
            for (int mi = 0; mi < 4; mi++) {
                ldsm4(ah[mi], (bufA_h + aBase[mi]) ^ kbA);
                ldsm4(al[mi], (bufA_l + aBase[mi]) ^ kbA);
            }
#pragma unroll
            for (int nj = 0; nj < 2; nj++) {
                uint32_t r[4];
                ldsm4(r, (bufB_h + bBase[nj]) ^ kbB);
                bh[nj * 2][0] = r[0]; bh[nj * 2][1] = r[1];
                bh[nj * 2 + 1][0] = r[2]; bh[nj * 2 + 1][1] = r[3];
                ldsm4(r, (bufB_l + bBase[nj]) ^ kbB);
                bl[nj * 2][0] = r[0]; bl[nj * 2][1] = r[1];
                bl[nj * 2 + 1][0] = r[2]; bl[nj * 2 + 1][1] = r[3];
            }
#pragma unroll
            for (int mi = 0; mi < 4; mi++)
#pragma unroll
                for (int ni = 0; ni < 4; ni++) {
                    mma16816(c[mi][ni], ah[mi], bh[ni]);
                    mma16816(c[mi][ni], ah[mi], bl[ni]);
                    mma16816(c[mi][ni], al[mi], bh[ni]);
                }
        }
        __syncthreads();
        if (ch + 2 < nchunks) { load_chunk(ch + 2, ch & 1); CP_COMMIT(); }
    }

    // epilogue: add bias, write fp32 to g_xg
    const int er = lane >> 2;           // 0..7
    const int ec = (lane & 3) * 2;      // 0,2,4,6
#pragma unroll
    for (int mi = 0; mi < 4; mi++) {
        int row0 = m0 + m0w + mi * 16 + er;
#pragma unroll
        for (int ni = 0; ni < 4; ni++) {
            int nloc = n0w + ni * 8 + ec;
            int coln = n0 + nloc;
            float b0 = bias_s[nloc], b1 = bias_s[nloc + 1];
            float* p0 = g_xg + (size_t)row0 * NG + coln;
            float* p1 = g_xg + (size_t)(row0 + 8) * NG + coln;
            *(float2*)p0 = make_float2(c[mi][ni][0] + b0, c[mi][ni][1] + b1);
            *(float2*)p1 = make_float2(c[mi][ni][2] + b0, c[mi][ni][3] + b1);
        }
    }
}

// ===========================================================================
// Persistent recurrence kernel (unchanged from R3 — proven correct)
// ===========================================================================
#define WS_OFF 0
#define WS_SZ  (512*34)
#define HS_OFF (WS_OFF + WS_SZ)
#define HS_SZ  (64*68)
#define GS_OFF (HS_OFF + HS_SZ)
#define GS_SZ  (32*65)
#define CS_OFF (GS_OFF + GS_SZ)
#define CS_SZ  (512)
#define LS_OFF (CS_OFF + CS_SZ)
#define LS_SZ  (64)
#define SMEM_FLOATS (LS_OFF + LS_SZ)
#define SMEM_BYTES  (SMEM_FLOATS * 4)

__device__ __forceinline__ void grid_barrier(unsigned target)
{
    __syncthreads();
    if (threadIdx.x == 0) {
        __threadfence();
        atomicAdd(&g_bar, 1u);
        int backoff = 32;
        for (;;) {
            unsigned v;
            asm volatile("ld.acquire.gpu.global.u32 %0, [%1];"
                         : "=r"(v) : "l"(&g_bar));
            if (v >= target) break;
            __nanosleep(backoff);
            if (backoff < 256) backoff <<= 1;
        }
    }
    __syncthreads();
}

__global__ void __launch_bounds__(256)
lstm_layer(const float* __restrict__ Whf, const float* __restrict__ Whb,
           const int* __restrict__ lengths, float* __restrict__ Y)
{
    extern __shared__ float smemf[];
    float* ws = smemf + WS_OFF;
    float* hs = smemf + HS_OFF;
    float* gs = smemf + GS_OFF;
    float* cs = smemf + CS_OFF;
    int*   ls = (int*)(smemf + LS_OFF);

    const int bid = blockIdx.x;
    const int dir = bid >> 6;
    const int n0  = (bid & 63) * 8;
    const float* Wh = dir ? Whb : Whf;

    const int tid = threadIdx.x;
    const int tb  = tid & 15;
    const int tr  = tid >> 4;

    for (int idx = tid; idx < 32 * 512; idx += 256) {
        int r = idx >> 9;
        int k = idx & 511;
        int j = (r >> 3) * Hz + n0 + (r & 7);
        ws[k * 34 + r] = Wh[(size_t)j * Hz + k];
    }
    for (int i = tid; i < 512; i += 256) cs[i] = 0.f;
    if (tid < 64) ls[tid] = lengths[tid];
    __syncthreads();

    for (int s = 0; s < Tz; s++) {
        const int t = dir ? (Tz - 1 - s) : s;
        const float* hin  = g_h[s & 1]       + dir * Bz * Hz;
        float*       hout = g_h[(s & 1) ^ 1] + dir * Bz * Hz;

        float acc[4][2];
#pragma unroll
        for (int i = 0; i < 4; i++) { acc[i][0] = 0.f; acc[i][1] = 0.f; }

        for (int kt = 0; kt < 8; kt++) {
            __syncthreads();
            {
                int lb = tid >> 2;
                int lk = (tid & 3) * 16;
                const float* src = hin + lb * Hz + kt * 64 + lk;
#pragma unroll
                for (int q = 0; q < 4; q++) {
                    float4 v = *(const float4*)(src + q * 4);
                    hs[(lk + q * 4 + 0) * 68 + lb] = v.x;
                    hs[(lk + q * 4 + 1) * 68 + lb] = v.y;
                    hs[(lk + q * 4 + 2) * 68 + lb] = v.z;
                    hs[(lk + q * 4 + 3) * 68 + lb] = v.w;
                }
            }
            __syncthreads();
            const float* wsk = ws + (kt * 64) * 34;
#pragma unroll 16
            for (int kk = 0; kk < 64; kk++) {
                float4 a = *(const float4*)&hs[kk * 68 + tb * 4];
                float2 w = *(const float2*)&wsk[kk * 34 + tr * 2];
                acc[0][0] += a.x * w.x;  acc[0][1] += a.x * w.y;
                acc[1][0] += a.y * w.x;  acc[1][1] += a.y * w.y;
                acc[2][0] += a.z * w.x;  acc[2][1] += a.z * w.y;
                acc[3][0] += a.w * w.x;  acc[3][1] += a.w * w.y;
            }
        }
        __syncthreads();
#pragma unroll
        for (int j = 0; j < 2; j++)
#pragma unroll
            for (int i = 0; i < 4; i++)
                gs[(tr * 2 + j) * 65 + tb * 4 + i] = acc[i][j];
        __syncthreads();

#pragma unroll
        for (int o = tid; o < 512; o += 256) {
            int nl = o & 7;
            int b  = o >> 3;
            int n  = n0 + nl;
            const float* xgp = g_xg + ((size_t)t * Bz + b) * NG + (size_t)dir * G4;
            float gi = gs[(0 * 8 + nl) * 65 + b] + xgp[0 * Hz + n];
            float gf = gs[(1 * 8 + nl) * 65 + b] + xgp[1 * Hz + n];
            float gg = gs[(2 * 8 + nl) * 65 + b] + xgp[2 * Hz + n];
            float go = gs[(3 * 8 + nl) * 65 + b] + xgp[3 * Hz + n];
            float iv = 1.f / (1.f + expf(-gi));
            float fv = 1.f / (1.f + expf(-gf));
            float gv = tanhf(gg);
            float ov = 1.f / (1.f + expf(-go));
            float cold = cs[o];
            float hold = hin[b * Hz + n];
            float cn = fv * cold + iv * gv;
            float hn = ov * tanhf(cn);
            bool m = (t < ls[b]);
            hout[b * Hz + n] = m ? hn : hold;
            cs[o]            = m ? cn : cold;
            Y[((size_t)b * Tz + t) * (2 * Hz) + (size_t)dir * Hz + n] = m ? hn : 0.f;
        }

        if (s < Tz - 1) grid_barrier((unsigned)(s + 1) * NCTA);
    }

    __syncthreads();
    for (int o = tid; o < 512; o += 256)
        g_c[dir * Bz * Hz + (o >> 3) * Hz + n0 + (o & 7)] = cs[o];

    __threadfence();
    __syncthreads();
    if (tid == 0) {
        unsigned d = atomicAdd(&g_done, 1u);
        if (d == NCTA - 1) {
            atomicExch(&g_bar, 0u);
            atomicExch(&g_done, 0u);
            __threadfence();
        }
    }
}

__global__ void copy_states(float* __restrict__ out_h, float* __restrict__ out_c)
{
    int i = blockIdx.x * blockDim.x + threadIdx.x;
    if (i < 2 * Bz * Hz) {
        out_h[i] = g_h[0][i];
        out_c[i] = g_c[i];
    }
}

extern "C" void kernel_launch(void* const* d_in, const int* in_sizes, int n_in,
                              void* d_out, int out_size)
{
    const float* x      = (const float*)d_in[0];
    const int*  lengths = (const int*)  d_in[1];
    const float* Wi_f0 = (const float*)d_in[2];
    const float* Wh_f0 = (const float*)d_in[3];
    const float* b_f0  = (const float*)d_in[4];
    const float* Wi_b0 = (const float*)d_in[5];
    const float* Wh_b0 = (const float*)d_in[6];
    const float* b_b0  = (const float*)d_in[7];
    const float* Wi_f1 = (const float*)d_in[8];
    const float* Wh_f1 = (const float*)d_in[9];
    const float* b_f1  = (const float*)d_in[10];
    const float* Wi_b1 = (const float*)d_in[11];
    const float* Wh_b1 = (const float*)d_in[12];
    const float* b_b1  = (const float*)d_in[13];
    float* out = (float*)d_out;

    cudaFuncSetAttribute(lstm_layer,
                         cudaFuncAttributeMaxDynamicSharedMemorySize, SMEM_BYTES);
    cudaFuncSetAttribute(gemm_mma,
                         cudaFuncAttributeMaxDynamicSharedMemorySize, SMEM_TC);

    float *hptr, *y0p;
    __nv_bfloat16 *ahp, *alp;
    cudaGetSymbolAddress((void**)&hptr, g_h);
    cudaGetSymbolAddress((void**)&y0p,  g_y0);
    cudaGetSymbolAddress((void**)&ahp,  g_Ah);
    cudaGetSymbolAddress((void**)&alp,  g_Al);

    const dim3 gemm_grid(NG / 128, Mz / 128);
    const int  copy_blocks = (2 * Bz * Hz + 255) / 256;

    // ---- layer 0 (K = 512) ----
    cudaMemsetAsync(hptr, 0, sizeof(float) * 2 * 2 * Bz * Hz);
    split_x<<<dim3(Mz, 1), 128>>>(x, Dz, ahp, alp);
    split_w<<<dim3(NG, 1), 128>>>(Wi_f0, Wi_b0, Dz);
    gemm_mma<<<gemm_grid, 256, SMEM_TC>>>(Dz, b_f0, b_b0);
    lstm_layer<<<NCTA, 256, SMEM_BYTES>>>(Wh_f0, Wh_b0, lengths, y0p);
    copy_states<<<copy_blocks, 256>>>(out + XOUT,
                                      out + XOUT + 4 * Bz * Hz);

    // ---- layer 1 (K = 1024) ----
    cudaMemsetAsync(hptr, 0, sizeof(float) * 2 * 2 * Bz * Hz);
    split_x<<<dim3(Mz, 2), 128>>>(y0p, 2 * Hz, ahp, alp);
    split_w<<<dim3(NG, 2), 128>>>(Wi_f1, Wi_b1, 2 * Hz);
    gemm_mma<<<gemm_grid, 256, SMEM_TC>>>(2 * Hz, b_f1, b_b1);
    lstm_layer<<<NCTA, 256, SMEM_BYTES>>>(Wh_f1, Wh_b1, lengths, out);
    copy_states<<<copy_blocks, 256>>>(out + XOUT + 2 * Bz * Hz,
                                      out + XOUT + 4 * Bz * Hz + 2 * Bz * Hz);
}

// round 6
// speedup vs baseline: 3.1661x; 2.5362x over previous
#include <cuda_runtime.h>
#include <cuda_bf16.h>
#include <math.h>
#include <stdint.h>

// Problem constants
#define Bz 64
#define Tz 512
#define Dz 512
#define Hz 512
#define G4 (4*Hz)        // 2048 gates per direction
#define NG (2*G4)        // 4096 gates both directions (fused GEMM N)
#define Mz (Bz*Tz)       // 32768 GEMM rows
#define NCTA 128         // persistent recurrence CTAs
#define XOUT ((size_t)Bz*Tz*2*Hz)

// Scratch (static device globals — no allocation)
__device__ float g_xg[(size_t)Tz*Bz*NG];       // [t*B+b][dir*2048 + gate*512 + n]
__device__ float g_y0[(size_t)Bz*Tz*2*Hz];     // layer0 output, [b][t][dir*512+n]
__device__ float g_h[2][2*Bz*Hz];              // ping-pong h (fp32, exact carry)
__device__ float g_c[2*Bz*Hz];                 // c final-state staging
__device__ unsigned g_bar;
__device__ unsigned g_done;
// bf16 hi/lo split operands for tensor-core GEMM (K-major rows)
__device__ __align__(16) __nv_bfloat16 g_Ah[(size_t)Mz*1024];
__device__ __align__(16) __nv_bfloat16 g_Al[(size_t)Mz*1024];
__device__ __align__(16) __nv_bfloat16 g_Bh[(size_t)NG*1024];
__device__ __align__(16) __nv_bfloat16 g_Bl[(size_t)NG*1024];
// bf16 hi/lo ping-pong h for the tensor-core recurrence
__device__ __align__(16) __nv_bfloat16 g_hh[2][2*Bz*Hz];
__device__ __align__(16) __nv_bfloat16 g_hl[2][2*Bz*Hz];

// ===========================================================================
// PTX helpers — only baseline (non-'a') features: mma.sync, ldmatrix, cp.async
// ===========================================================================
__device__ __forceinline__ uint32_t smem_u32(const void* p) {
    uint32_t a;
    asm("{ .reg .u64 t; cvta.to.shared.u64 t, %1; cvt.u32.u64 %0, t; }"
        : "=r"(a) : "l"(p));
    return a;
}
__device__ __forceinline__ void ldsm4(uint32_t* r, uint32_t addr) {
    asm volatile("ldmatrix.sync.aligned.m8n8.x4.shared.b16 {%0,%1,%2,%3}, [%4];"
                 : "=r"(r[0]), "=r"(r[1]), "=r"(r[2]), "=r"(r[3]) : "r"(addr));
}
__device__ __forceinline__ void mma16816(float* c, const uint32_t* a, const uint32_t* b) {
    asm volatile("mma.sync.aligned.m16n8k16.row.col.f32.bf16.bf16.f32 "
                 "{%0,%1,%2,%3}, {%4,%5,%6,%7}, {%8,%9}, {%0,%1,%2,%3};"
                 : "+f"(c[0]), "+f"(c[1]), "+f"(c[2]), "+f"(c[3])
                 : "r"(a[0]), "r"(a[1]), "r"(a[2]), "r"(a[3]),
                   "r"(b[0]), "r"(b[1]));
}
#define CP_ASYNC16(dst, src) \
    asm volatile("cp.async.cg.shared.global [%0], [%1], 16;" :: "r"(dst), "l"(src))
#define CP_COMMIT() asm volatile("cp.async.commit_group;" ::: "memory")
#define CP_WAIT1()  asm volatile("cp.async.wait_group 1;" ::: "memory")
#define CP_WAIT0()  asm volatile("cp.async.wait_group 0;" ::: "memory")

// ===========================================================================
// Conversion: fp32 -> bf16 hi + bf16 lo, with [b][t] -> m=t*B+b transpose.
// ===========================================================================
__global__ void __launch_bounds__(128)
split_x(const float* __restrict__ src, int K,
        __nv_bfloat16* __restrict__ dh, __nv_bfloat16* __restrict__ dl)
{
    const int m = blockIdx.x;
    const int k = blockIdx.y * 512 + threadIdx.x * 4;
    const int srow = (m & 63) * Tz + (m >> 6);
    float4 v = *(const float4*)(src + (size_t)srow * K + k);
    __nv_bfloat16 h0 = __float2bfloat16(v.x);
    __nv_bfloat16 h1 = __float2bfloat16(v.y);
    __nv_bfloat16 h2 = __float2bfloat16(v.z);
    __nv_bfloat16 h3 = __float2bfloat16(v.w);
    __nv_bfloat16 l0 = __float2bfloat16(v.x - __bfloat162float(h0));
    __nv_bfloat16 l1 = __float2bfloat16(v.y - __bfloat162float(h1));
    __nv_bfloat16 l2 = __float2bfloat16(v.z - __bfloat162float(h2));
    __nv_bfloat16 l3 = __float2bfloat16(v.w - __bfloat162float(h3));
    size_t o = (size_t)m * K + k;
    *(__nv_bfloat162*)(dh + o)     = __halves2bfloat162(h0, h1);
    *(__nv_bfloat162*)(dh + o + 2) = __halves2bfloat162(h2, h3);
    *(__nv_bfloat162*)(dl + o)     = __halves2bfloat162(l0, l1);
    *(__nv_bfloat162*)(dl + o + 2) = __halves2bfloat162(l2, l3);
}

__global__ void __launch_bounds__(128)
split_w(const float* __restrict__ Wf, const float* __restrict__ Wb, int K)
{
    const int n = blockIdx.x;
    const int k = blockIdx.y * 512 + threadIdx.x * 4;
    const float* src = (n < G4) ? (Wf + (size_t)n * K) : (Wb + (size_t)(n - G4) * K);
    float4 v = *(const float4*)(src + k);
    __nv_bfloat16 h0 = __float2bfloat16(v.x);
    __nv_bfloat16 h1 = __float2bfloat16(v.y);
    __nv_bfloat16 h2 = __float2bfloat16(v.z);
    __nv_bfloat16 h3 = __float2bfloat16(v.w);
    __nv_bfloat16 l0 = __float2bfloat16(v.x - __bfloat162float(h0));
    __nv_bfloat16 l1 = __float2bfloat16(v.y - __bfloat162float(h1));
    __nv_bfloat16 l2 = __float2bfloat16(v.z - __bfloat162float(h2));
    __nv_bfloat16 l3 = __float2bfloat16(v.w - __bfloat162float(h3));
    size_t o = (size_t)n * K + k;
    *(__nv_bfloat162*)(g_Bh + o)     = __halves2bfloat162(h0, h1);
    *(__nv_bfloat162*)(g_Bh + o + 2) = __halves2bfloat162(h2, h3);
    *(__nv_bfloat162*)(g_Bl + o)     = __halves2bfloat162(l0, l1);
    *(__nv_bfloat162*)(g_Bl + o + 2) = __halves2bfloat162(l2, l3);
}

// ===========================================================================
// bf16 mma.sync GEMM with 3-term compensation (unchanged from R5 PASS)
// ===========================================================================
#define TILE_B  16384
#define BUF_B   (4*TILE_B)
#define BIAS_OFF (2*BUF_B)
#define SMEM_TC  (BIAS_OFF + 512)

__global__ void __launch_bounds__(256, 1)
gemm_mma(int K, const float* __restrict__ bfp, const float* __restrict__ bbp)
{
    extern __shared__ char smem[];
    const uint32_t sbase = smem_u32(smem);
    const int tid  = threadIdx.x;
    const int wid  = tid >> 5;
    const int lane = tid & 31;
    const int n0 = blockIdx.x * 128;
    const int m0 = blockIdx.y * 128;
    const int nchunks = K / 64;

    float* bias_s = (float*)(smem + BIAS_OFF);
    if (tid < 128) {
        int n = n0 + tid;
        bias_s[tid] = (n < G4) ? bfp[n] : bbp[n - G4];
    }

    const char* tsrc[4];
    tsrc[0] = (const char*)(g_Ah + (size_t)m0 * K);
    tsrc[1] = (const char*)(g_Al + (size_t)m0 * K);
    tsrc[2] = (const char*)(g_Bh + (size_t)n0 * K);
    tsrc[3] = (const char*)(g_Bl + (size_t)n0 * K);

    const int l_row = tid >> 3;
    const int l_g   = tid & 7;

    auto load_chunk = [&](int c, int b) {
#pragma unroll
        for (int t4 = 0; t4 < 4; t4++) {
            const char* src0 = tsrc[t4] + (size_t)c * 128;
            uint32_t dst0 = sbase + b * BUF_B + t4 * TILE_B;
#pragma unroll
            for (int i = 0; i < 4; i++) {
                int row = l_row + i * 32;
                uint32_t dst = dst0 + row * 128 + ((l_g * 16) ^ ((row & 7) << 4));
                CP_ASYNC16(dst, src0 + (size_t)row * K * 2 + l_g * 16);
            }
        }
    };

    const int m0w = (wid & 1) * 64;
    const int n0w = (wid >> 1) * 32;

    uint32_t aBase[4];
    const int a_row_l = (lane & 15);
    const uint32_t a_klane = (lane >> 4) * 16;
#pragma unroll
    for (int mi = 0; mi < 4; mi++) {
        int row = m0w + mi * 16 + a_row_l;
        aBase[mi] = row * 128 + ((row & 7) << 4);
    }
    uint32_t bBase[2];
    const int b_row_l = ((lane >> 4) * 8) + (lane & 7);
    const uint32_t b_klane = ((lane >> 3) & 1) * 16;
#pragma unroll
    for (int nj = 0; nj < 2; nj++) {
        int row = n0w + nj * 16 + b_row_l;
        bBase[nj] = row * 128 + ((row & 7) << 4);
    }

    float c[4][4][4];
#pragma unroll
    for (int mi = 0; mi < 4; mi++)
#pragma unroll
        for (int ni = 0; ni < 4; ni++)
#pragma unroll
            for (int q = 0; q < 4; q++) c[mi][ni][q] = 0.f;

    load_chunk(0, 0); CP_COMMIT();
    if (nchunks > 1) { load_chunk(1, 1); CP_COMMIT(); }

    for (int ch = 0; ch < nchunks; ch++) {
        if (ch == nchunks - 1) CP_WAIT0(); else CP_WAIT1();
        __syncthreads();

        const uint32_t bufA_h = sbase + (ch & 1) * BUF_B;
        const uint32_t bufA_l = bufA_h + TILE_B;
        const uint32_t bufB_h = bufA_h + 2 * TILE_B;
        const uint32_t bufB_l = bufA_h + 3 * TILE_B;

#pragma unroll
        for (int ks = 0; ks < 4; ks++) {
            const uint32_t kbA = ks * 32 + a_klane;
            const uint32_t kbB = ks * 32 + b_klane;
            uint32_t ah[4][4], al[4][4], bh[4][2], bl[4][2];
#pragma unroll
            for (int mi = 0; mi < 4; mi++) {
                ldsm4(ah[mi], (bufA_h + aBase[mi]) ^ kbA);
                ldsm4(al[mi], (bufA_l + aBase[mi]) ^ kbA);
            }
#pragma unroll
            for (int nj = 0; nj < 2; nj++) {
                uint32_t r[4];
                ldsm4(r, (bufB_h + bBase[nj]) ^ kbB);
                bh[nj * 2][0] = r[0]; bh[nj * 2][1] = r[1];
                bh[nj * 2 + 1][0] = r[2]; bh[nj * 2 + 1][1] = r[3];
                ldsm4(r, (bufB_l + bBase[nj]) ^ kbB);
                bl[nj * 2][0] = r[0]; bl[nj * 2][1] = r[1];
                bl[nj * 2 + 1][0] = r[2]; bl[nj * 2 + 1][1] = r[3];
            }
#pragma unroll
            for (int mi = 0; mi < 4; mi++)
#pragma unroll
                for (int ni = 0; ni < 4; ni++) {
                    mma16816(c[mi][ni], ah[mi], bh[ni]);
                    mma16816(c[mi][ni], ah[mi], bl[ni]);
                    mma16816(c[mi][ni], al[mi], bh[ni]);
                }
        }
        __syncthreads();
        if (ch + 2 < nchunks) { load_chunk(ch + 2, ch & 1); CP_COMMIT(); }
    }

    const int er = lane >> 2;
    const int ec = (lane & 3) * 2;
#pragma unroll
    for (int mi = 0; mi < 4; mi++) {
        int row0 = m0 + m0w + mi * 16 + er;
#pragma unroll
        for (int ni = 0; ni < 4; ni++) {
            int nloc = n0w + ni * 8 + ec;
            int coln = n0 + nloc;
            float b0 = bias_s[nloc], b1 = bias_s[nloc + 1];
            float* p0 = g_xg + (size_t)row0 * NG + coln;
            float* p1 = g_xg + (size_t)(row0 + 8) * NG + coln;
            *(float2*)p0 = make_float2(c[mi][ni][0] + b0, c[mi][ni][1] + b1);
            *(float2*)p1 = make_float2(c[mi][ni][2] + b0, c[mi][ni][3] + b1);
        }
    }
}

// ===========================================================================
// Tensor-core persistent recurrence.
// 128 CTAs (dir = bid>>6, 8 hidden cols = (bid&63)*8 -> 32 gate rows), 8 warps.
// Wh slice hi/lo swizzled in smem ONCE (64KB). h kept as bf16 hi/lo ping-pong
// in global; per step: G = h @ Wh^T via m16n8k16 with 3-term compensation,
// cp.async double-buffered over 8 x 64-K chunks. fp32 h ping-pong retained
// for exact masked carry + final states; c fp32 in smem.
// ===========================================================================
#define R_WHH 0                    // 8 chunk-tiles x 4KB = 32KB (Wh hi)
#define R_WHL 32768                // 32KB (Wh lo)
#define R_HB  65536                // 2 bufs x (hi 8KB + lo 8KB) = 32KB
#define R_GS  98304                // float gs[32][68] = 8704B
#define R_CS  107008               // 512 floats
#define R_LS  109056               // 64 ints
#define R_SMEM 109312

__device__ __forceinline__ void grid_barrier(unsigned target)
{
    __syncthreads();
    if (threadIdx.x == 0) {
        __threadfence();
        atomicAdd(&g_bar, 1u);
        int backoff = 32;
        for (;;) {
            unsigned v;
            asm volatile("ld.acquire.gpu.global.u32 %0, [%1];"
                         : "=r"(v) : "l"(&g_bar));
            if (v >= target) break;
            __nanosleep(backoff);
            if (backoff < 256) backoff <<= 1;
        }
    }
    __syncthreads();
}

__global__ void __launch_bounds__(256, 1)
lstm_layer_tc(const float* __restrict__ Whf, const float* __restrict__ Whb,
              const int* __restrict__ lengths, float* __restrict__ Y)
{
    extern __shared__ char smem[];
    const uint32_t sbase = smem_u32(smem);
    float* gs = (float*)(smem + R_GS);
    float* cs = (float*)(smem + R_CS);
    int*   ls = (int*)(smem + R_LS);

    const int bid = blockIdx.x;
    const int dir = bid >> 6;
    const int n0  = (bid & 63) * 8;
    const float* Wh = dir ? Whb : Whf;

    const int tid  = threadIdx.x;
    const int wid  = tid >> 5;
    const int lane = tid & 31;

    // ---- one-time: Wh slice -> smem, split hi/lo, SW128-swizzled ----
    for (int idx = tid; idx < 8192; idx += 256) {
        int r  = idx >> 8;            // 0..31
        int kp = idx & 255;           // k pair; k = kp*2
        int j  = (r >> 3) * Hz + n0 + (r & 7);
        float2 v = *(const float2*)(Wh + (size_t)j * Hz + kp * 2);
        __nv_bfloat16 h0 = __float2bfloat16(v.x);
        __nv_bfloat16 h1 = __float2bfloat16(v.y);
        __nv_bfloat16 l0 = __float2bfloat16(v.x - __bfloat162float(h0));
        __nv_bfloat16 l1 = __float2bfloat16(v.y - __bfloat162float(h1));
        int c  = kp >> 5;             // chunk (k/64)
        int kb = (kp & 31) * 4;       // byte offset of pair within 128B row
        uint32_t off = c * 4096 + r * 128 + ((uint32_t)kb ^ (((uint32_t)r & 7) << 4));
        *(__nv_bfloat162*)(smem + R_WHH + off) = __halves2bfloat162(h0, h1);
        *(__nv_bfloat162*)(smem + R_WHL + off) = __halves2bfloat162(l0, l1);
    }
    for (int i = tid; i < 512; i += 256) cs[i] = 0.f;
    if (tid < 64) ls[tid] = lengths[tid];
    __syncthreads();

    // warp tiling: 4m x 2n; warp tile m16 x n16
    const int m0w = (wid & 3) * 16;
    const int n0w = (wid >> 2) * 16;
    const int a_row = m0w + (lane & 15);
    const uint32_t a_klane = (lane >> 4) * 16;
    const int b_row = n0w + ((lane >> 4) * 8) + (lane & 7);
    const uint32_t b_klane = ((lane >> 3) & 1) * 16;
    const uint32_t aOff = a_row * 128 + (((uint32_t)a_row & 7) << 4);
    const uint32_t bOff = b_row * 128 + (((uint32_t)b_row & 7) << 4);

    // h chunk loader (cp.async): 64 rows x 128B, hi + lo
    const int l_row = tid >> 3;       // 0..31
    const int l_g   = tid & 7;

    for (int s = 0; s < Tz; s++) {
        const int t   = dir ? (Tz - 1 - s) : s;
        const int par = s & 1;
        const float* hin  = g_h[par]     + dir * Bz * Hz;
        float*       hout = g_h[par ^ 1] + dir * Bz * Hz;
        const __nv_bfloat16* hh = g_hh[par] + dir * Bz * Hz;
        const __nv_bfloat16* hl = g_hl[par] + dir * Bz * Hz;
        __nv_bfloat16* hho = g_hh[par ^ 1] + dir * Bz * Hz;
        __nv_bfloat16* hlo = g_hl[par ^ 1] + dir * Bz * Hz;

        auto load_h = [&](int c, int buf) {
            uint32_t dhi = sbase + R_HB + buf * 16384;
#pragma unroll
            for (int i = 0; i < 2; i++) {
                int b = l_row + i * 32;
                uint32_t off = b * 128 + ((l_g * 16) ^ ((b & 7) << 4));
                CP_ASYNC16(dhi + off,
                           (const char*)(hh + (size_t)b * Hz + c * 64) + l_g * 16);
                CP_ASYNC16(dhi + 8192 + off,
                           (const char*)(hl + (size_t)b * Hz + c * 64) + l_g * 16);
            }
        };

        float c0[4] = {0.f, 0.f, 0.f, 0.f};
        float c1[4] = {0.f, 0.f, 0.f, 0.f};

        load_h(0, 0); CP_COMMIT();
        load_h(1, 1); CP_COMMIT();

        for (int ch = 0; ch < 8; ch++) {
            if (ch == 7) CP_WAIT0(); else CP_WAIT1();
            __syncthreads();
            const uint32_t ahB = sbase + R_HB + (ch & 1) * 16384 + aOff;
            const uint32_t alB = ahB + 8192;
            const uint32_t bhB = sbase + R_WHH + ch * 4096 + bOff;
            const uint32_t blB = bhB + 32768;
#pragma unroll
            for (int ks = 0; ks < 4; ks++) {
                const uint32_t kA = ks * 32 + a_klane;
                const uint32_t kB = ks * 32 + b_klane;
                uint32_t ah[4], al[4], bhh[4], bll[4];
                ldsm4(ah,  ahB ^ kA);
                ldsm4(al,  alB ^ kA);
                ldsm4(bhh, bhB ^ kB);
                ldsm4(bll, blB ^ kB);
                mma16816(c0, ah, bhh);      // n8 tile 0: regs 0,1
                mma16816(c0, ah, bll);
                mma16816(c0, al, bhh);
                mma16816(c1, ah, bhh + 2);  // n8 tile 1: regs 2,3
                mma16816(c1, ah, bll + 2);
                mma16816(c1, al, bhh + 2);
            }
            __syncthreads();
            if (ch + 2 < 8) { load_h(ch + 2, ch & 1); CP_COMMIT(); }
        }

        // write fragments to gs[col(r)][row(b)]
        {
            const int row0 = m0w + (lane >> 2);
            const int col0 = n0w + (lane & 3) * 2;
            gs[(col0)     * 68 + row0]     = c0[0];
            gs[(col0 + 1) * 68 + row0]     = c0[1];
            gs[(col0)     * 68 + row0 + 8] = c0[2];
            gs[(col0 + 1) * 68 + row0 + 8] = c0[3];
            gs[(col0 + 8) * 68 + row0]     = c1[0];
            gs[(col0 + 9) * 68 + row0]     = c1[1];
            gs[(col0 + 8) * 68 + row0 + 8] = c1[2];
            gs[(col0 + 9) * 68 + row0 + 8] = c1[3];
        }
        __syncthreads();

        // output phase: 512 (b, nl) outputs, 2 per thread
#pragma unroll
        for (int o = tid; o < 512; o += 256) {
            int nl = o & 7;
            int b  = o >> 3;
            int n  = n0 + nl;
            const float* xgp = g_xg + ((size_t)t * Bz + b) * NG + (size_t)dir * G4;
            float gi = gs[(0 * 8 + nl) * 68 + b] + xgp[0 * Hz + n];
            float gf = gs[(1 * 8 + nl) * 68 + b] + xgp[1 * Hz + n];
            float gg = gs[(2 * 8 + nl) * 68 + b] + xgp[2 * Hz + n];
            float go = gs[(3 * 8 + nl) * 68 + b] + xgp[3 * Hz + n];
            float iv = 1.f / (1.f + expf(-gi));
            float fv = 1.f / (1.f + expf(-gf));
            float gv = tanhf(gg);
            float ov = 1.f / (1.f + expf(-go));
            float cold = cs[o];
            float hold = hin[b * Hz + n];
            float cn = fv * cold + iv * gv;
            float hn = ov * tanhf(cn);
            bool m = (t < ls[b]);
            float hv = m ? hn : hold;
            hout[b * Hz + n] = hv;
            __nv_bfloat16 hhi = __float2bfloat16(hv);
            hho[b * Hz + n] = hhi;
            hlo[b * Hz + n] = __float2bfloat16(hv - __bfloat162float(hhi));
            cs[o] = m ? cn : cold;
            Y[((size_t)b * Tz + t) * (2 * Hz) + (size_t)dir * Hz + n] = m ? hn : 0.f;
        }

        if (s < Tz - 1) grid_barrier((unsigned)(s + 1) * NCTA);
    }

    // final c state -> global
    __syncthreads();
    for (int o = tid; o < 512; o += 256)
        g_c[dir * Bz * Hz + (o >> 3) * Hz + n0 + (o & 7)] = cs[o];

    // self-resetting exit
    __threadfence();
    __syncthreads();
    if (tid == 0) {
        unsigned d = atomicAdd(&g_done, 1u);
        if (d == NCTA - 1) {
            atomicExch(&g_bar, 0u);
            atomicExch(&g_done, 0u);
            __threadfence();
        }
    }
}

__global__ void copy_states(float* __restrict__ out_h, float* __restrict__ out_c)
{
    int i = blockIdx.x * blockDim.x + threadIdx.x;
    if (i < 2 * Bz * Hz) {
        out_h[i] = g_h[0][i];
        out_c[i] = g_c[i];
    }
}

extern "C" void kernel_launch(void* const* d_in, const int* in_sizes, int n_in,
                              void* d_out, int out_size)
{
    const float* x      = (const float*)d_in[0];
    const int*  lengths = (const int*)  d_in[1];
    const float* Wi_f0 = (const float*)d_in[2];
    const float* Wh_f0 = (const float*)d_in[3];
    const float* b_f0  = (const float*)d_in[4];
    const float* Wi_b0 = (const float*)d_in[5];
    const float* Wh_b0 = (const float*)d_in[6];
    const float* b_b0  = (const float*)d_in[7];
    const float* Wi_f1 = (const float*)d_in[8];
    const float* Wh_f1 = (const float*)d_in[9];
    const float* b_f1  = (const float*)d_in[10];
    const float* Wi_b1 = (const float*)d_in[11];
    const float* Wh_b1 = (const float*)d_in[12];
    const float* b_b1  = (const float*)d_in[13];
    float* out = (float*)d_out;

    cudaFuncSetAttribute(lstm_layer_tc,
                         cudaFuncAttributeMaxDynamicSharedMemorySize, R_SMEM);
    cudaFuncSetAttribute(gemm_mma,
                         cudaFuncAttributeMaxDynamicSharedMemorySize, SMEM_TC);

    float *hptr, *y0p;
    __nv_bfloat16 *ahp, *alp, *hhp, *hlp;
    cudaGetSymbolAddress((void**)&hptr, g_h);
    cudaGetSymbolAddress((void**)&y0p,  g_y0);
    cudaGetSymbolAddress((void**)&ahp,  g_Ah);
    cudaGetSymbolAddress((void**)&alp,  g_Al);
    cudaGetSymbolAddress((void**)&hhp,  g_hh);
    cudaGetSymbolAddress((void**)&hlp,  g_hl);

    const dim3 gemm_grid(NG / 128, Mz / 128);
    const int  copy_blocks = (2 * Bz * Hz + 255) / 256;
    const size_t hbytes  = sizeof(float) * 2 * 2 * Bz * Hz;
    const size_t hbbytes = sizeof(__nv_bfloat16) * 2 * 2 * Bz * Hz;

    // ---- layer 0 (K = 512) ----
    cudaMemsetAsync(hptr, 0, hbytes);
    cudaMemsetAsync(hhp,  0, hbbytes);
    cudaMemsetAsync(hlp,  0, hbbytes);
    split_x<<<dim3(Mz, 1), 128>>>(x, Dz, ahp, alp);
    split_w<<<dim3(NG, 1), 128>>>(Wi_f0, Wi_b0, Dz);
    gemm_mma<<<gemm_grid, 256, SMEM_TC>>>(Dz, b_f0, b_b0);
    lstm_layer_tc<<<NCTA, 256, R_SMEM>>>(Wh_f0, Wh_b0, lengths, y0p);
    copy_states<<<copy_blocks, 256>>>(out + XOUT,
                                      out + XOUT + 4 * Bz * Hz);

    // ---- layer 1 (K = 1024) ----
    cudaMemsetAsync(hptr, 0, hbytes);
    cudaMemsetAsync(hhp,  0, hbbytes);
    cudaMemsetAsync(hlp,  0, hbbytes);
    split_x<<<dim3(Mz, 2), 128>>>(y0p, 2 * Hz, ahp, alp);
    split_w<<<dim3(NG, 2), 128>>>(Wi_f1, Wi_b1, 2 * Hz);
    gemm_mma<<<gemm_grid, 256, SMEM_TC>>>(2 * Hz, b_f1, b_b1);
    lstm_layer_tc<<<NCTA, 256, R_SMEM>>>(Wh_f1, Wh_b1, lengths, out);
    copy_states<<<copy_blocks, 256>>>(out + XOUT + 2 * Bz * Hz,
                                      out + XOUT + 4 * Bz * Hz + 2 * Bz * Hz);
}

// round 7
// speedup vs baseline: 3.4455x; 1.0882x over previous
#include <cuda_runtime.h>
#include <cuda_bf16.h>
#include <math.h>
#include <stdint.h>

// Problem constants
#define Bz 64
#define Tz 512
#define Dz 512
#define Hz 512
#define G4 (4*Hz)        // 2048 gates per direction
#define NG (2*G4)        // 4096 gates both directions (fused GEMM N)
#define Mz (Bz*Tz)       // 32768 GEMM rows
#define NCTA 128         // persistent recurrence CTAs
#define XOUT ((size_t)Bz*Tz*2*Hz)

// Scratch (static device globals — no allocation)
__device__ float g_xg[(size_t)Tz*Bz*NG];       // [t*B+b][dir*2048 + gate*512 + n]
__device__ float g_c[2*Bz*Hz];                 // c final-state staging
__device__ unsigned g_bar2[64];                // per-dir barrier counters ([0],[32])
__device__ unsigned g_done;
// bf16 hi/lo split operands for tensor-core GEMM (K-major rows)
__device__ __align__(16) __nv_bfloat16 g_Ah[(size_t)Mz*1024];
__device__ __align__(16) __nv_bfloat16 g_Al[(size_t)Mz*1024];
__device__ __align__(16) __nv_bfloat16 g_Bh[(size_t)NG*1024];
__device__ __align__(16) __nv_bfloat16 g_Bl[(size_t)NG*1024];
// bf16 hi/lo ping-pong h for the tensor-core recurrence
__device__ __align__(16) __nv_bfloat16 g_hh[2][2*Bz*Hz];
__device__ __align__(16) __nv_bfloat16 g_hl[2][2*Bz*Hz];

// ===========================================================================
// PTX helpers — only baseline (non-'a') features: mma.sync, ldmatrix, cp.async
// ===========================================================================
__device__ __forceinline__ uint32_t smem_u32(const void* p) {
    uint32_t a;
    asm("{ .reg .u64 t; cvta.to.shared.u64 t, %1; cvt.u32.u64 %0, t; }"
        : "=r"(a) : "l"(p));
    return a;
}
__device__ __forceinline__ void ldsm4(uint32_t* r, uint32_t addr) {
    asm volatile("ldmatrix.sync.aligned.m8n8.x4.shared.b16 {%0,%1,%2,%3}, [%4];"
                 : "=r"(r[0]), "=r"(r[1]), "=r"(r[2]), "=r"(r[3]) : "r"(addr));
}
__device__ __forceinline__ void mma16816(float* c, const uint32_t* a, const uint32_t* b) {
    asm volatile("mma.sync.aligned.m16n8k16.row.col.f32.bf16.bf16.f32 "
                 "{%0,%1,%2,%3}, {%4,%5,%6,%7}, {%8,%9}, {%0,%1,%2,%3};"
                 : "+f"(c[0]), "+f"(c[1]), "+f"(c[2]), "+f"(c[3])
                 : "r"(a[0]), "r"(a[1]), "r"(a[2]), "r"(a[3]),
                   "r"(b[0]), "r"(b[1]));
}
#define CP_ASYNC16(dst, src) \
    asm volatile("cp.async.cg.shared.global [%0], [%1], 16;" :: "r"(dst), "l"(src))
#define CP_COMMIT() asm volatile("cp.async.commit_group;" ::: "memory")
#define CP_WAIT1()  asm volatile("cp.async.wait_group 1;" ::: "memory")
#define CP_WAIT0()  asm volatile("cp.async.wait_group 0;" ::: "memory")

// ===========================================================================
// Conversion: fp32 -> bf16 hi + bf16 lo, with [b][t] -> m=t*B+b transpose.
// (only used for the layer-0 input x; layer-1's A is written by the
//  layer-0 recurrence epilogue directly)
// ===========================================================================
__global__ void __launch_bounds__(128)
split_x(const float* __restrict__ src, int K,
        __nv_bfloat16* __restrict__ dh, __nv_bfloat16* __restrict__ dl)
{
    const int m = blockIdx.x;
    const int k = blockIdx.y * 512 + threadIdx.x * 4;
    const int srow = (m & 63) * Tz + (m >> 6);
    float4 v = *(const float4*)(src + (size_t)srow * K + k);
    __nv_bfloat16 h0 = __float2bfloat16(v.x);
    __nv_bfloat16 h1 = __float2bfloat16(v.y);
    __nv_bfloat16 h2 = __float2bfloat16(v.z);
    __nv_bfloat16 h3 = __float2bfloat16(v.w);
    __nv_bfloat16 l0 = __float2bfloat16(v.x - __bfloat162float(h0));
    __nv_bfloat16 l1 = __float2bfloat16(v.y - __bfloat162float(h1));
    __nv_bfloat16 l2 = __float2bfloat16(v.z - __bfloat162float(h2));
    __nv_bfloat16 l3 = __float2bfloat16(v.w - __bfloat162float(h3));
    size_t o = (size_t)m * K + k;
    *(__nv_bfloat162*)(dh + o)     = __halves2bfloat162(h0, h1);
    *(__nv_bfloat162*)(dh + o + 2) = __halves2bfloat162(h2, h3);
    *(__nv_bfloat162*)(dl + o)     = __halves2bfloat162(l0, l1);
    *(__nv_bfloat162*)(dl + o + 2) = __halves2bfloat162(l2, l3);
}

__global__ void __launch_bounds__(128)
split_w(const float* __restrict__ Wf, const float* __restrict__ Wb, int K)
{
    const int n = blockIdx.x;
    const int k = blockIdx.y * 512 + threadIdx.x * 4;
    const float* src = (n < G4) ? (Wf + (size_t)n * K) : (Wb + (size_t)(n - G4) * K);
    float4 v = *(const float4*)(src + k);
    __nv_bfloat16 h0 = __float2bfloat16(v.x);
    __nv_bfloat16 h1 = __float2bfloat16(v.y);
    __nv_bfloat16 h2 = __float2bfloat16(v.z);
    __nv_bfloat16 h3 = __float2bfloat16(v.w);
    __nv_bfloat16 l0 = __float2bfloat16(v.x - __bfloat162float(h0));
    __nv_bfloat16 l1 = __float2bfloat16(v.y - __bfloat162float(h1));
    __nv_bfloat16 l2 = __float2bfloat16(v.z - __bfloat162float(h2));
    __nv_bfloat16 l3 = __float2bfloat16(v.w - __bfloat162float(h3));
    size_t o = (size_t)n * K + k;
    *(__nv_bfloat162*)(g_Bh + o)     = __halves2bfloat162(h0, h1);
    *(__nv_bfloat162*)(g_Bh + o + 2) = __halves2bfloat162(h2, h3);
    *(__nv_bfloat162*)(g_Bl + o)     = __halves2bfloat162(l0, l1);
    *(__nv_bfloat162*)(g_Bl + o + 2) = __halves2bfloat162(l2, l3);
}

// ===========================================================================
// bf16 mma.sync GEMM with 3-term compensation (unchanged from R5/R6 PASS)
// ===========================================================================
#define TILE_B  16384
#define BUF_B   (4*TILE_B)
#define BIAS_OFF (2*BUF_B)
#define SMEM_TC  (BIAS_OFF + 512)

__global__ void __launch_bounds__(256, 1)
gemm_mma(int K, const float* __restrict__ bfp, const float* __restrict__ bbp)
{
    extern __shared__ char smem[];
    const uint32_t sbase = smem_u32(smem);
    const int tid  = threadIdx.x;
    const int wid  = tid >> 5;
    const int lane = tid & 31;
    const int n0 = blockIdx.x * 128;
    const int m0 = blockIdx.y * 128;
    const int nchunks = K / 64;

    float* bias_s = (float*)(smem + BIAS_OFF);
    if (tid < 128) {
        int n = n0 + tid;
        bias_s[tid] = (n < G4) ? bfp[n] : bbp[n - G4];
    }

    const char* tsrc[4];
    tsrc[0] = (const char*)(g_Ah + (size_t)m0 * K);
    tsrc[1] = (const char*)(g_Al + (size_t)m0 * K);
    tsrc[2] = (const char*)(g_Bh + (size_t)n0 * K);
    tsrc[3] = (const char*)(g_Bl + (size_t)n0 * K);

    const int l_row = tid >> 3;
    const int l_g   = tid & 7;

    auto load_chunk = [&](int c, int b) {
#pragma unroll
        for (int t4 = 0; t4 < 4; t4++) {
            const char* src0 = tsrc[t4] + (size_t)c * 128;
            uint32_t dst0 = sbase + b * BUF_B + t4 * TILE_B;
#pragma unroll
            for (int i = 0; i < 4; i++) {
                int row = l_row + i * 32;
                uint32_t dst = dst0 + row * 128 + ((l_g * 16) ^ ((row & 7) << 4));
                CP_ASYNC16(dst, src0 + (size_t)row * K * 2 + l_g * 16);
            }
        }
    };

    const int m0w = (wid & 1) * 64;
    const int n0w = (wid >> 1) * 32;

    uint32_t aBase[4];
    const int a_row_l = (lane & 15);
    const uint32_t a_klane = (lane >> 4) * 16;
#pragma unroll
    for (int mi = 0; mi < 4; mi++) {
        int row = m0w + mi * 16 + a_row_l;
        aBase[mi] = row * 128 + ((row & 7) << 4);
    }
    uint32_t bBase[2];
    const int b_row_l = ((lane >> 4) * 8) + (lane & 7);
    const uint32_t b_klane = ((lane >> 3) & 1) * 16;
#pragma unroll
    for (int nj = 0; nj < 2; nj++) {
        int row = n0w + nj * 16 + b_row_l;
        bBase[nj] = row * 128 + ((row & 7) << 4);
    }

    float c[4][4][4];
#pragma unroll
    for (int mi = 0; mi < 4; mi++)
#pragma unroll
        for (int ni = 0; ni < 4; ni++)
#pragma unroll
            for (int q = 0; q < 4; q++) c[mi][ni][q] = 0.f;

    load_chunk(0, 0); CP_COMMIT();
    if (nchunks > 1) { load_chunk(1, 1); CP_COMMIT(); }

    for (int ch = 0; ch < nchunks; ch++) {
        if (ch == nchunks - 1) CP_WAIT0(); else CP_WAIT1();
        __syncthreads();

        const uint32_t bufA_h = sbase + (ch & 1) * BUF_B;
        const uint32_t bufA_l = bufA_h + TILE_B;
        const uint32_t bufB_h = bufA_h + 2 * TILE_B;
        const uint32_t bufB_l = bufA_h + 3 * TILE_B;

#pragma unroll
        for (int ks = 0; ks < 4; ks++) {
            const uint32_t kbA = ks * 32 + a_klane;
            const uint32_t kbB = ks * 32 + b_klane;
            uint32_t ah[4][4], al[4][4], bh[4][2], bl[4][2];
#pragma unroll
            for (int mi = 0; mi < 4; mi++) {
                ldsm4(ah[mi], (bufA_h + aBase[mi]) ^ kbA);
                ldsm4(al[mi], (bufA_l + aBase[mi]) ^ kbA);
            }
#pragma unroll
            for (int nj = 0; nj < 2; nj++) {
                uint32_t r[4];
                ldsm4(r, (bufB_h + bBase[nj]) ^ kbB);
                bh[nj * 2][0] = r[0]; bh[nj * 2][1] = r[1];
                bh[nj * 2 + 1][0] = r[2]; bh[nj * 2 + 1][1] = r[3];
                ldsm4(r, (bufB_l + bBase[nj]) ^ kbB);
                bl[nj * 2][0] = r[0]; bl[nj * 2][1] = r[1];
                bl[nj * 2 + 1][0] = r[2]; bl[nj * 2 + 1][1] = r[3];
            }
#pragma unroll
            for (int mi = 0; mi < 4; mi++)
#pragma unroll
                for (int ni = 0; ni < 4; ni++) {
                    mma16816(c[mi][ni], ah[mi], bh[ni]);
                    mma16816(c[mi][ni], ah[mi], bl[ni]);
                    mma16816(c[mi][ni], al[mi], bh[ni]);
                }
        }
        __syncthreads();
        if (ch + 2 < nchunks) { load_chunk(ch + 2, ch & 1); CP_COMMIT(); }
    }

    const int er = lane >> 2;
    const int ec = (lane & 3) * 2;
#pragma unroll
    for (int mi = 0; mi < 4; mi++) {
        int row0 = m0 + m0w + mi * 16 + er;
#pragma unroll
        for (int ni = 0; ni < 4; ni++) {
            int nloc = n0w + ni * 8 + ec;
            int coln = n0 + nloc;
            float b0 = bias_s[nloc], b1 = bias_s[nloc + 1];
            float* p0 = g_xg + (size_t)row0 * NG + coln;
            float* p1 = g_xg + (size_t)(row0 + 8) * NG + coln;
            *(float2*)p0 = make_float2(c[mi][ni][0] + b0, c[mi][ni][1] + b1);
            *(float2*)p1 = make_float2(c[mi][ni][2] + b0, c[mi][ni][3] + b1);
        }
    }
}

// ===========================================================================
// Tensor-core persistent recurrence. Changes vs R6:
//  - xg slab prefetched into smem via cp.async (bundled with chunk-0 group)
//  - fp32 h ping-pong removed (carry reconstructed hh+hl)
//  - per-direction grid barrier (64-CTA span)
//  - wsplit=1 (layer 0): epilogue writes Y as bf16 hi/lo into g_Ah/g_Al
//    (the layer-1 GEMM A operand) instead of fp32 Y
// ===========================================================================
#define R_WHH 0                    // 8 chunk-tiles x 4KB = 32KB (Wh hi)
#define R_WHL 32768                // 32KB (Wh lo)
#define R_HB  65536                // 2 bufs x (hi 8KB + lo 8KB) = 32KB
#define R_GS  98304                // float gs[32][68] = 8704B
#define R_CS  107008               // 512 floats
#define R_LS  109056               // 64 ints
#define R_XG  109312               // float xg_s[64][40] = 10240B
#define R_SMEM 119552

__device__ __forceinline__ void grid_barrier_dir(int dir, unsigned target)
{
    __syncthreads();
    if (threadIdx.x == 0) {
        unsigned* ctr = &g_bar2[dir * 32];
        __threadfence();
        atomicAdd(ctr, 1u);
        int backoff = 32;
        for (;;) {
            unsigned v;
            asm volatile("ld.acquire.gpu.global.u32 %0, [%1];"
                         : "=r"(v) : "l"(ctr));
            if (v >= target) break;
            __nanosleep(backoff);
            if (backoff < 256) backoff <<= 1;
        }
    }
    __syncthreads();
}

__global__ void __launch_bounds__(256, 1)
lstm_layer_tc(const float* __restrict__ Whf, const float* __restrict__ Whb,
              const int* __restrict__ lengths, float* __restrict__ Y,
              int wsplit)
{
    extern __shared__ char smem[];
    const uint32_t sbase = smem_u32(smem);
    float* gs   = (float*)(smem + R_GS);
    float* cs   = (float*)(smem + R_CS);
    int*   ls   = (int*)(smem + R_LS);
    float* xg_s = (float*)(smem + R_XG);

    const int bid = blockIdx.x;
    const int dir = bid >> 6;
    const int n0  = (bid & 63) * 8;
    const float* Wh = dir ? Whb : Whf;

    const int tid  = threadIdx.x;
    const int wid  = tid >> 5;
    const int lane = tid & 31;

    // ---- one-time: Wh slice -> smem, split hi/lo, SW128-swizzled ----
    for (int idx = tid; idx < 8192; idx += 256) {
        int r  = idx >> 8;            // 0..31
        int kp = idx & 255;           // k pair; k = kp*2
        int j  = (r >> 3) * Hz + n0 + (r & 7);
        float2 v = *(const float2*)(Wh + (size_t)j * Hz + kp * 2);
        __nv_bfloat16 h0 = __float2bfloat16(v.x);
        __nv_bfloat16 h1 = __float2bfloat16(v.y);
        __nv_bfloat16 l0 = __float2bfloat16(v.x - __bfloat162float(h0));
        __nv_bfloat16 l1 = __float2bfloat16(v.y - __bfloat162float(h1));
        int c  = kp >> 5;
        int kb = (kp & 31) * 4;
        uint32_t off = c * 4096 + r * 128 + ((uint32_t)kb ^ (((uint32_t)r & 7) << 4));
        *(__nv_bfloat162*)(smem + R_WHH + off) = __halves2bfloat162(h0, h1);
        *(__nv_bfloat162*)(smem + R_WHL + off) = __halves2bfloat162(l0, l1);
    }
    for (int i = tid; i < 512; i += 256) cs[i] = 0.f;
    if (tid < 64) ls[tid] = lengths[tid];
    __syncthreads();

    // warp tiling: 4m x 2n; warp tile m16 x n16
    const int m0w = (wid & 3) * 16;
    const int n0w = (wid >> 2) * 16;
    const int a_row = m0w + (lane & 15);
    const uint32_t a_klane = (lane >> 4) * 16;
    const int b_row = n0w + ((lane >> 4) * 8) + (lane & 7);
    const uint32_t b_klane = ((lane >> 3) & 1) * 16;
    const uint32_t aOff = a_row * 128 + (((uint32_t)a_row & 7) << 4);
    const uint32_t bOff = b_row * 128 + (((uint32_t)b_row & 7) << 4);

    const int l_row = tid >> 3;       // 0..31
    const int l_g   = tid & 7;

    for (int s = 0; s < Tz; s++) {
        const int t   = dir ? (Tz - 1 - s) : s;
        const int par = s & 1;
        const __nv_bfloat16* hh = g_hh[par] + dir * Bz * Hz;
        const __nv_bfloat16* hl = g_hl[par] + dir * Bz * Hz;
        __nv_bfloat16* hho = g_hh[par ^ 1] + dir * Bz * Hz;
        __nv_bfloat16* hlo = g_hl[par ^ 1] + dir * Bz * Hz;

        auto load_h = [&](int c, int buf) {
            uint32_t dhi = sbase + R_HB + buf * 16384;
#pragma unroll
            for (int i = 0; i < 2; i++) {
                int b = l_row + i * 32;
                uint32_t off = b * 128 + ((l_g * 16) ^ ((b & 7) << 4));
                CP_ASYNC16(dhi + off,
                           (const char*)(hh + (size_t)b * Hz + c * 64) + l_g * 16);
                CP_ASYNC16(dhi + 8192 + off,
                           (const char*)(hl + (size_t)b * Hz + c * 64) + l_g * 16);
            }
        };

        // xg prefetch (512 x 16B) bundled with chunk-0's commit group
        {
            const float* xg0 = g_xg + ((size_t)t * Bz) * NG + (size_t)dir * G4 + n0;
#pragma unroll
            for (int i = 0; i < 2; i++) {
                int e = tid + i * 256;        // 0..511
                int b = e >> 3;
                int g = (e >> 1) & 3;
                int hf = e & 1;
                uint32_t dst = sbase + R_XG + (b * 40 + g * 8 + hf * 4) * 4;
                CP_ASYNC16(dst, xg0 + (size_t)b * NG + g * Hz + hf * 4);
            }
        }
        load_h(0, 0); CP_COMMIT();
        load_h(1, 1); CP_COMMIT();

        float c0[4] = {0.f, 0.f, 0.f, 0.f};
        float c1[4] = {0.f, 0.f, 0.f, 0.f};

        for (int ch = 0; ch < 8; ch++) {
            if (ch == 7) CP_WAIT0(); else CP_WAIT1();
            __syncthreads();
            const uint32_t ahB = sbase + R_HB + (ch & 1) * 16384 + aOff;
            const uint32_t alB = ahB + 8192;
            const uint32_t bhB = sbase + R_WHH + ch * 4096 + bOff;
            const uint32_t blB = bhB + 32768;
#pragma unroll
            for (int ks = 0; ks < 4; ks++) {
                const uint32_t kA = ks * 32 + a_klane;
                const uint32_t kB = ks * 32 + b_klane;
                uint32_t ah[4], al[4], bhh[4], bll[4];
                ldsm4(ah,  ahB ^ kA);
                ldsm4(al,  alB ^ kA);
                ldsm4(bhh, bhB ^ kB);
                ldsm4(bll, blB ^ kB);
                mma16816(c0, ah, bhh);
                mma16816(c0, ah, bll);
                mma16816(c0, al, bhh);
                mma16816(c1, ah, bhh + 2);
                mma16816(c1, ah, bll + 2);
                mma16816(c1, al, bhh + 2);
            }
            __syncthreads();
            if (ch + 2 < 8) { load_h(ch + 2, ch & 1); CP_COMMIT(); }
        }

        // write fragments to gs[col(r)][row(b)]
        {
            const int row0 = m0w + (lane >> 2);
            const int col0 = n0w + (lane & 3) * 2;
            gs[(col0)     * 68 + row0]     = c0[0];
            gs[(col0 + 1) * 68 + row0]     = c0[1];
            gs[(col0)     * 68 + row0 + 8] = c0[2];
            gs[(col0 + 1) * 68 + row0 + 8] = c0[3];
            gs[(col0 + 8) * 68 + row0]     = c1[0];
            gs[(col0 + 9) * 68 + row0]     = c1[1];
            gs[(col0 + 8) * 68 + row0 + 8] = c1[2];
            gs[(col0 + 9) * 68 + row0 + 8] = c1[3];
        }
        __syncthreads();

        // output phase: 512 (b, nl) outputs, 2 per thread
#pragma unroll
        for (int o = tid; o < 512; o += 256) {
            int nl = o & 7;
            int b  = o >> 3;
            int n  = n0 + nl;
            const float* xr = xg_s + b * 40;
            float gi = gs[(0 * 8 + nl) * 68 + b] + xr[0 * 8 + nl];
            float gf = gs[(1 * 8 + nl) * 68 + b] + xr[1 * 8 + nl];
            float gg = gs[(2 * 8 + nl) * 68 + b] + xr[2 * 8 + nl];
            float go = gs[(3 * 8 + nl) * 68 + b] + xr[3 * 8 + nl];
            float iv = 1.f / (1.f + expf(-gi));
            float fv = 1.f / (1.f + expf(-gf));
            float gv = tanhf(gg);
            float ov = 1.f / (1.f + expf(-go));
            float cold = cs[o];
            float hold = __bfloat162float(hh[b * Hz + n])
                       + __bfloat162float(hl[b * Hz + n]);
            float cn = fv * cold + iv * gv;
            float hn = ov * tanhf(cn);
            bool m = (t < ls[b]);
            float hv = m ? hn : hold;
            __nv_bfloat16 hhi = __float2bfloat16(hv);
            hho[b * Hz + n] = hhi;
            hlo[b * Hz + n] = __float2bfloat16(hv - __bfloat162float(hhi));
            cs[o] = m ? cn : cold;
            float yv = m ? hn : 0.f;
            if (wsplit) {
                size_t yo = ((size_t)t * Bz + b) * 1024 + (size_t)dir * Hz + n;
                __nv_bfloat16 yh = __float2bfloat16(yv);
                g_Ah[yo] = yh;
                g_Al[yo] = __float2bfloat16(yv - __bfloat162float(yh));
            } else {
                Y[((size_t)b * Tz + t) * (2 * Hz) + (size_t)dir * Hz + n] = yv;
            }
        }

        if (s < Tz - 1) grid_barrier_dir(dir, (unsigned)(s + 1) * 64);
    }

    // final c state -> global
    __syncthreads();
    for (int o = tid; o < 512; o += 256)
        g_c[dir * Bz * Hz + (o >> 3) * Hz + n0 + (o & 7)] = cs[o];

    // self-resetting exit
    __threadfence();
    __syncthreads();
    if (tid == 0) {
        unsigned d = atomicAdd(&g_done, 1u);
        if (d == NCTA - 1) {
            atomicExch(&g_bar2[0], 0u);
            atomicExch(&g_bar2[32], 0u);
            atomicExch(&g_done, 0u);
            __threadfence();
        }
    }
}

// copy final states (parity 0 after 512 steps) into d_out hN/cN sections
__global__ void copy_states(float* __restrict__ out_h, float* __restrict__ out_c)
{
    int i = blockIdx.x * blockDim.x + threadIdx.x;
    if (i < 2 * Bz * Hz) {
        out_h[i] = __bfloat162float(g_hh[0][i]) + __bfloat162float(g_hl[0][i]);
        out_c[i] = g_c[i];
    }
}

extern "C" void kernel_launch(void* const* d_in, const int* in_sizes, int n_in,
                              void* d_out, int out_size)
{
    const float* x      = (const float*)d_in[0];
    const int*  lengths = (const int*)  d_in[1];
    const float* Wi_f0 = (const float*)d_in[2];
    const float* Wh_f0 = (const float*)d_in[3];
    const float* b_f0  = (const float*)d_in[4];
    const float* Wi_b0 = (const float*)d_in[5];
    const float* Wh_b0 = (const float*)d_in[6];
    const float* b_b0  = (const float*)d_in[7];
    const float* Wi_f1 = (const float*)d_in[8];
    const float* Wh_f1 = (const float*)d_in[9];
    const float* b_f1  = (const float*)d_in[10];
    const float* Wi_b1 = (const float*)d_in[11];
    const float* Wh_b1 = (const float*)d_in[12];
    const float* b_b1  = (const float*)d_in[13];
    float* out = (float*)d_out;

    cudaFuncSetAttribute(lstm_layer_tc,
                         cudaFuncAttributeMaxDynamicSharedMemorySize, R_SMEM);
    cudaFuncSetAttribute(gemm_mma,
                         cudaFuncAttributeMaxDynamicSharedMemorySize, SMEM_TC);

    __nv_bfloat16 *ahp, *alp, *hhp, *hlp;
    cudaGetSymbolAddress((void**)&ahp,  g_Ah);
    cudaGetSymbolAddress((void**)&alp,  g_Al);
    cudaGetSymbolAddress((void**)&hhp,  g_hh);
    cudaGetSymbolAddress((void**)&hlp,  g_hl);

    const dim3 gemm_grid(NG / 128, Mz / 128);
    const int  copy_blocks = (2 * Bz * Hz + 255) / 256;
    const size_t hbbytes = sizeof(__nv_bfloat16) * 2 * 2 * Bz * Hz;

    // ---- layer 0 (K = 512) ----
    cudaMemsetAsync(hhp, 0, hbbytes);
    cudaMemsetAsync(hlp, 0, hbbytes);
    split_x<<<dim3(Mz, 1), 128>>>(x, Dz, ahp, alp);
    split_w<<<dim3(NG, 1), 128>>>(Wi_f0, Wi_b0, Dz);
    gemm_mma<<<gemm_grid, 256, SMEM_TC>>>(Dz, b_f0, b_b0);
    lstm_layer_tc<<<NCTA, 256, R_SMEM>>>(Wh_f0, Wh_b0, lengths, out, 1);
    copy_states<<<copy_blocks, 256>>>(out + XOUT,
                                      out + XOUT + 4 * Bz * Hz);

    // ---- layer 1 (K = 1024; A operand written by layer-0 recurrence) ----
    cudaMemsetAsync(hhp, 0, hbbytes);
    cudaMemsetAsync(hlp, 0, hbbytes);
    split_w<<<dim3(NG, 2), 128>>>(Wi_f1, Wi_b1, 2 * Hz);
    gemm_mma<<<gemm_grid, 256, SMEM_TC>>>(2 * Hz, b_f1, b_b1);
    lstm_layer_tc<<<NCTA, 256, R_SMEM>>>(Wh_f1, Wh_b1, lengths, out, 0);
    copy_states<<<copy_blocks, 256>>>(out + XOUT + 2 * Bz * Hz,
                                      out + XOUT + 4 * Bz * Hz + 2 * Bz * Hz);
}

// round 12
// speedup vs baseline: 3.7004x; 1.0740x over previous
#include <cuda_runtime.h>
#include <cuda_bf16.h>
#include <math.h>
#include <stdint.h>

// Problem constants
#define Bz 64
#define Tz 512
#define Dz 512
#define Hz 512
#define G4 (4*Hz)        // 2048 gates per direction
#define NG (2*G4)        // 4096 gates both directions (fused GEMM N)
#define Mz (Bz*Tz)       // 32768 GEMM rows
#define NCTA 128         // persistent recurrence CTAs
#define XOUT ((size_t)Bz*Tz*2*Hz)

// Scratch (static device globals — no allocation)
__device__ float g_xg[(size_t)Tz*Bz*NG];       // [t*B+b][dir*2048 + gate*512 + n]
__device__ float g_hf[2*Bz*Hz];                // final h per layer ([dir][b][n])
__device__ float g_c[2*Bz*Hz];                 // final c per layer
__device__ unsigned g_bar2[64];                // per-dir barrier counters ([0],[32])
__device__ unsigned g_done;
// bf16 hi/lo split operands for tensor-core GEMM (K-major rows)
__device__ __align__(16) __nv_bfloat16 g_Ah[(size_t)Mz*1024];
__device__ __align__(16) __nv_bfloat16 g_Al[(size_t)Mz*1024];
__device__ __align__(16) __nv_bfloat16 g_Bh[(size_t)NG*1024];
__device__ __align__(16) __nv_bfloat16 g_Bl[(size_t)NG*1024];
// bf16 hi/lo ping-pong h for the tensor-core recurrence
__device__ __align__(16) __nv_bfloat16 g_hh[2][2*Bz*Hz];
__device__ __align__(16) __nv_bfloat16 g_hl[2][2*Bz*Hz];

// ===========================================================================
// PTX helpers — only baseline (non-'a') features: mma.sync, ldmatrix, cp.async
// ===========================================================================
__device__ __forceinline__ uint32_t smem_u32(const void* p) {
    uint32_t a;
    asm("{ .reg .u64 t; cvta.to.shared.u64 t, %1; cvt.u32.u64 %0, t; }"
        : "=r"(a) : "l"(p));
    return a;
}
__device__ __forceinline__ void ldsm4(uint32_t* r, uint32_t addr) {
    asm volatile("ldmatrix.sync.aligned.m8n8.x4.shared.b16 {%0,%1,%2,%3}, [%4];"
                 : "=r"(r[0]), "=r"(r[1]), "=r"(r[2]), "=r"(r[3]) : "r"(addr));
}
__device__ __forceinline__ void mma16816(float* c, const uint32_t* a, const uint32_t* b) {
    asm volatile("mma.sync.aligned.m16n8k16.row.col.f32.bf16.bf16.f32 "
                 "{%0,%1,%2,%3}, {%4,%5,%6,%7}, {%8,%9}, {%0,%1,%2,%3};"
                 : "+f"(c[0]), "+f"(c[1]), "+f"(c[2]), "+f"(c[3])
                 : "r"(a[0]), "r"(a[1]), "r"(a[2]), "r"(a[3]),
                   "r"(b[0]), "r"(b[1]));
}
#define CP_ASYNC16(dst, src) \
    asm volatile("cp.async.cg.shared.global [%0], [%1], 16;" :: "r"(dst), "l"(src))
#define CP_COMMIT() asm volatile("cp.async.commit_group;" ::: "memory")
#define CP_WAIT1()  asm volatile("cp.async.wait_group 1;" ::: "memory")
#define CP_WAIT0()  asm volatile("cp.async.wait_group 0;" ::: "memory")

// ===========================================================================
// Conversion: fp32 -> bf16 hi + bf16 lo, with [b][t] -> m=t*B+b transpose.
// ===========================================================================
__global__ void __launch_bounds__(128)
split_x(const float* __restrict__ src, int K,
        __nv_bfloat16* __restrict__ dh, __nv_bfloat16* __restrict__ dl)
{
    const int m = blockIdx.x;
    const int k = blockIdx.y * 512 + threadIdx.x * 4;
    const int srow = (m & 63) * Tz + (m >> 6);
    float4 v = *(const float4*)(src + (size_t)srow * K + k);
    __nv_bfloat16 h0 = __float2bfloat16(v.x);
    __nv_bfloat16 h1 = __float2bfloat16(v.y);
    __nv_bfloat16 h2 = __float2bfloat16(v.z);
    __nv_bfloat16 h3 = __float2bfloat16(v.w);
    __nv_bfloat16 l0 = __float2bfloat16(v.x - __bfloat162float(h0));
    __nv_bfloat16 l1 = __float2bfloat16(v.y - __bfloat162float(h1));
    __nv_bfloat16 l2 = __float2bfloat16(v.z - __bfloat162float(h2));
    __nv_bfloat16 l3 = __float2bfloat16(v.w - __bfloat162float(h3));
    size_t o = (size_t)m * K + k;
    *(__nv_bfloat162*)(dh + o)     = __halves2bfloat162(h0, h1);
    *(__nv_bfloat162*)(dh + o + 2) = __halves2bfloat162(h2, h3);
    *(__nv_bfloat162*)(dl + o)     = __halves2bfloat162(l0, l1);
    *(__nv_bfloat162*)(dl + o + 2) = __halves2bfloat162(l2, l3);
}

__global__ void __launch_bounds__(128)
split_w(const float* __restrict__ Wf, const float* __restrict__ Wb, int K)
{
    const int n = blockIdx.x;
    const int k = blockIdx.y * 512 + threadIdx.x * 4;
    const float* src = (n < G4) ? (Wf + (size_t)n * K) : (Wb + (size_t)(n - G4) * K);
    float4 v = *(const float4*)(src + k);
    __nv_bfloat16 h0 = __float2bfloat16(v.x);
    __nv_bfloat16 h1 = __float2bfloat16(v.y);
    __nv_bfloat16 h2 = __float2bfloat16(v.z);
    __nv_bfloat16 h3 = __float2bfloat16(v.w);
    __nv_bfloat16 l0 = __float2bfloat16(v.x - __bfloat162float(h0));
    __nv_bfloat16 l1 = __float2bfloat16(v.y - __bfloat162float(h1));
    __nv_bfloat16 l2 = __float2bfloat16(v.z - __bfloat162float(h2));
    __nv_bfloat16 l3 = __float2bfloat16(v.w - __bfloat162float(h3));
    size_t o = (size_t)n * K + k;
    *(__nv_bfloat162*)(g_Bh + o)     = __halves2bfloat162(h0, h1);
    *(__nv_bfloat162*)(g_Bh + o + 2) = __halves2bfloat162(h2, h3);
    *(__nv_bfloat162*)(g_Bl + o)     = __halves2bfloat162(l0, l1);
    *(__nv_bfloat162*)(g_Bl + o + 2) = __halves2bfloat162(l2, l3);
}

// ===========================================================================
// bf16 mma.sync GEMM with 3-term compensation (unchanged from R5-R7 PASS)
// ===========================================================================
#define TILE_B  16384
#define BUF_B   (4*TILE_B)
#define BIAS_OFF (2*BUF_B)
#define SMEM_TC  (BIAS_OFF + 512)

__global__ void __launch_bounds__(256, 1)
gemm_mma(int K, const float* __restrict__ bfp, const float* __restrict__ bbp)
{
    extern __shared__ char smem[];
    const uint32_t sbase = smem_u32(smem);
    const int tid  = threadIdx.x;
    const int wid  = tid >> 5;
    const int lane = tid & 31;
    const int n0 = blockIdx.x * 128;
    const int m0 = blockIdx.y * 128;
    const int nchunks = K / 64;

    float* bias_s = (float*)(smem + BIAS_OFF);
    if (tid < 128) {
        int n = n0 + tid;
        bias_s[tid] = (n < G4) ? bfp[n] : bbp[n - G4];
    }

    const char* tsrc[4];
    tsrc[0] = (const char*)(g_Ah + (size_t)m0 * K);
    tsrc[1] = (const char*)(g_Al + (size_t)m0 * K);
    tsrc[2] = (const char*)(g_Bh + (size_t)n0 * K);
    tsrc[3] = (const char*)(g_Bl + (size_t)n0 * K);

    const int l_row = tid >> 3;
    const int l_g   = tid & 7;

    auto load_chunk = [&](int c, int b) {
#pragma unroll
        for (int t4 = 0; t4 < 4; t4++) {
            const char* src0 = tsrc[t4] + (size_t)c * 128;
            uint32_t dst0 = sbase + b * BUF_B + t4 * TILE_B;
#pragma unroll
            for (int i = 0; i < 4; i++) {
                int row = l_row + i * 32;
                uint32_t dst = dst0 + row * 128 + ((l_g * 16) ^ ((row & 7) << 4));
                CP_ASYNC16(dst, src0 + (size_t)row * K * 2 + l_g * 16);
            }
        }
    };

    const int m0w = (wid & 1) * 64;
    const int n0w = (wid >> 1) * 32;

    uint32_t aBase[4];
    const int a_row_l = (lane & 15);
    const uint32_t a_klane = (lane >> 4) * 16;
#pragma unroll
    for (int mi = 0; mi < 4; mi++) {
        int row = m0w + mi * 16 + a_row_l;
        aBase[mi] = row * 128 + ((row & 7) << 4);
    }
    uint32_t bBase[2];
    const int b_row_l = ((lane >> 4) * 8) + (lane & 7);
    const uint32_t b_klane = ((lane >> 3) & 1) * 16;
#pragma unroll
    for (int nj = 0; nj < 2; nj++) {
        int row = n0w + nj * 16 + b_row_l;
        bBase[nj] = row * 128 + ((row & 7) << 4);
    }

    float c[4][4][4];
#pragma unroll
    for (int mi = 0; mi < 4; mi++)
#pragma unroll
        for (int ni = 0; ni < 4; ni++)
#pragma unroll
            for (int q = 0; q < 4; q++) c[mi][ni][q] = 0.f;

    load_chunk(0, 0); CP_COMMIT();
    if (nchunks > 1) { load_chunk(1, 1); CP_COMMIT(); }

    for (int ch = 0; ch < nchunks; ch++) {
        if (ch == nchunks - 1) CP_WAIT0(); else CP_WAIT1();
        __syncthreads();

        const uint32_t bufA_h = sbase + (ch & 1) * BUF_B;
        const uint32_t bufA_l = bufA_h + TILE_B;
        const uint32_t bufB_h = bufA_h + 2 * TILE_B;
        const uint32_t bufB_l = bufA_h + 3 * TILE_B;

#pragma unroll
        for (int ks = 0; ks < 4; ks++) {
            const uint32_t kbA = ks * 32 + a_klane;
            const uint32_t kbB = ks * 32 + b_klane;
            uint32_t ah[4][4], al[4][4], bh[4][2], bl[4][2];
#pragma unroll
            for (int mi = 0; mi < 4; mi++) {
                ldsm4(ah[mi], (bufA_h + aBase[mi]) ^ kbA);
                ldsm4(al[mi], (bufA_l + aBase[mi]) ^ kbA);
            }
#pragma unroll
            for (int nj = 0; nj < 2; nj++) {
                uint32_t r[4];
                ldsm4(r, (bufB_h + bBase[nj]) ^ kbB);
                bh[nj * 2][0] = r[0]; bh[nj * 2][1] = r[1];
                bh[nj * 2 + 1][0] = r[2]; bh[nj * 2 + 1][1] = r[3];
                ldsm4(r, (bufB_l + bBase[nj]) ^ kbB);
                bl[nj * 2][0] = r[0]; bl[nj * 2][1] = r[1];
                bl[nj * 2 + 1][0] = r[2]; bl[nj * 2 + 1][1] = r[3];
            }
#pragma unroll
            for (int mi = 0; mi < 4; mi++)
#pragma unroll
                for (int ni = 0; ni < 4; ni++) {
                    mma16816(c[mi][ni], ah[mi], bh[ni]);
                    mma16816(c[mi][ni], ah[mi], bl[ni]);
                    mma16816(c[mi][ni], al[mi], bh[ni]);
                }
        }
        __syncthreads();
        if (ch + 2 < nchunks) { load_chunk(ch + 2, ch & 1); CP_COMMIT(); }
    }

    const int er = lane >> 2;
    const int ec = (lane & 3) * 2;
#pragma unroll
    for (int mi = 0; mi < 4; mi++) {
        int row0 = m0 + m0w + mi * 16 + er;
#pragma unroll
        for (int ni = 0; ni < 4; ni++) {
            int nloc = n0w + ni * 8 + ec;
            int coln = n0 + nloc;
            float b0 = bias_s[nloc], b1 = bias_s[nloc + 1];
            float* p0 = g_xg + (size_t)row0 * NG + coln;
            float* p1 = g_xg + (size_t)(row0 + 8) * NG + coln;
            *(float2*)p0 = make_float2(c[mi][ni][0] + b0, c[mi][ni][1] + b1);
            *(float2*)p1 = make_float2(c[mi][ni][2] + b0, c[mi][ni][3] + b1);
        }
    }
}

// ===========================================================================
// Tensor-core persistent recurrence with active-prefix masking.
// lengths sorted descending => active rows {b: len[b] > t} are a prefix of
// size nb(t) (precomputed table). MMA m-tiles / h loads / xg prefetch /
// output phase restricted to the prefix. Masked outputs are pre-zeroed by
// host memsets; final h/c written once at each row's last active step.
// ===========================================================================
#define R_WHH 0                    // 8 chunk-tiles x 4KB = 32KB (Wh hi)
#define R_WHL 32768                // 32KB (Wh lo)
#define R_HB  65536                // 2 bufs x (hi 8KB + lo 8KB) = 32KB
#define R_GS  98304                // float gs[32][68] = 8704B
#define R_CS  107008               // 512 floats
#define R_LS  109056               // 64 ints
#define R_XG  109312               // float xg_s[64][40] = 10240B
#define R_NB  119552               // int nbArr[512] = 2048B
#define R_SMEM 121600

__device__ __forceinline__ void grid_barrier_dir(int dir, unsigned target)
{
    __syncthreads();
    if (threadIdx.x == 0) {
        unsigned* ctr = &g_bar2[dir * 32];
        __threadfence();
        atomicAdd(ctr, 1u);
        int backoff = 32;
        for (;;) {
            unsigned v;
            asm volatile("ld.acquire.gpu.global.u32 %0, [%1];"
                         : "=r"(v) : "l"(ctr));
            if (v >= target) break;
            __nanosleep(backoff);
            if (backoff < 256) backoff <<= 1;
        }
    }
    __syncthreads();
}

__global__ void __launch_bounds__(256, 1)
lstm_layer_tc(const float* __restrict__ Whf, const float* __restrict__ Whb,
              const int* __restrict__ lengths, float* __restrict__ Y,
              int wsplit)
{
    extern __shared__ char smem[];
    const uint32_t sbase = smem_u32(smem);
    float* gs    = (float*)(smem + R_GS);
    float* cs    = (float*)(smem + R_CS);
    int*   ls    = (int*)(smem + R_LS);
    float* xg_s  = (float*)(smem + R_XG);
    int*   nbArr = (int*)(smem + R_NB);

    const int bid = blockIdx.x;
    const int dir = bid >> 6;
    const int n0  = (bid & 63) * 8;
    const float* Wh = dir ? Whb : Whf;

    const int tid  = threadIdx.x;
    const int wid  = tid >> 5;
    const int lane = tid & 31;

    // ---- one-time: Wh slice -> smem, split hi/lo, SW128-swizzled ----
    for (int idx = tid; idx < 8192; idx += 256) {
        int r  = idx >> 8;
        int kp = idx & 255;
        int j  = (r >> 3) * Hz + n0 + (r & 7);
        float2 v = *(const float2*)(Wh + (size_t)j * Hz + kp * 2);
        __nv_bfloat16 h0 = __float2bfloat16(v.x);
        __nv_bfloat16 h1 = __float2bfloat16(v.y);
        __nv_bfloat16 l0 = __float2bfloat16(v.x - __bfloat162float(h0));
        __nv_bfloat16 l1 = __float2bfloat16(v.y - __bfloat162float(h1));
        int c  = kp >> 5;
        int kb = (kp & 31) * 4;
        uint32_t off = c * 4096 + r * 128 + ((uint32_t)kb ^ (((uint32_t)r & 7) << 4));
        *(__nv_bfloat162*)(smem + R_WHH + off) = __halves2bfloat162(h0, h1);
        *(__nv_bfloat162*)(smem + R_WHL + off) = __halves2bfloat162(l0, l1);
    }
    for (int i = tid; i < 512; i += 256) cs[i] = 0.f;
    if (tid < 64) ls[tid] = lengths[tid];
    __syncthreads();
    // active-prefix table: nbArr[t] = #{b : len[b] > t}
    for (int t = tid; t < 512; t += 256) {
        int cnt = 0;
#pragma unroll 16
        for (int b = 0; b < 64; b++) cnt += (ls[b] > t) ? 1 : 0;
        nbArr[t] = cnt;
    }
    __syncthreads();

    // warp tiling: 4m x 2n; warp tile m16 x n16
    const int m0w = (wid & 3) * 16;
    const int n0w = (wid >> 2) * 16;
    const int a_row = m0w + (lane & 15);
    const uint32_t a_klane = (lane >> 4) * 16;
    const int b_row = n0w + ((lane >> 4) * 8) + (lane & 7);
    const uint32_t b_klane = ((lane >> 3) & 1) * 16;
    const uint32_t aOff = a_row * 128 + (((uint32_t)a_row & 7) << 4);
    const uint32_t bOff = b_row * 128 + (((uint32_t)b_row & 7) << 4);

    const int l_row = tid >> 3;
    const int l_g   = tid & 7;

    for (int s = 0; s < Tz; s++) {
        const int t   = dir ? (Tz - 1 - s) : s;
        const int par = s & 1;
        const int nb  = nbArr[t];
        const int nbr = (nb + 15) & ~15;
        const __nv_bfloat16* hh = g_hh[par] + dir * Bz * Hz;
        const __nv_bfloat16* hl = g_hl[par] + dir * Bz * Hz;
        __nv_bfloat16* hho = g_hh[par ^ 1] + dir * Bz * Hz;
        __nv_bfloat16* hlo = g_hl[par ^ 1] + dir * Bz * Hz;

        auto load_h = [&](int c, int buf) {
            uint32_t dhi = sbase + R_HB + buf * 16384;
#pragma unroll
            for (int i = 0; i < 2; i++) {
                int b = l_row + i * 32;
                if (b < nbr) {
                    uint32_t off = b * 128 + ((l_g * 16) ^ ((b & 7) << 4));
                    CP_ASYNC16(dhi + off,
                               (const char*)(hh + (size_t)b * Hz + c * 64) + l_g * 16);
                    CP_ASYNC16(dhi + 8192 + off,
                               (const char*)(hl + (size_t)b * Hz + c * 64) + l_g * 16);
                }
            }
        };

        // xg prefetch (active rows only) bundled with chunk-0's commit group
        {
            const float* xg0 = g_xg + ((size_t)t * Bz) * NG + (size_t)dir * G4 + n0;
#pragma unroll
            for (int i = 0; i < 2; i++) {
                int e = tid + i * 256;
                int b = e >> 3;
                if (b < nb) {
                    int g  = (e >> 1) & 3;
                    int hf = e & 1;
                    uint32_t dst = sbase + R_XG + (b * 40 + g * 8 + hf * 4) * 4;
                    CP_ASYNC16(dst, xg0 + (size_t)b * NG + g * Hz + hf * 4);
                }
            }
        }
        load_h(0, 0); CP_COMMIT();
        load_h(1, 1); CP_COMMIT();

        float c0[4] = {0.f, 0.f, 0.f, 0.f};
        float c1[4] = {0.f, 0.f, 0.f, 0.f};
        const bool wactive = (m0w < nbr);

        for (int ch = 0; ch < 8; ch++) {
            if (ch == 7) CP_WAIT0(); else CP_WAIT1();
            __syncthreads();
            if (wactive) {
                const uint32_t ahB = sbase + R_HB + (ch & 1) * 16384 + aOff;
                const uint32_t alB = ahB + 8192;
                const uint32_t bhB = sbase + R_WHH + ch * 4096 + bOff;
                const uint32_t blB = bhB + 32768;
#pragma unroll
                for (int ks = 0; ks < 4; ks++) {
                    const uint32_t kA = ks * 32 + a_klane;
                    const uint32_t kB = ks * 32 + b_klane;
                    uint32_t ah[4], al[4], bhh[4], bll[4];
                    ldsm4(ah,  ahB ^ kA);
                    ldsm4(al,  alB ^ kA);
                    ldsm4(bhh, bhB ^ kB);
                    ldsm4(bll, blB ^ kB);
                    mma16816(c0, ah, bhh);
                    mma16816(c0, ah, bll);
                    mma16816(c0, al, bhh);
                    mma16816(c1, ah, bhh + 2);
                    mma16816(c1, ah, bll + 2);
                    mma16816(c1, al, bhh + 2);
                }
            }
            __syncthreads();
            if (ch + 2 < 8) { load_h(ch + 2, ch & 1); CP_COMMIT(); }
        }

        // write fragments to gs[col(r)][row(b)]
        if (wactive) {
            const int row0 = m0w + (lane >> 2);
            const int col0 = n0w + (lane & 3) * 2;
            gs[(col0)     * 68 + row0]     = c0[0];
            gs[(col0 + 1) * 68 + row0]     = c0[1];
            gs[(col0)     * 68 + row0 + 8] = c0[2];
            gs[(col0 + 1) * 68 + row0 + 8] = c0[3];
            gs[(col0 + 8) * 68 + row0]     = c1[0];
            gs[(col0 + 9) * 68 + row0]     = c1[1];
            gs[(col0 + 8) * 68 + row0 + 8] = c1[2];
            gs[(col0 + 9) * 68 + row0 + 8] = c1[3];
        }
        __syncthreads();

        // output phase: active rows only (b < nb => mask is always true)
        for (int o = tid; o < nb * 8; o += 256) {
            int nl = o & 7;
            int b  = o >> 3;
            int n  = n0 + nl;
            const float* xr = xg_s + b * 40;
            float gi = gs[(0 * 8 + nl) * 68 + b] + xr[0 * 8 + nl];
            float gf = gs[(1 * 8 + nl) * 68 + b] + xr[1 * 8 + nl];
            float gg = gs[(2 * 8 + nl) * 68 + b] + xr[2 * 8 + nl];
            float go = gs[(3 * 8 + nl) * 68 + b] + xr[3 * 8 + nl];
            float iv = 1.f / (1.f + expf(-gi));
            float fv = 1.f / (1.f + expf(-gf));
            float gv = tanhf(gg);
            float ov = 1.f / (1.f + expf(-go));
            float cn = fv * cs[o] + iv * gv;
            float hn = ov * tanhf(cn);
            cs[o] = cn;
            __nv_bfloat16 hhi = __float2bfloat16(hn);
            hho[b * Hz + n] = hhi;
            hlo[b * Hz + n] = __float2bfloat16(hn - __bfloat162float(hhi));
            if (wsplit) {
                size_t yo = ((size_t)t * Bz + b) * 1024 + (size_t)dir * Hz + n;
                __nv_bfloat16 yh = __float2bfloat16(hn);
                g_Ah[yo] = yh;
                g_Al[yo] = __float2bfloat16(hn - __bfloat162float(yh));
            } else {
                Y[((size_t)b * Tz + t) * (2 * Hz) + (size_t)dir * Hz + n] = hn;
            }
            // final state: last active step (fwd: t==len-1, bwd: t==0)
            if (t == (dir ? 0 : (ls[b] - 1))) {
                g_hf[dir * Bz * Hz + b * Hz + n] = hn;
                g_c [dir * Bz * Hz + b * Hz + n] = cn;
            }
        }

        if (s < Tz - 1) grid_barrier_dir(dir, (unsigned)(s + 1) * 64);
    }

    // self-resetting exit
    __threadfence();
    __syncthreads();
    if (tid == 0) {
        unsigned d = atomicAdd(&g_done, 1u);
        if (d == NCTA - 1) {
            atomicExch(&g_bar2[0], 0u);
            atomicExch(&g_bar2[32], 0u);
            atomicExch(&g_done, 0u);
            __threadfence();
        }
    }
}

// copy final states into d_out hN/cN sections
__global__ void copy_states(float* __restrict__ out_h, float* __restrict__ out_c)
{
    int i = blockIdx.x * blockDim.x + threadIdx.x;
    if (i < 2 * Bz * Hz) {
        out_h[i] = g_hf[i];
        out_c[i] = g_c[i];
    }
}

extern "C" void kernel_launch(void* const* d_in, const int* in_sizes, int n_in,
                              void* d_out, int out_size)
{
    const float* x      = (const float*)d_in[0];
    const int*  lengths = (const int*)  d_in[1];
    const float* Wi_f0 = (const float*)d_in[2];
    const float* Wh_f0 = (const float*)d_in[3];
    const float* b_f0  = (const float*)d_in[4];
    const float* Wi_b0 = (const float*)d_in[5];
    const float* Wh_b0 = (const float*)d_in[6];
    const float* b_b0  = (const float*)d_in[7];
    const float* Wi_f1 = (const float*)d_in[8];
    const float* Wh_f1 = (const float*)d_in[9];
    const float* b_f1  = (const float*)d_in[10];
    const float* Wi_b1 = (const float*)d_in[11];
    const float* Wh_b1 = (const float*)d_in[12];
    const float* b_b1  = (const float*)d_in[13];
    float* out = (float*)d_out;

    cudaFuncSetAttribute(lstm_layer_tc,
                         cudaFuncAttributeMaxDynamicSharedMemorySize, R_SMEM);
    cudaFuncSetAttribute(gemm_mma,
                         cudaFuncAttributeMaxDynamicSharedMemorySize, SMEM_TC);

    __nv_bfloat16 *ahp, *alp, *hhp, *hlp;
    cudaGetSymbolAddress((void**)&ahp,  g_Ah);
    cudaGetSymbolAddress((void**)&alp,  g_Al);
    cudaGetSymbolAddress((void**)&hhp,  g_hh);
    cudaGetSymbolAddress((void**)&hlp,  g_hl);

    const dim3 gemm_grid(NG / 128, Mz / 128);
    const int  copy_blocks = (2 * Bz * Hz + 255) / 256;
    const size_t hbbytes = sizeof(__nv_bfloat16) * 2 * 2 * Bz * Hz;

    // masked Y elements are never written by the recurrence: pre-zero them
    cudaMemsetAsync(out, 0, XOUT * sizeof(float));

    // ---- layer 0 (K = 512) ----
    cudaMemsetAsync(hhp, 0, hbbytes);
    cudaMemsetAsync(hlp, 0, hbbytes);
    split_x<<<dim3(Mz, 1), 128>>>(x, Dz, ahp, alp);
    split_w<<<dim3(NG, 1), 128>>>(Wi_f0, Wi_b0, Dz);
    gemm_mma<<<gemm_grid, 256, SMEM_TC>>>(Dz, b_f0, b_b0);
    // zero layer-1 A operand (masked y rows must read as 0)
    cudaMemsetAsync(ahp, 0, (size_t)Mz * 1024 * sizeof(__nv_bfloat16));
    cudaMemsetAsync(alp, 0, (size_t)Mz * 1024 * sizeof(__nv_bfloat16));
    lstm_layer_tc<<<NCTA, 256, R_SMEM>>>(Wh_f0, Wh_b0, lengths, out, 1);
    copy_states<<<copy_blocks, 256>>>(out + XOUT,
                                      out + XOUT + 4 * Bz * Hz);

    // ---- layer 1 (K = 1024; A operand written by layer-0 recurrence) ----
    cudaMemsetAsync(hhp, 0, hbbytes);
    cudaMemsetAsync(hlp, 0, hbbytes);
    split_w<<<dim3(NG, 2), 128>>>(Wi_f1, Wi_b1, 2 * Hz);
    gemm_mma<<<gemm_grid, 256, SMEM_TC>>>(2 * Hz, b_f1, b_b1);
    lstm_layer_tc<<<NCTA, 256, R_SMEM>>>(Wh_f1, Wh_b1, lengths, out, 0);
    copy_states<<<copy_blocks, 256>>>(out + XOUT + 2 * Bz * Hz,
                                      out + XOUT + 4 * Bz * Hz + 2 * Bz * Hz);
}

// round 13
// speedup vs baseline: 3.7376x; 1.0101x over previous
#include <cuda_runtime.h>
#include <cuda_bf16.h>
#include <math.h>
#include <stdint.h>

// Problem constants
#define Bz 64
#define Tz 512
#define Dz 512
#define Hz 512
#define G4 (4*Hz)        // 2048 gates per direction
#define NG (2*G4)        // 4096 gates both directions (fused GEMM N)
#define Mz (Bz*Tz)       // 32768 GEMM rows
#define NCTA 128         // persistent recurrence CTAs
#define XOUT ((size_t)Bz*Tz*2*Hz)

// Scratch (static device globals — no allocation)
__device__ float g_xg[(size_t)Tz*Bz*NG];       // [t*B+b][dir*2048 + gate*512 + n]
__device__ float g_hf[2*Bz*Hz];                // final h per layer ([dir][b][n])
__device__ float g_c[2*Bz*Hz];                 // final c per layer
__device__ unsigned g_bar2[64];                // per-dir barrier counters ([0],[32])
__device__ unsigned g_done;
// bf16 hi/lo split operands for tensor-core GEMM (K-major rows)
__device__ __align__(16) __nv_bfloat16 g_Ah[(size_t)Mz*1024];
__device__ __align__(16) __nv_bfloat16 g_Al[(size_t)Mz*1024];
__device__ __align__(16) __nv_bfloat16 g_Bh[(size_t)NG*1024];
__device__ __align__(16) __nv_bfloat16 g_Bl[(size_t)NG*1024];
// bf16 hi/lo ping-pong h for the tensor-core recurrence
__device__ __align__(16) __nv_bfloat16 g_hh[2][2*Bz*Hz];
__device__ __align__(16) __nv_bfloat16 g_hl[2][2*Bz*Hz];

// ===========================================================================
// PTX helpers — only baseline (non-'a') features: mma.sync, ldmatrix, cp.async
// ===========================================================================
__device__ __forceinline__ uint32_t smem_u32(const void* p) {
    uint32_t a;
    asm("{ .reg .u64 t; cvta.to.shared.u64 t, %1; cvt.u32.u64 %0, t; }"
        : "=r"(a) : "l"(p));
    return a;
}
__device__ __forceinline__ void ldsm4(uint32_t* r, uint32_t addr) {
    asm volatile("ldmatrix.sync.aligned.m8n8.x4.shared.b16 {%0,%1,%2,%3}, [%4];"
                 : "=r"(r[0]), "=r"(r[1]), "=r"(r[2]), "=r"(r[3]) : "r"(addr));
}
__device__ __forceinline__ void mma16816(float* c, const uint32_t* a, const uint32_t* b) {
    asm volatile("mma.sync.aligned.m16n8k16.row.col.f32.bf16.bf16.f32 "
                 "{%0,%1,%2,%3}, {%4,%5,%6,%7}, {%8,%9}, {%0,%1,%2,%3};"
                 : "+f"(c[0]), "+f"(c[1]), "+f"(c[2]), "+f"(c[3])
                 : "r"(a[0]), "r"(a[1]), "r"(a[2]), "r"(a[3]),
                   "r"(b[0]), "r"(b[1]));
}
#define CP_ASYNC16(dst, src) \
    asm volatile("cp.async.cg.shared.global [%0], [%1], 16;" :: "r"(dst), "l"(src))
#define CP_COMMIT() asm volatile("cp.async.commit_group;" ::: "memory")
#define CP_WAIT1()  asm volatile("cp.async.wait_group 1;" ::: "memory")
#define CP_WAIT0()  asm volatile("cp.async.wait_group 0;" ::: "memory")

// ===========================================================================
// Conversion: fp32 -> bf16 hi + bf16 lo, with [b][t] -> m=t*B+b transpose.
// ===========================================================================
__global__ void __launch_bounds__(128)
split_x(const float* __restrict__ src, int K,
        __nv_bfloat16* __restrict__ dh, __nv_bfloat16* __restrict__ dl)
{
    const int m = blockIdx.x;
    const int k = blockIdx.y * 512 + threadIdx.x * 4;
    const int srow = (m & 63) * Tz + (m >> 6);
    float4 v = *(const float4*)(src + (size_t)srow * K + k);
    __nv_bfloat16 h0 = __float2bfloat16(v.x);
    __nv_bfloat16 h1 = __float2bfloat16(v.y);
    __nv_bfloat16 h2 = __float2bfloat16(v.z);
    __nv_bfloat16 h3 = __float2bfloat16(v.w);
    __nv_bfloat16 l0 = __float2bfloat16(v.x - __bfloat162float(h0));
    __nv_bfloat16 l1 = __float2bfloat16(v.y - __bfloat162float(h1));
    __nv_bfloat16 l2 = __float2bfloat16(v.z - __bfloat162float(h2));
    __nv_bfloat16 l3 = __float2bfloat16(v.w - __bfloat162float(h3));
    size_t o = (size_t)m * K + k;
    *(__nv_bfloat162*)(dh + o)     = __halves2bfloat162(h0, h1);
    *(__nv_bfloat162*)(dh + o + 2) = __halves2bfloat162(h2, h3);
    *(__nv_bfloat162*)(dl + o)     = __halves2bfloat162(l0, l1);
    *(__nv_bfloat162*)(dl + o + 2) = __halves2bfloat162(l2, l3);
}

__global__ void __launch_bounds__(128)
split_w(const float* __restrict__ Wf, const float* __restrict__ Wb, int K)
{
    const int n = blockIdx.x;
    const int k = blockIdx.y * 512 + threadIdx.x * 4;
    const float* src = (n < G4) ? (Wf + (size_t)n * K) : (Wb + (size_t)(n - G4) * K);
    float4 v = *(const float4*)(src + k);
    __nv_bfloat16 h0 = __float2bfloat16(v.x);
    __nv_bfloat16 h1 = __float2bfloat16(v.y);
    __nv_bfloat16 h2 = __float2bfloat16(v.z);
    __nv_bfloat16 h3 = __float2bfloat16(v.w);
    __nv_bfloat16 l0 = __float2bfloat16(v.x - __bfloat162float(h0));
    __nv_bfloat16 l1 = __float2bfloat16(v.y - __bfloat162float(h1));
    __nv_bfloat16 l2 = __float2bfloat16(v.z - __bfloat162float(h2));
    __nv_bfloat16 l3 = __float2bfloat16(v.w - __bfloat162float(h3));
    size_t o = (size_t)n * K + k;
    *(__nv_bfloat162*)(g_Bh + o)     = __halves2bfloat162(h0, h1);
    *(__nv_bfloat162*)(g_Bh + o + 2) = __halves2bfloat162(h2, h3);
    *(__nv_bfloat162*)(g_Bl + o)     = __halves2bfloat162(l0, l1);
    *(__nv_bfloat162*)(g_Bl + o + 2) = __halves2bfloat162(l2, l3);
}

// ===========================================================================
// bf16 mma.sync GEMM with 3-term compensation.
// CTA tile 128(m) x 256(n), 512 threads (16 warps as 2m x 8n, warp tile
// 64x32 — identical inner loop to the proven R5-R12 kernel). K-chunks of 64,
// 2-stage cp.async pipeline. Smem/stage: Ah 16K | Al 16K | Bh 32K | Bl 32K.
// ===========================================================================
#define GM_AH   0
#define GM_AL   16384
#define GM_BH   32768
#define GM_BL   65536
#define GM_STAGE 98304
#define GM_BIAS (2*GM_STAGE)          // 196608
#define GM_SMEM (GM_BIAS + 1024)      // 197632 bytes

__global__ void __launch_bounds__(512, 1)
gemm_mma(int K, const float* __restrict__ bfp, const float* __restrict__ bbp)
{
    extern __shared__ char smem[];
    const uint32_t sbase = smem_u32(smem);
    const int tid  = threadIdx.x;
    const int wid  = tid >> 5;
    const int lane = tid & 31;
    const int n0 = blockIdx.x * 256;
    const int m0 = blockIdx.y * 128;
    const int nchunks = K / 64;

    float* bias_s = (float*)(smem + GM_BIAS);
    if (tid < 256) {
        int n = n0 + tid;
        bias_s[tid] = (n < G4) ? bfp[n] : bbp[n - G4];
    }

    const char* srcAh = (const char*)(g_Ah + (size_t)m0 * K);
    const char* srcAl = (const char*)(g_Al + (size_t)m0 * K);
    const char* srcBh = (const char*)(g_Bh + (size_t)n0 * K);
    const char* srcBl = (const char*)(g_Bl + (size_t)n0 * K);

    auto load_chunk = [&](int c, int st) {
        const uint32_t base = sbase + st * GM_STAGE;
        const size_t koff = (size_t)c * 128;
        // A: 128 rows x 8 groups, hi+lo (2 iters x 512 threads)
#pragma unroll
        for (int i = 0; i < 2; i++) {
            int idx = tid + i * 512;
            int row = idx >> 3;
            int g   = idx & 7;
            uint32_t off = row * 128 + ((g * 16) ^ ((row & 7) << 4));
            const size_t so = (size_t)row * K * 2 + koff + g * 16;
            CP_ASYNC16(base + GM_AH + off, srcAh + so);
            CP_ASYNC16(base + GM_AL + off, srcAl + so);
        }
        // B: 256 rows x 8 groups, hi+lo (4 iters x 512 threads)
#pragma unroll
        for (int i = 0; i < 4; i++) {
            int idx = tid + i * 512;
            int row = idx >> 3;
            int g   = idx & 7;
            uint32_t off = row * 128 + ((g * 16) ^ ((row & 7) << 4));
            const size_t so = (size_t)row * K * 2 + koff + g * 16;
            CP_ASYNC16(base + GM_BH + off, srcBh + so);
            CP_ASYNC16(base + GM_BL + off, srcBl + so);
        }
    };

    // warp tiling: 2m x 8n, warp tile 64x32
    const int m0w = (wid & 1) * 64;
    const int n0w = (wid >> 1) * 32;

    uint32_t aBase[4];
    const int a_row_l = (lane & 15);
    const uint32_t a_klane = (lane >> 4) * 16;
#pragma unroll
    for (int mi = 0; mi < 4; mi++) {
        int row = m0w + mi * 16 + a_row_l;
        aBase[mi] = row * 128 + ((row & 7) << 4);
    }
    uint32_t bBase[2];
    const int b_row_l = ((lane >> 4) * 8) + (lane & 7);
    const uint32_t b_klane = ((lane >> 3) & 1) * 16;
#pragma unroll
    for (int nj = 0; nj < 2; nj++) {
        int row = n0w + nj * 16 + b_row_l;
        bBase[nj] = row * 128 + ((row & 7) << 4);
    }

    float c[4][4][4];
#pragma unroll
    for (int mi = 0; mi < 4; mi++)
#pragma unroll
        for (int ni = 0; ni < 4; ni++)
#pragma unroll
            for (int q = 0; q < 4; q++) c[mi][ni][q] = 0.f;

    load_chunk(0, 0); CP_COMMIT();
    if (nchunks > 1) { load_chunk(1, 1); CP_COMMIT(); }

    for (int ch = 0; ch < nchunks; ch++) {
        if (ch == nchunks - 1) CP_WAIT0(); else CP_WAIT1();
        __syncthreads();

        const uint32_t stb = sbase + (ch & 1) * GM_STAGE;
        const uint32_t bufA_h = stb + GM_AH;
        const uint32_t bufA_l = stb + GM_AL;
        const uint32_t bufB_h = stb + GM_BH;
        const uint32_t bufB_l = stb + GM_BL;

#pragma unroll
        for (int ks = 0; ks < 4; ks++) {
            const uint32_t kbA = ks * 32 + a_klane;
            const uint32_t kbB = ks * 32 + b_klane;
            uint32_t ah[4][4], al[4][4], bh[4][2], bl[4][2];
#pragma unroll
            for (int mi = 0; mi < 4; mi++) {
                ldsm4(ah[mi], (bufA_h + aBase[mi]) ^ kbA);
                ldsm4(al[mi], (bufA_l + aBase[mi]) ^ kbA);
            }
#pragma unroll
            for (int nj = 0; nj < 2; nj++) {
                uint32_t r[4];
                ldsm4(r, (bufB_h + bBase[nj]) ^ kbB);
                bh[nj * 2][0] = r[0]; bh[nj * 2][1] = r[1];
                bh[nj * 2 + 1][0] = r[2]; bh[nj * 2 + 1][1] = r[3];
                ldsm4(r, (bufB_l + bBase[nj]) ^ kbB);
                bl[nj * 2][0] = r[0]; bl[nj * 2][1] = r[1];
                bl[nj * 2 + 1][0] = r[2]; bl[nj * 2 + 1][1] = r[3];
            }
#pragma unroll
            for (int mi = 0; mi < 4; mi++)
#pragma unroll
                for (int ni = 0; ni < 4; ni++) {
                    mma16816(c[mi][ni], ah[mi], bh[ni]);
                    mma16816(c[mi][ni], ah[mi], bl[ni]);
                    mma16816(c[mi][ni], al[mi], bh[ni]);
                }
        }
        __syncthreads();
        if (ch + 2 < nchunks) { load_chunk(ch + 2, ch & 1); CP_COMMIT(); }
    }

    const int er = lane >> 2;
    const int ec = (lane & 3) * 2;
#pragma unroll
    for (int mi = 0; mi < 4; mi++) {
        int row0 = m0 + m0w + mi * 16 + er;
#pragma unroll
        for (int ni = 0; ni < 4; ni++) {
            int nloc = n0w + ni * 8 + ec;
            int coln = n0 + nloc;
            float b0 = bias_s[nloc], b1 = bias_s[nloc + 1];
            float* p0 = g_xg + (size_t)row0 * NG + coln;
            float* p1 = g_xg + (size_t)(row0 + 8) * NG + coln;
            *(float2*)p0 = make_float2(c[mi][ni][0] + b0, c[mi][ni][1] + b1);
            *(float2*)p1 = make_float2(c[mi][ni][2] + b0, c[mi][ni][3] + b1);
        }
    }
}

// ===========================================================================
// Tensor-core persistent recurrence with active-prefix masking.
// (unchanged from R12 PASS)
// ===========================================================================
#define R_WHH 0                    // 8 chunk-tiles x 4KB = 32KB (Wh hi)
#define R_WHL 32768                // 32KB (Wh lo)
#define R_HB  65536                // 2 bufs x (hi 8KB + lo 8KB) = 32KB
#define R_GS  98304                // float gs[32][68] = 8704B
#define R_CS  107008               // 512 floats
#define R_LS  109056               // 64 ints
#define R_XG  109312               // float xg_s[64][40] = 10240B
#define R_NB  119552               // int nbArr[512] = 2048B
#define R_SMEM 121600

__device__ __forceinline__ void grid_barrier_dir(int dir, unsigned target)
{
    __syncthreads();
    if (threadIdx.x == 0) {
        unsigned* ctr = &g_bar2[dir * 32];
        __threadfence();
        atomicAdd(ctr, 1u);
        int backoff = 32;
        for (;;) {
            unsigned v;
            asm volatile("ld.acquire.gpu.global.u32 %0, [%1];"
                         : "=r"(v) : "l"(ctr));
            if (v >= target) break;
            __nanosleep(backoff);
            if (backoff < 256) backoff <<= 1;
        }
    }
    __syncthreads();
}

__global__ void __launch_bounds__(256, 1)
lstm_layer_tc(const float* __restrict__ Whf, const float* __restrict__ Whb,
              const int* __restrict__ lengths, float* __restrict__ Y,
              int wsplit)
{
    extern __shared__ char smem[];
    const uint32_t sbase = smem_u32(smem);
    float* gs    = (float*)(smem + R_GS);
    float* cs    = (float*)(smem + R_CS);
    int*   ls    = (int*)(smem + R_LS);
    float* xg_s  = (float*)(smem + R_XG);
    int*   nbArr = (int*)(smem + R_NB);

    const int bid = blockIdx.x;
    const int dir = bid >> 6;
    const int n0  = (bid & 63) * 8;
    const float* Wh = dir ? Whb : Whf;

    const int tid  = threadIdx.x;
    const int wid  = tid >> 5;
    const int lane = tid & 31;

    // ---- one-time: Wh slice -> smem, split hi/lo, SW128-swizzled ----
    for (int idx = tid; idx < 8192; idx += 256) {
        int r  = idx >> 8;
        int kp = idx & 255;
        int j  = (r >> 3) * Hz + n0 + (r & 7);
        float2 v = *(const float2*)(Wh + (size_t)j * Hz + kp * 2);
        __nv_bfloat16 h0 = __float2bfloat16(v.x);
        __nv_bfloat16 h1 = __float2bfloat16(v.y);
        __nv_bfloat16 l0 = __float2bfloat16(v.x - __bfloat162float(h0));
        __nv_bfloat16 l1 = __float2bfloat16(v.y - __bfloat162float(h1));
        int c  = kp >> 5;
        int kb = (kp & 31) * 4;
        uint32_t off = c * 4096 + r * 128 + ((uint32_t)kb ^ (((uint32_t)r & 7) << 4));
        *(__nv_bfloat162*)(smem + R_WHH + off) = __halves2bfloat162(h0, h1);
        *(__nv_bfloat162*)(smem + R_WHL + off) = __halves2bfloat162(l0, l1);
    }
    for (int i = tid; i < 512; i += 256) cs[i] = 0.f;
    if (tid < 64) ls[tid] = lengths[tid];
    __syncthreads();
    // active-prefix table: nbArr[t] = #{b : len[b] > t}
    for (int t = tid; t < 512; t += 256) {
        int cnt = 0;
#pragma unroll 16
        for (int b = 0; b < 64; b++) cnt += (ls[b] > t) ? 1 : 0;
        nbArr[t] = cnt;
    }
    __syncthreads();

    // warp tiling: 4m x 2n; warp tile m16 x n16
    const int m0w = (wid & 3) * 16;
    const int n0w = (wid >> 2) * 16;
    const int a_row = m0w + (lane & 15);
    const uint32_t a_klane = (lane >> 4) * 16;
    const int b_row = n0w + ((lane >> 4) * 8) + (lane & 7);
    const uint32_t b_klane = ((lane >> 3) & 1) * 16;
    const uint32_t aOff = a_row * 128 + (((uint32_t)a_row & 7) << 4);
    const uint32_t bOff = b_row * 128 + (((uint32_t)b_row & 7) << 4);

    const int l_row = tid >> 3;
    const int l_g   = tid & 7;

    for (int s = 0; s < Tz; s++) {
        const int t   = dir ? (Tz - 1 - s) : s;
        const int par = s & 1;
        const int nb  = nbArr[t];
        const int nbr = (nb + 15) & ~15;
        const __nv_bfloat16* hh = g_hh[par] + dir * Bz * Hz;
        const __nv_bfloat16* hl = g_hl[par] + dir * Bz * Hz;
        __nv_bfloat16* hho = g_hh[par ^ 1] + dir * Bz * Hz;
        __nv_bfloat16* hlo = g_hl[par ^ 1] + dir * Bz * Hz;

        auto load_h = [&](int c, int buf) {
            uint32_t dhi = sbase + R_HB + buf * 16384;
#pragma unroll
            for (int i = 0; i < 2; i++) {
                int b = l_row + i * 32;
                if (b < nbr) {
                    uint32_t off = b * 128 + ((l_g * 16) ^ ((b & 7) << 4));
                    CP_ASYNC16(dhi + off,
                               (const char*)(hh + (size_t)b * Hz + c * 64) + l_g * 16);
                    CP_ASYNC16(dhi + 8192 + off,
                               (const char*)(hl + (size_t)b * Hz + c * 64) + l_g * 16);
                }
            }
        };

        // xg prefetch (active rows only) bundled with chunk-0's commit group
        {
            const float* xg0 = g_xg + ((size_t)t * Bz) * NG + (size_t)dir * G4 + n0;
#pragma unroll
            for (int i = 0; i < 2; i++) {
                int e = tid + i * 256;
                int b = e >> 3;
                if (b < nb) {
                    int g  = (e >> 1) & 3;
                    int hf = e & 1;
                    uint32_t dst = sbase + R_XG + (b * 40 + g * 8 + hf * 4) * 4;
                    CP_ASYNC16(dst, xg0 + (size_t)b * NG + g * Hz + hf * 4);
                }
            }
        }
        load_h(0, 0); CP_COMMIT();
        load_h(1, 1); CP_COMMIT();

        float c0[4] = {0.f, 0.f, 0.f, 0.f};
        float c1[4] = {0.f, 0.f, 0.f, 0.f};
        const bool wactive = (m0w < nbr);

        for (int ch = 0; ch < 8; ch++) {
            if (ch == 7) CP_WAIT0(); else CP_WAIT1();
            __syncthreads();
            if (wactive) {
                const uint32_t ahB = sbase + R_HB + (ch & 1) * 16384 + aOff;
                const uint32_t alB = ahB + 8192;
                const uint32_t bhB = sbase + R_WHH + ch * 4096 + bOff;
                const uint32_t blB = bhB + 32768;
#pragma unroll
                for (int ks = 0; ks < 4; ks++) {
                    const uint32_t kA = ks * 32 + a_klane;
                    const uint32_t kB = ks * 32 + b_klane;
                    uint32_t ah[4], al[4], bhh[4], bll[4];
                    ldsm4(ah,  ahB ^ kA);
                    ldsm4(al,  alB ^ kA);
                    ldsm4(bhh, bhB ^ kB);
                    ldsm4(bll, blB ^ kB);
                    mma16816(c0, ah, bhh);
                    mma16816(c0, ah, bll);
                    mma16816(c0, al, bhh);
                    mma16816(c1, ah, bhh + 2);
                    mma16816(c1, ah, bll + 2);
                    mma16816(c1, al, bhh + 2);
                }
            }
            __syncthreads();
            if (ch + 2 < 8) { load_h(ch + 2, ch & 1); CP_COMMIT(); }
        }

        // write fragments to gs[col(r)][row(b)]
        if (wactive) {
            const int row0 = m0w + (lane >> 2);
            const int col0 = n0w + (lane & 3) * 2;
            gs[(col0)     * 68 + row0]     = c0[0];
            gs[(col0 + 1) * 68 + row0]     = c0[1];
            gs[(col0)     * 68 + row0 + 8] = c0[2];
            gs[(col0 + 1) * 68 + row0 + 8] = c0[3];
            gs[(col0 + 8) * 68 + row0]     = c1[0];
            gs[(col0 + 9) * 68 + row0]     = c1[1];
            gs[(col0 + 8) * 68 + row0 + 8] = c1[2];
            gs[(col0 + 9) * 68 + row0 + 8] = c1[3];
        }
        __syncthreads();

        // output phase: active rows only (b < nb => mask is always true)
        for (int o = tid; o < nb * 8; o += 256) {
            int nl = o & 7;
            int b  = o >> 3;
            int n  = n0 + nl;
            const float* xr = xg_s + b * 40;
            float gi = gs[(0 * 8 + nl) * 68 + b] + xr[0 * 8 + nl];
            float gf = gs[(1 * 8 + nl) * 68 + b] + xr[1 * 8 + nl];
            float gg = gs[(2 * 8 + nl) * 68 + b] + xr[2 * 8 + nl];
            float go = gs[(3 * 8 + nl) * 68 + b] + xr[3 * 8 + nl];
            float iv = 1.f / (1.f + expf(-gi));
            float fv = 1.f / (1.f + expf(-gf));
            float gv = tanhf(gg);
            float ov = 1.f / (1.f + expf(-go));
            float cn = fv * cs[o] + iv * gv;
            float hn = ov * tanhf(cn);
            cs[o] = cn;
            __nv_bfloat16 hhi = __float2bfloat16(hn);
            hho[b * Hz + n] = hhi;
            hlo[b * Hz + n] = __float2bfloat16(hn - __bfloat162float(hhi));
            if (wsplit) {
                size_t yo = ((size_t)t * Bz + b) * 1024 + (size_t)dir * Hz + n;
                __nv_bfloat16 yh = __float2bfloat16(hn);
                g_Ah[yo] = yh;
                g_Al[yo] = __float2bfloat16(hn - __bfloat162float(yh));
            } else {
                Y[((size_t)b * Tz + t) * (2 * Hz) + (size_t)dir * Hz + n] = hn;
            }
            // final state: last active step (fwd: t==len-1, bwd: t==0)
            if (t == (dir ? 0 : (ls[b] - 1))) {
                g_hf[dir * Bz * Hz + b * Hz + n] = hn;
                g_c [dir * Bz * Hz + b * Hz + n] = cn;
            }
        }

        if (s < Tz - 1) grid_barrier_dir(dir, (unsigned)(s + 1) * 64);
    }

    // self-resetting exit
    __threadfence();
    __syncthreads();
    if (tid == 0) {
        unsigned d = atomicAdd(&g_done, 1u);
        if (d == NCTA - 1) {
            atomicExch(&g_bar2[0], 0u);
            atomicExch(&g_bar2[32], 0u);
            atomicExch(&g_done, 0u);
            __threadfence();
        }
    }
}

// copy final states into d_out hN/cN sections
__global__ void copy_states(float* __restrict__ out_h, float* __restrict__ out_c)
{
    int i = blockIdx.x * blockDim.x + threadIdx.x;
    if (i < 2 * Bz * Hz) {
        out_h[i] = g_hf[i];
        out_c[i] = g_c[i];
    }
}

extern "C" void kernel_launch(void* const* d_in, const int* in_sizes, int n_in,
                              void* d_out, int out_size)
{
    const float* x      = (const float*)d_in[0];
    const int*  lengths = (const int*)  d_in[1];
    const float* Wi_f0 = (const float*)d_in[2];
    const float* Wh_f0 = (const float*)d_in[3];
    const float* b_f0  = (const float*)d_in[4];
    const float* Wi_b0 = (const float*)d_in[5];
    const float* Wh_b0 = (const float*)d_in[6];
    const float* b_b0  = (const float*)d_in[7];
    const float* Wi_f1 = (const float*)d_in[8];
    const float* Wh_f1 = (const float*)d_in[9];
    const float* b_f1  = (const float*)d_in[10];
    const float* Wi_b1 = (const float*)d_in[11];
    const float* Wh_b1 = (const float*)d_in[12];
    const float* b_b1  = (const float*)d_in[13];
    float* out = (float*)d_out;

    cudaFuncSetAttribute(lstm_layer_tc,
                         cudaFuncAttributeMaxDynamicSharedMemorySize, R_SMEM);
    cudaFuncSetAttribute(gemm_mma,
                         cudaFuncAttributeMaxDynamicSharedMemorySize, GM_SMEM);

    __nv_bfloat16 *ahp, *alp, *hhp, *hlp;
    cudaGetSymbolAddress((void**)&ahp,  g_Ah);
    cudaGetSymbolAddress((void**)&alp,  g_Al);
    cudaGetSymbolAddress((void**)&hhp,  g_hh);
    cudaGetSymbolAddress((void**)&hlp,  g_hl);

    const dim3 gemm_grid(NG / 256, Mz / 128);
    const int  copy_blocks = (2 * Bz * Hz + 255) / 256;
    const size_t hbbytes = sizeof(__nv_bfloat16) * 2 * 2 * Bz * Hz;

    // masked Y elements are never written by the recurrence: pre-zero them
    cudaMemsetAsync(out, 0, XOUT * sizeof(float));

    // ---- layer 0 (K = 512) ----
    cudaMemsetAsync(hhp, 0, hbbytes);
    cudaMemsetAsync(hlp, 0, hbbytes);
    split_x<<<dim3(Mz, 1), 128>>>(x, Dz, ahp, alp);
    split_w<<<dim3(NG, 1), 128>>>(Wi_f0, Wi_b0, Dz);
    gemm_mma<<<gemm_grid, 512, GM_SMEM>>>(Dz, b_f0, b_b0);
    // zero layer-1 A operand (masked y rows must read as 0)
    cudaMemsetAsync(ahp, 0, (size_t)Mz * 1024 * sizeof(__nv_bfloat16));
    cudaMemsetAsync(alp, 0, (size_t)Mz * 1024 * sizeof(__nv_bfloat16));
    lstm_layer_tc<<<NCTA, 256, R_SMEM>>>(Wh_f0, Wh_b0, lengths, out, 1);
    copy_states<<<copy_blocks, 256>>>(out + XOUT,
                                      out + XOUT + 4 * Bz * Hz);

    // ---- layer 1 (K = 1024; A operand written by layer-0 recurrence) ----
    cudaMemsetAsync(hhp, 0, hbbytes);
    cudaMemsetAsync(hlp, 0, hbbytes);
    split_w<<<dim3(NG, 2), 128>>>(Wi_f1, Wi_b1, 2 * Hz);
    gemm_mma<<<gemm_grid, 512, GM_SMEM>>>(2 * Hz, b_f1, b_b1);
    lstm_layer_tc<<<NCTA, 256, R_SMEM>>>(Wh_f1, Wh_b1, lengths, out, 0);
    copy_states<<<copy_blocks, 256>>>(out + XOUT + 2 * Bz * Hz,
                                      out + XOUT + 4 * Bz * Hz + 2 * Bz * Hz);
}

// round 15
// speedup vs baseline: 4.0836x; 1.0926x over previous
#include <cuda_runtime.h>
#include <cuda_bf16.h>
#include <math.h>
#include <stdint.h>

// Problem constants
#define Bz 64
#define Tz 512
#define Dz 512
#define Hz 512
#define G4 (4*Hz)        // 2048 gates per direction
#define NG (2*G4)        // 4096 gates both directions (fused GEMM N)
#define Mz (Bz*Tz)       // 32768 GEMM rows
#define NCTA 128         // persistent recurrence CTAs
#define XOUT ((size_t)Bz*Tz*2*Hz)

// Scratch (static device globals — no allocation)
__device__ float g_xg[(size_t)Tz*Bz*NG];       // [t*B+b][dir*2048 + gate*512 + n]
__device__ float g_hf[2*Bz*Hz];                // final h per layer ([dir][b][n])
__device__ float g_c[2*Bz*Hz];                 // final c per layer
__device__ unsigned g_bar2[64];                // per-dir barrier counters ([0],[32])
__device__ unsigned g_done;
// bf16 hi/lo split operands for tensor-core GEMM (K-major rows)
__device__ __align__(16) __nv_bfloat16 g_Ah[(size_t)Mz*1024];
__device__ __align__(16) __nv_bfloat16 g_Al[(size_t)Mz*1024];
__device__ __align__(16) __nv_bfloat16 g_Bh[(size_t)NG*1024];
__device__ __align__(16) __nv_bfloat16 g_Bl[(size_t)NG*1024];
// bf16 hi/lo ping-pong h for the tensor-core recurrence
__device__ __align__(16) __nv_bfloat16 g_hh[2][2*Bz*Hz];
__device__ __align__(16) __nv_bfloat16 g_hl[2][2*Bz*Hz];

// ===========================================================================
// PTX helpers — only baseline (non-'a') features: mma.sync, ldmatrix, cp.async
// ===========================================================================
__device__ __forceinline__ uint32_t smem_u32(const void* p) {
    uint32_t a;
    asm("{ .reg .u64 t; cvta.to.shared.u64 t, %1; cvt.u32.u64 %0, t; }"
        : "=r"(a) : "l"(p));
    return a;
}
__device__ __forceinline__ void ldsm4(uint32_t* r, uint32_t addr) {
    asm volatile("ldmatrix.sync.aligned.m8n8.x4.shared.b16 {%0,%1,%2,%3}, [%4];"
                 : "=r"(r[0]), "=r"(r[1]), "=r"(r[2]), "=r"(r[3]) : "r"(addr));
}
__device__ __forceinline__ void mma16816(float* c, const uint32_t* a, const uint32_t* b) {
    asm volatile("mma.sync.aligned.m16n8k16.row.col.f32.bf16.bf16.f32 "
                 "{%0,%1,%2,%3}, {%4,%5,%6,%7}, {%8,%9}, {%0,%1,%2,%3};"
                 : "+f"(c[0]), "+f"(c[1]), "+f"(c[2]), "+f"(c[3])
                 : "r"(a[0]), "r"(a[1]), "r"(a[2]), "r"(a[3]),
                   "r"(b[0]), "r"(b[1]));
}
#define CP_ASYNC16(dst, src) \
    asm volatile("cp.async.cg.shared.global [%0], [%1], 16;" :: "r"(dst), "l"(src))
#define CP_COMMIT() asm volatile("cp.async.commit_group;" ::: "memory")
#define CP_WAIT1()  asm volatile("cp.async.wait_group 1;" ::: "memory")
#define CP_WAIT0()  asm volatile("cp.async.wait_group 0;" ::: "memory")

// ===========================================================================
// Conversion: fp32 -> bf16 hi + bf16 lo, with [b][t] -> m=t*B+b transpose.
// ===========================================================================
__global__ void __launch_bounds__(128)
split_x(const float* __restrict__ src, int K,
        __nv_bfloat16* __restrict__ dh, __nv_bfloat16* __restrict__ dl)
{
    const int m = blockIdx.x;
    const int k = blockIdx.y * 512 + threadIdx.x * 4;
    const int srow = (m & 63) * Tz + (m >> 6);
    float4 v = *(const float4*)(src + (size_t)srow * K + k);
    __nv_bfloat16 h0 = __float2bfloat16(v.x);
    __nv_bfloat16 h1 = __float2bfloat16(v.y);
    __nv_bfloat16 h2 = __float2bfloat16(v.z);
    __nv_bfloat16 h3 = __float2bfloat16(v.w);
    __nv_bfloat16 l0 = __float2bfloat16(v.x - __bfloat162float(h0));
    __nv_bfloat16 l1 = __float2bfloat16(v.y - __bfloat162float(h1));
    __nv_bfloat16 l2 = __float2bfloat16(v.z - __bfloat162float(h2));
    __nv_bfloat16 l3 = __float2bfloat16(v.w - __bfloat162float(h3));
    size_t o = (size_t)m * K + k;
    *(__nv_bfloat162*)(dh + o)     = __halves2bfloat162(h0, h1);
    *(__nv_bfloat162*)(dh + o + 2) = __halves2bfloat162(h2, h3);
    *(__nv_bfloat162*)(dl + o)     = __halves2bfloat162(l0, l1);
    *(__nv_bfloat162*)(dl + o + 2) = __halves2bfloat162(l2, l3);
}

__global__ void __launch_bounds__(128)
split_w(const float* __restrict__ Wf, const float* __restrict__ Wb, int K)
{
    const int n = blockIdx.x;
    const int k = blockIdx.y * 512 + threadIdx.x * 4;
    const float* src = (n < G4) ? (Wf + (size_t)n * K) : (Wb + (size_t)(n - G4) * K);
    float4 v = *(const float4*)(src + k);
    __nv_bfloat16 h0 = __float2bfloat16(v.x);
    __nv_bfloat16 h1 = __float2bfloat16(v.y);
    __nv_bfloat16 h2 = __float2bfloat16(v.z);
    __nv_bfloat16 h3 = __float2bfloat16(v.w);
    __nv_bfloat16 l0 = __float2bfloat16(v.x - __bfloat162float(h0));
    __nv_bfloat16 l1 = __float2bfloat16(v.y - __bfloat162float(h1));
    __nv_bfloat16 l2 = __float2bfloat16(v.z - __bfloat162float(h2));
    __nv_bfloat16 l3 = __float2bfloat16(v.w - __bfloat162float(h3));
    size_t o = (size_t)n * K + k;
    *(__nv_bfloat162*)(g_Bh + o)     = __halves2bfloat162(h0, h1);
    *(__nv_bfloat162*)(g_Bh + o + 2) = __halves2bfloat162(h2, h3);
    *(__nv_bfloat162*)(g_Bl + o)     = __halves2bfloat162(l0, l1);
    *(__nv_bfloat162*)(g_Bl + o + 2) = __halves2bfloat162(l2, l3);
}

// ===========================================================================
// bf16 mma.sync GEMM with 3-term compensation (unchanged from R13 PASS).
// CTA tile 128(m) x 256(n), 512 threads (16 warps as 2m x 8n, warp tile 64x32).
// ===========================================================================
#define GM_AH   0
#define GM_AL   16384
#define GM_BH   32768
#define GM_BL   65536
#define GM_STAGE 98304
#define GM_BIAS (2*GM_STAGE)          // 196608
#define GM_SMEM (GM_BIAS + 1024)      // 197632 bytes

__global__ void __launch_bounds__(512, 1)
gemm_mma(int K, const float* __restrict__ bfp, const float* __restrict__ bbp)
{
    extern __shared__ char smem[];
    const uint32_t sbase = smem_u32(smem);
    const int tid  = threadIdx.x;
    const int wid  = tid >> 5;
    const int lane = tid & 31;
    const int n0 = blockIdx.x * 256;
    const int m0 = blockIdx.y * 128;
    const int nchunks = K / 64;

    float* bias_s = (float*)(smem + GM_BIAS);
    if (tid < 256) {
        int n = n0 + tid;
        bias_s[tid] = (n < G4) ? bfp[n] : bbp[n - G4];
    }

    const char* srcAh = (const char*)(g_Ah + (size_t)m0 * K);
    const char* srcAl = (const char*)(g_Al + (size_t)m0 * K);
    const char* srcBh = (const char*)(g_Bh + (size_t)n0 * K);
    const char* srcBl = (const char*)(g_Bl + (size_t)n0 * K);

    auto load_chunk = [&](int c, int st) {
        const uint32_t base = sbase + st * GM_STAGE;
        const size_t koff = (size_t)c * 128;
#pragma unroll
        for (int i = 0; i < 2; i++) {
            int idx = tid + i * 512;
            int row = idx >> 3;
            int g   = idx & 7;
            uint32_t off = row * 128 + ((g * 16) ^ ((row & 7) << 4));
            const size_t so = (size_t)row * K * 2 + koff + g * 16;
            CP_ASYNC16(base + GM_AH + off, srcAh + so);
            CP_ASYNC16(base + GM_AL + off, srcAl + so);
        }
#pragma unroll
        for (int i = 0; i < 4; i++) {
            int idx = tid + i * 512;
            int row = idx >> 3;
            int g   = idx & 7;
            uint32_t off = row * 128 + ((g * 16) ^ ((row & 7) << 4));
            const size_t so = (size_t)row * K * 2 + koff + g * 16;
            CP_ASYNC16(base + GM_BH + off, srcBh + so);
            CP_ASYNC16(base + GM_BL + off, srcBl + so);
        }
    };

    const int m0w = (wid & 1) * 64;
    const int n0w = (wid >> 1) * 32;

    uint32_t aBase[4];
    const int a_row_l = (lane & 15);
    const uint32_t a_klane = (lane >> 4) * 16;
#pragma unroll
    for (int mi = 0; mi < 4; mi++) {
        int row = m0w + mi * 16 + a_row_l;
        aBase[mi] = row * 128 + ((row & 7) << 4);
    }
    uint32_t bBase[2];
    const int b_row_l = ((lane >> 4) * 8) + (lane & 7);
    const uint32_t b_klane = ((lane >> 3) & 1) * 16;
#pragma unroll
    for (int nj = 0; nj < 2; nj++) {
        int row = n0w + nj * 16 + b_row_l;
        bBase[nj] = row * 128 + ((row & 7) << 4);
    }

    float c[4][4][4];
#pragma unroll
    for (int mi = 0; mi < 4; mi++)
#pragma unroll
        for (int ni = 0; ni < 4; ni++)
#pragma unroll
            for (int q = 0; q < 4; q++) c[mi][ni][q] = 0.f;

    load_chunk(0, 0); CP_COMMIT();
    if (nchunks > 1) { load_chunk(1, 1); CP_COMMIT(); }

    for (int ch = 0; ch < nchunks; ch++) {
        if (ch == nchunks - 1) CP_WAIT0(); else CP_WAIT1();
        __syncthreads();

        const uint32_t stb = sbase + (ch & 1) * GM_STAGE;
        const uint32_t bufA_h = stb + GM_AH;
        const uint32_t bufA_l = stb + GM_AL;
        const uint32_t bufB_h = stb + GM_BH;
        const uint32_t bufB_l = stb + GM_BL;

#pragma unroll
        for (int ks = 0; ks < 4; ks++) {
            const uint32_t kbA = ks * 32 + a_klane;
            const uint32_t kbB = ks * 32 + b_klane;
            uint32_t ah[4][4], al[4][4], bh[4][2], bl[4][2];
#pragma unroll
            for (int mi = 0; mi < 4; mi++) {
                ldsm4(ah[mi], (bufA_h + aBase[mi]) ^ kbA);
                ldsm4(al[mi], (bufA_l + aBase[mi]) ^ kbA);
            }
#pragma unroll
            for (int nj = 0; nj < 2; nj++) {
                uint32_t r[4];
                ldsm4(r, (bufB_h + bBase[nj]) ^ kbB);
                bh[nj * 2][0] = r[0]; bh[nj * 2][1] = r[1];
                bh[nj * 2 + 1][0] = r[2]; bh[nj * 2 + 1][1] = r[3];
                ldsm4(r, (bufB_l + bBase[nj]) ^ kbB);
                bl[nj * 2][0] = r[0]; bl[nj * 2][1] = r[1];
                bl[nj * 2 + 1][0] = r[2]; bl[nj * 2 + 1][1] = r[3];
            }
#pragma unroll
            for (int mi = 0; mi < 4; mi++)
#pragma unroll
                for (int ni = 0; ni < 4; ni++) {
                    mma16816(c[mi][ni], ah[mi], bh[ni]);
                    mma16816(c[mi][ni], ah[mi], bl[ni]);
                    mma16816(c[mi][ni], al[mi], bh[ni]);
                }
        }
        __syncthreads();
        if (ch + 2 < nchunks) { load_chunk(ch + 2, ch & 1); CP_COMMIT(); }
    }

    const int er = lane >> 2;
    const int ec = (lane & 3) * 2;
#pragma unroll
    for (int mi = 0; mi < 4; mi++) {
        int row0 = m0 + m0w + mi * 16 + er;
#pragma unroll
        for (int ni = 0; ni < 4; ni++) {
            int nloc = n0w + ni * 8 + ec;
            int coln = n0 + nloc;
            float b0 = bias_s[nloc], b1 = bias_s[nloc + 1];
            float* p0 = g_xg + (size_t)row0 * NG + coln;
            float* p1 = g_xg + (size_t)(row0 + 8) * NG + coln;
            *(float2*)p0 = make_float2(c[mi][ni][0] + b0, c[mi][ni][1] + b1);
            *(float2*)p1 = make_float2(c[mi][ni][2] + b0, c[mi][ni][3] + b1);
        }
    }
}

// ===========================================================================
// Tensor-core persistent recurrence, flattened per-step pipeline:
// ALL h chunks (hi+lo, full K=512) + xg slab loaded in ONE cp.async group
// into smem (h fits: 128KB), then one wait + one sync + uninterrupted MMA
// burst over all 8 chunks. Per step: 2 syncthreads + grid barrier (was ~18).
// Active-prefix masking as in R12/R13. Accumulation order unchanged.
// ===========================================================================
#define R_WHH 0                    // 32KB  Wh hi (8 chunk-tiles x 4KB)
#define R_WHL 32768                // 32KB  Wh lo
#define R_HH  65536                // 64KB  h hi (8 chunk-tiles x 8KB)
#define R_HL  131072               // 64KB  h lo
#define R_GS  196608               // float gs[32][68] = 8704B
#define R_CS  205312               // 512 floats
#define R_LS  207360               // 64 ints
#define R_XG  207616               // float xg_s[64][40] = 10240B
#define R_NB  217856               // int nbArr[512] = 2048B
#define R_SMEM 219904

__device__ __forceinline__ void grid_barrier_dir(int dir, unsigned target)
{
    __syncthreads();
    if (threadIdx.x == 0) {
        unsigned* ctr = &g_bar2[dir * 32];
        __threadfence();
        atomicAdd(ctr, 1u);
        int backoff = 32;
        for (;;) {
            unsigned v;
            asm volatile("ld.acquire.gpu.global.u32 %0, [%1];"
                         : "=r"(v) : "l"(ctr));
            if (v >= target) break;
            __nanosleep(backoff);
            if (backoff < 256) backoff <<= 1;
        }
    }
    __syncthreads();
}

__global__ void __launch_bounds__(256, 1)
lstm_layer_tc(const float* __restrict__ Whf, const float* __restrict__ Whb,
              const int* __restrict__ lengths, float* __restrict__ Y,
              int wsplit)
{
    extern __shared__ char smem[];
    const uint32_t sbase = smem_u32(smem);
    float* gs    = (float*)(smem + R_GS);
    float* cs    = (float*)(smem + R_CS);
    int*   ls    = (int*)(smem + R_LS);
    float* xg_s  = (float*)(smem + R_XG);
    int*   nbArr = (int*)(smem + R_NB);

    const int bid = blockIdx.x;
    const int dir = bid >> 6;
    const int n0  = (bid & 63) * 8;
    const float* Wh = dir ? Whb : Whf;

    const int tid  = threadIdx.x;
    const int wid  = tid >> 5;
    const int lane = tid & 31;

    // ---- one-time: Wh slice -> smem, split hi/lo, SW128-swizzled ----
    for (int idx = tid; idx < 8192; idx += 256) {
        int r  = idx >> 8;
        int kp = idx & 255;
        int j  = (r >> 3) * Hz + n0 + (r & 7);
        float2 v = *(const float2*)(Wh + (size_t)j * Hz + kp * 2);
        __nv_bfloat16 h0 = __float2bfloat16(v.x);
        __nv_bfloat16 h1 = __float2bfloat16(v.y);
        __nv_bfloat16 l0 = __float2bfloat16(v.x - __bfloat162float(h0));
        __nv_bfloat16 l1 = __float2bfloat16(v.y - __bfloat162float(h1));
        int c  = kp >> 5;
        int kb = (kp & 31) * 4;
        uint32_t off = c * 4096 + r * 128 + ((uint32_t)kb ^ (((uint32_t)r & 7) << 4));
        *(__nv_bfloat162*)(smem + R_WHH + off) = __halves2bfloat162(h0, h1);
        *(__nv_bfloat162*)(smem + R_WHL + off) = __halves2bfloat162(l0, l1);
    }
    for (int i = tid; i < 512; i += 256) cs[i] = 0.f;
    if (tid < 64) ls[tid] = lengths[tid];
    __syncthreads();
    // active-prefix table: nbArr[t] = #{b : len[b] > t}
    for (int t = tid; t < 512; t += 256) {
        int cnt = 0;
#pragma unroll 16
        for (int b = 0; b < 64; b++) cnt += (ls[b] > t) ? 1 : 0;
        nbArr[t] = cnt;
    }
    __syncthreads();

    // warp tiling: 4m x 2n; warp tile m16 x n16
    const int m0w = (wid & 3) * 16;
    const int n0w = (wid >> 2) * 16;
    const int a_row = m0w + (lane & 15);
    const uint32_t a_klane = (lane >> 4) * 16;
    const int b_row = n0w + ((lane >> 4) * 8) + (lane & 7);
    const uint32_t b_klane = ((lane >> 3) & 1) * 16;
    const uint32_t aOff = a_row * 128 + (((uint32_t)a_row & 7) << 4);
    const uint32_t bOff = b_row * 128 + (((uint32_t)b_row & 7) << 4);

    for (int s = 0; s < Tz; s++) {
        const int t   = dir ? (Tz - 1 - s) : s;
        const int par = s & 1;
        const int nb  = nbArr[t];
        const int nbr = (nb + 15) & ~15;
        const __nv_bfloat16* hh = g_hh[par] + dir * Bz * Hz;
        const __nv_bfloat16* hl = g_hl[par] + dir * Bz * Hz;
        __nv_bfloat16* hho = g_hh[par ^ 1] + dir * Bz * Hz;
        __nv_bfloat16* hlo = g_hl[par ^ 1] + dir * Bz * Hz;

        // single cp.async group: xg slab (active rows) + full h hi/lo
        {
            const float* xg0 = g_xg + ((size_t)t * Bz) * NG + (size_t)dir * G4 + n0;
#pragma unroll
            for (int i = 0; i < 2; i++) {
                int e = tid + i * 256;
                int b = e >> 3;
                if (b < nb) {
                    int g  = (e >> 1) & 3;
                    int hf = e & 1;
                    uint32_t dst = sbase + R_XG + (b * 40 + g * 8 + hf * 4) * 4;
                    CP_ASYNC16(dst, xg0 + (size_t)b * NG + g * Hz + hf * 4);
                }
            }
            // h: nbr rows x 8 chunks x 8 groups of 16B, hi + lo
            for (int idx = tid; idx < nbr * 64; idx += 256) {
                int b = idx >> 6;
                int q = idx & 63;
                int c = q >> 3;
                int g = q & 7;
                uint32_t off = c * 8192 + b * 128 + (((uint32_t)g * 16) ^ (((uint32_t)b & 7) << 4));
                const char* sh = (const char*)(hh + (size_t)b * Hz + c * 64) + g * 16;
                const char* sl = (const char*)(hl + (size_t)b * Hz + c * 64) + g * 16;
                CP_ASYNC16(sbase + R_HH + off, sh);
                CP_ASYNC16(sbase + R_HL + off, sl);
            }
        }
        CP_COMMIT();
        CP_WAIT0();
        __syncthreads();

        float c0[4] = {0.f, 0.f, 0.f, 0.f};
        float c1[4] = {0.f, 0.f, 0.f, 0.f};
        const bool wactive = (m0w < nbr);

        if (wactive) {
            for (int ch = 0; ch < 8; ch++) {
                const uint32_t ahB = sbase + R_HH + ch * 8192 + aOff;
                const uint32_t alB = sbase + R_HL + ch * 8192 + aOff;
                const uint32_t bhB = sbase + R_WHH + ch * 4096 + bOff;
                const uint32_t blB = bhB + 32768;
#pragma unroll
                for (int ks = 0; ks < 4; ks++) {
                    const uint32_t kA = ks * 32 + a_klane;
                    const uint32_t kB = ks * 32 + b_klane;
                    uint32_t ah[4], al[4], bhh[4], bll[4];
                    ldsm4(ah,  ahB ^ kA);
                    ldsm4(al,  alB ^ kA);
                    ldsm4(bhh, bhB ^ kB);
                    ldsm4(bll, blB ^ kB);
                    mma16816(c0, ah, bhh);
                    mma16816(c0, ah, bll);
                    mma16816(c0, al, bhh);
                    mma16816(c1, ah, bhh + 2);
                    mma16816(c1, ah, bll + 2);
                    mma16816(c1, al, bhh + 2);
                }
            }
            // write fragments to gs[col(r)][row(b)] (no sync needed before:
            // gs last read before the previous step's barrier)
            const int row0 = m0w + (lane >> 2);
            const int col0 = n0w + (lane & 3) * 2;
            gs[(col0)     * 68 + row0]     = c0[0];
            gs[(col0 + 1) * 68 + row0]     = c0[1];
            gs[(col0)     * 68 + row0 + 8] = c0[2];
            gs[(col0 + 1) * 68 + row0 + 8] = c0[3];
            gs[(col0 + 8) * 68 + row0]     = c1[0];
            gs[(col0 + 9) * 68 + row0]     = c1[1];
            gs[(col0 + 8) * 68 + row0 + 8] = c1[2];
            gs[(col0 + 9) * 68 + row0 + 8] = c1[3];
        }
        __syncthreads();

        // output phase: active rows only (b < nb => mask is always true)
        for (int o = tid; o < nb * 8; o += 256) {
            int nl = o & 7;
            int b  = o >> 3;
            int n  = n0 + nl;
            const float* xr = xg_s + b * 40;
            float gi = gs[(0 * 8 + nl) * 68 + b] + xr[0 * 8 + nl];
            float gf = gs[(1 * 8 + nl) * 68 + b] + xr[1 * 8 + nl];
            float gg = gs[(2 * 8 + nl) * 68 + b] + xr[2 * 8 + nl];
            float go = gs[(3 * 8 + nl) * 68 + b] + xr[3 * 8 + nl];
            float iv = 1.f / (1.f + expf(-gi));
            float fv = 1.f / (1.f + expf(-gf));
            float gv = tanhf(gg);
            float ov = 1.f / (1.f + expf(-go));
            float cn = fv * cs[o] + iv * gv;
            float hn = ov * tanhf(cn);
            cs[o] = cn;
            __nv_bfloat16 hhi = __float2bfloat16(hn);
            hho[b * Hz + n] = hhi;
            hlo[b * Hz + n] = __float2bfloat16(hn - __bfloat162float(hhi));
            if (wsplit) {
                size_t yo = ((size_t)t * Bz + b) * 1024 + (size_t)dir * Hz + n;
                __nv_bfloat16 yh = __float2bfloat16(hn);
                g_Ah[yo] = yh;
                g_Al[yo] = __float2bfloat16(hn - __bfloat162float(yh));
            } else {
                Y[((size_t)b * Tz + t) * (2 * Hz) + (size_t)dir * Hz + n] = hn;
            }
            // final state: last active step (fwd: t==len-1, bwd: t==0)
            if (t == (dir ? 0 : (ls[b] - 1))) {
                g_hf[dir * Bz * Hz + b * Hz + n] = hn;
                g_c [dir * Bz * Hz + b * Hz + n] = cn;
            }
        }

        if (s < Tz - 1) grid_barrier_dir(dir, (unsigned)(s + 1) * 64);
    }

    // self-resetting exit
    __threadfence();
    __syncthreads();
    if (tid == 0) {
        unsigned d = atomicAdd(&g_done, 1u);
        if (d == NCTA - 1) {
            atomicExch(&g_bar2[0], 0u);
            atomicExch(&g_bar2[32], 0u);
            atomicExch(&g_done, 0u);
            __threadfence();
        }
    }
}

// copy final states into d_out hN/cN sections
__global__ void copy_states(float* __restrict__ out_h, float* __restrict__ out_c)
{
    int i = blockIdx.x * blockDim.x + threadIdx.x;
    if (i < 2 * Bz * Hz) {
        out_h[i] = g_hf[i];
        out_c[i] = g_c[i];
    }
}

extern "C" void kernel_launch(void* const* d_in, const int* in_sizes, int n_in,
                              void* d_out, int out_size)
{
    const float* x      = (const float*)d_in[0];
    const int*  lengths = (const int*)  d_in[1];
    const float* Wi_f0 = (const float*)d_in[2];
    const float* Wh_f0 = (const float*)d_in[3];
    const float* b_f0  = (const float*)d_in[4];
    const float* Wi_b0 = (const float*)d_in[5];
    const float* Wh_b0 = (const float*)d_in[6];
    const float* b_b0  = (const float*)d_in[7];
    const float* Wi_f1 = (const float*)d_in[8];
    const float* Wh_f1 = (const float*)d_in[9];
    const float* b_f1  = (const float*)d_in[10];
    const float* Wi_b1 = (const float*)d_in[11];
    const float* Wh_b1 = (const float*)d_in[12];
    const float* b_b1  = (const float*)d_in[13];
    float* out = (float*)d_out;

    cudaFuncSetAttribute(lstm_layer_tc,
                         cudaFuncAttributeMaxDynamicSharedMemorySize, R_SMEM);
    cudaFuncSetAttribute(gemm_mma,
                         cudaFuncAttributeMaxDynamicSharedMemorySize, GM_SMEM);

    __nv_bfloat16 *ahp, *alp, *hhp, *hlp;
    cudaGetSymbolAddress((void**)&ahp,  g_Ah);
    cudaGetSymbolAddress((void**)&alp,  g_Al);
    cudaGetSymbolAddress((void**)&hhp,  g_hh);
    cudaGetSymbolAddress((void**)&hlp,  g_hl);

    const dim3 gemm_grid(NG / 256, Mz / 128);
    const int  copy_blocks = (2 * Bz * Hz + 255) / 256;
    const size_t hbbytes = sizeof(__nv_bfloat16) * 2 * 2 * Bz * Hz;

    // masked Y elements are never written by the recurrence: pre-zero them
    cudaMemsetAsync(out, 0, XOUT * sizeof(float));

    // ---- layer 0 (K = 512) ----
    cudaMemsetAsync(hhp, 0, hbbytes);
    cudaMemsetAsync(hlp, 0, hbbytes);
    split_x<<<dim3(Mz, 1), 128>>>(x, Dz, ahp, alp);
    split_w<<<dim3(NG, 1), 128>>>(Wi_f0, Wi_b0, Dz);
    gemm_mma<<<gemm_grid, 512, GM_SMEM>>>(Dz, b_f0, b_b0);
    // zero layer-1 A operand (masked y rows must read as 0)
    cudaMemsetAsync(ahp, 0, (size_t)Mz * 1024 * sizeof(__nv_bfloat16));
    cudaMemsetAsync(alp, 0, (size_t)Mz * 1024 * sizeof(__nv_bfloat16));
    lstm_layer_tc<<<NCTA, 256, R_SMEM>>>(Wh_f0, Wh_b0, lengths, out, 1);
    copy_states<<<copy_blocks, 256>>>(out + XOUT,
                                      out + XOUT + 4 * Bz * Hz);

    // ---- layer 1 (K = 1024; A operand written by layer-0 recurrence) ----
    cudaMemsetAsync(hhp, 0, hbbytes);
    cudaMemsetAsync(hlp, 0, hbbytes);
    split_w<<<dim3(NG, 2), 128>>>(Wi_f1, Wi_b1, 2 * Hz);
    gemm_mma<<<gemm_grid, 512, GM_SMEM>>>(2 * Hz, b_f1, b_b1);
    lstm_layer_tc<<<NCTA, 256, R_SMEM>>>(Wh_f1, Wh_b1, lengths, out, 0);
    copy_states<<<copy_blocks, 256>>>(out + XOUT + 2 * Bz * Hz,
                                      out + XOUT + 4 * Bz * Hz + 2 * Bz * Hz);
}

// round 16
// speedup vs baseline: 4.1456x; 1.0152x over previous
#include <cuda_runtime.h>
#include <cuda_bf16.h>
#include <math.h>
#include <stdint.h>

// Problem constants
#define Bz 64
#define Tz 512
#define Dz 512
#define Hz 512
#define G4 (4*Hz)        // 2048 gates per direction
#define NG (2*G4)        // 4096 gates both directions (fused GEMM N)
#define Mz (Bz*Tz)       // 32768 GEMM rows
#define NCTA 128         // persistent recurrence CTAs
#define XOUT ((size_t)Bz*Tz*2*Hz)

// Scratch (static device globals — no allocation)
__device__ float g_xg[(size_t)Tz*Bz*NG];       // [t*B+b][dir*2048 + gate*512 + n]
__device__ float g_hf[2*Bz*Hz];                // final h per layer ([dir][b][n])
__device__ float g_c[2*Bz*Hz];                 // final c per layer
__device__ unsigned g_bar2[64];                // per-dir barrier counters ([0],[32])
__device__ unsigned g_done;
// bf16 hi/lo split operands for tensor-core GEMM (K-major rows)
__device__ __align__(16) __nv_bfloat16 g_Ah[(size_t)Mz*1024];
__device__ __align__(16) __nv_bfloat16 g_Al[(size_t)Mz*1024];
__device__ __align__(16) __nv_bfloat16 g_Bh[(size_t)NG*1024];
__device__ __align__(16) __nv_bfloat16 g_Bl[(size_t)NG*1024];
// bf16 hi/lo ping-pong h for the tensor-core recurrence
__device__ __align__(16) __nv_bfloat16 g_hh[2][2*Bz*Hz];
__device__ __align__(16) __nv_bfloat16 g_hl[2][2*Bz*Hz];

// ===========================================================================
// PTX helpers — only baseline (non-'a') features: mma.sync, ldmatrix, cp.async
// ===========================================================================
__device__ __forceinline__ uint32_t smem_u32(const void* p) {
    uint32_t a;
    asm("{ .reg .u64 t; cvta.to.shared.u64 t, %1; cvt.u32.u64 %0, t; }"
        : "=r"(a) : "l"(p));
    return a;
}
__device__ __forceinline__ void ldsm4(uint32_t* r, uint32_t addr) {
    asm volatile("ldmatrix.sync.aligned.m8n8.x4.shared.b16 {%0,%1,%2,%3}, [%4];"
                 : "=r"(r[0]), "=r"(r[1]), "=r"(r[2]), "=r"(r[3]) : "r"(addr));
}
__device__ __forceinline__ void mma16816(float* c, const uint32_t* a, const uint32_t* b) {
    asm volatile("mma.sync.aligned.m16n8k16.row.col.f32.bf16.bf16.f32 "
                 "{%0,%1,%2,%3}, {%4,%5,%6,%7}, {%8,%9}, {%0,%1,%2,%3};"
                 : "+f"(c[0]), "+f"(c[1]), "+f"(c[2]), "+f"(c[3])
                 : "r"(a[0]), "r"(a[1]), "r"(a[2]), "r"(a[3]),
                   "r"(b[0]), "r"(b[1]));
}
#define CP_ASYNC16(dst, src) \
    asm volatile("cp.async.cg.shared.global [%0], [%1], 16;" :: "r"(dst), "l"(src))
#define CP_COMMIT() asm volatile("cp.async.commit_group;" ::: "memory")
#define CP_WAIT1()  asm volatile("cp.async.wait_group 1;" ::: "memory")
#define CP_WAIT0()  asm volatile("cp.async.wait_group 0;" ::: "memory")

// ===========================================================================
// Conversion: fp32 -> bf16 hi + bf16 lo, with [b][t] -> m=t*B+b transpose.
// ===========================================================================
__global__ void __launch_bounds__(128)
split_x(const float* __restrict__ src, int K,
        __nv_bfloat16* __restrict__ dh, __nv_bfloat16* __restrict__ dl)
{
    const int m = blockIdx.x;
    const int k = blockIdx.y * 512 + threadIdx.x * 4;
    const int srow = (m & 63) * Tz + (m >> 6);
    float4 v = *(const float4*)(src + (size_t)srow * K + k);
    __nv_bfloat16 h0 = __float2bfloat16(v.x);
    __nv_bfloat16 h1 = __float2bfloat16(v.y);
    __nv_bfloat16 h2 = __float2bfloat16(v.z);
    __nv_bfloat16 h3 = __float2bfloat16(v.w);
    __nv_bfloat16 l0 = __float2bfloat16(v.x - __bfloat162float(h0));
    __nv_bfloat16 l1 = __float2bfloat16(v.y - __bfloat162float(h1));
    __nv_bfloat16 l2 = __float2bfloat16(v.z - __bfloat162float(h2));
    __nv_bfloat16 l3 = __float2bfloat16(v.w - __bfloat162float(h3));
    size_t o = (size_t)m * K + k;
    *(__nv_bfloat162*)(dh + o)     = __halves2bfloat162(h0, h1);
    *(__nv_bfloat162*)(dh + o + 2) = __halves2bfloat162(h2, h3);
    *(__nv_bfloat162*)(dl + o)     = __halves2bfloat162(l0, l1);
    *(__nv_bfloat162*)(dl + o + 2) = __halves2bfloat162(l2, l3);
}

__global__ void __launch_bounds__(128)
split_w(const float* __restrict__ Wf, const float* __restrict__ Wb, int K)
{
    const int n = blockIdx.x;
    const int k = blockIdx.y * 512 + threadIdx.x * 4;
    const float* src = (n < G4) ? (Wf + (size_t)n * K) : (Wb + (size_t)(n - G4) * K);
    float4 v = *(const float4*)(src + k);
    __nv_bfloat16 h0 = __float2bfloat16(v.x);
    __nv_bfloat16 h1 = __float2bfloat16(v.y);
    __nv_bfloat16 h2 = __float2bfloat16(v.z);
    __nv_bfloat16 h3 = __float2bfloat16(v.w);
    __nv_bfloat16 l0 = __float2bfloat16(v.x - __bfloat162float(h0));
    __nv_bfloat16 l1 = __float2bfloat16(v.y - __bfloat162float(h1));
    __nv_bfloat16 l2 = __float2bfloat16(v.z - __bfloat162float(h2));
    __nv_bfloat16 l3 = __float2bfloat16(v.w - __bfloat162float(h3));
    size_t o = (size_t)n * K + k;
    *(__nv_bfloat162*)(g_Bh + o)     = __halves2bfloat162(h0, h1);
    *(__nv_bfloat162*)(g_Bh + o + 2) = __halves2bfloat162(h2, h3);
    *(__nv_bfloat162*)(g_Bl + o)     = __halves2bfloat162(l0, l1);
    *(__nv_bfloat162*)(g_Bl + o + 2) = __halves2bfloat162(l2, l3);
}

// ===========================================================================
// bf16 mma.sync GEMM with 3-term compensation (unchanged from R13/R15 PASS).
// CTA tile 128(m) x 256(n), 512 threads (16 warps as 2m x 8n, warp tile 64x32).
// ===========================================================================
#define GM_AH   0
#define GM_AL   16384
#define GM_BH   32768
#define GM_BL   65536
#define GM_STAGE 98304
#define GM_BIAS (2*GM_STAGE)          // 196608
#define GM_SMEM (GM_BIAS + 1024)      // 197632 bytes

__global__ void __launch_bounds__(512, 1)
gemm_mma(int K, const float* __restrict__ bfp, const float* __restrict__ bbp)
{
    extern __shared__ char smem[];
    const uint32_t sbase = smem_u32(smem);
    const int tid  = threadIdx.x;
    const int wid  = tid >> 5;
    const int lane = tid & 31;
    const int n0 = blockIdx.x * 256;
    const int m0 = blockIdx.y * 128;
    const int nchunks = K / 64;

    float* bias_s = (float*)(smem + GM_BIAS);
    if (tid < 256) {
        int n = n0 + tid;
        bias_s[tid] = (n < G4) ? bfp[n] : bbp[n - G4];
    }

    const char* srcAh = (const char*)(g_Ah + (size_t)m0 * K);
    const char* srcAl = (const char*)(g_Al + (size_t)m0 * K);
    const char* srcBh = (const char*)(g_Bh + (size_t)n0 * K);
    const char* srcBl = (const char*)(g_Bl + (size_t)n0 * K);

    auto load_chunk = [&](int c, int st) {
        const uint32_t base = sbase + st * GM_STAGE;
        const size_t koff = (size_t)c * 128;
#pragma unroll
        for (int i = 0; i < 2; i++) {
            int idx = tid + i * 512;
            int row = idx >> 3;
            int g   = idx & 7;
            uint32_t off = row * 128 + ((g * 16) ^ ((row & 7) << 4));
            const size_t so = (size_t)row * K * 2 + koff + g * 16;
            CP_ASYNC16(base + GM_AH + off, srcAh + so);
            CP_ASYNC16(base + GM_AL + off, srcAl + so);
        }
#pragma unroll
        for (int i = 0; i < 4; i++) {
            int idx = tid + i * 512;
            int row = idx >> 3;
            int g   = idx & 7;
            uint32_t off = row * 128 + ((g * 16) ^ ((row & 7) << 4));
            const size_t so = (size_t)row * K * 2 + koff + g * 16;
            CP_ASYNC16(base + GM_BH + off, srcBh + so);
            CP_ASYNC16(base + GM_BL + off, srcBl + so);
        }
    };

    const int m0w = (wid & 1) * 64;
    const int n0w = (wid >> 1) * 32;

    uint32_t aBase[4];
    const int a_row_l = (lane & 15);
    const uint32_t a_klane = (lane >> 4) * 16;
#pragma unroll
    for (int mi = 0; mi < 4; mi++) {
        int row = m0w + mi * 16 + a_row_l;
        aBase[mi] = row * 128 + ((row & 7) << 4);
    }
    uint32_t bBase[2];
    const int b_row_l = ((lane >> 4) * 8) + (lane & 7);
    const uint32_t b_klane = ((lane >> 3) & 1) * 16;
#pragma unroll
    for (int nj = 0; nj < 2; nj++) {
        int row = n0w + nj * 16 + b_row_l;
        bBase[nj] = row * 128 + ((row & 7) << 4);
    }

    float c[4][4][4];
#pragma unroll
    for (int mi = 0; mi < 4; mi++)
#pragma unroll
        for (int ni = 0; ni < 4; ni++)
#pragma unroll
            for (int q = 0; q < 4; q++) c[mi][ni][q] = 0.f;

    load_chunk(0, 0); CP_COMMIT();
    if (nchunks > 1) { load_chunk(1, 1); CP_COMMIT(); }

    for (int ch = 0; ch < nchunks; ch++) {
        if (ch == nchunks - 1) CP_WAIT0(); else CP_WAIT1();
        __syncthreads();

        const uint32_t stb = sbase + (ch & 1) * GM_STAGE;
        const uint32_t bufA_h = stb + GM_AH;
        const uint32_t bufA_l = stb + GM_AL;
        const uint32_t bufB_h = stb + GM_BH;
        const uint32_t bufB_l = stb + GM_BL;

#pragma unroll
        for (int ks = 0; ks < 4; ks++) {
            const uint32_t kbA = ks * 32 + a_klane;
            const uint32_t kbB = ks * 32 + b_klane;
            uint32_t ah[4][4], al[4][4], bh[4][2], bl[4][2];
#pragma unroll
            for (int mi = 0; mi < 4; mi++) {
                ldsm4(ah[mi], (bufA_h + aBase[mi]) ^ kbA);
                ldsm4(al[mi], (bufA_l + aBase[mi]) ^ kbA);
            }
#pragma unroll
            for (int nj = 0; nj < 2; nj++) {
                uint32_t r[4];
                ldsm4(r, (bufB_h + bBase[nj]) ^ kbB);
                bh[nj * 2][0] = r[0]; bh[nj * 2][1] = r[1];
                bh[nj * 2 + 1][0] = r[2]; bh[nj * 2 + 1][1] = r[3];
                ldsm4(r, (bufB_l + bBase[nj]) ^ kbB);
                bl[nj * 2][0] = r[0]; bl[nj * 2][1] = r[1];
                bl[nj * 2 + 1][0] = r[2]; bl[nj * 2 + 1][1] = r[3];
            }
#pragma unroll
            for (int mi = 0; mi < 4; mi++)
#pragma unroll
                for (int ni = 0; ni < 4; ni++) {
                    mma16816(c[mi][ni], ah[mi], bh[ni]);
                    mma16816(c[mi][ni], ah[mi], bl[ni]);
                    mma16816(c[mi][ni], al[mi], bh[ni]);
                }
        }
        __syncthreads();
        if (ch + 2 < nchunks) { load_chunk(ch + 2, ch & 1); CP_COMMIT(); }
    }

    const int er = lane >> 2;
    const int ec = (lane & 3) * 2;
#pragma unroll
    for (int mi = 0; mi < 4; mi++) {
        int row0 = m0 + m0w + mi * 16 + er;
#pragma unroll
        for (int ni = 0; ni < 4; ni++) {
            int nloc = n0w + ni * 8 + ec;
            int coln = n0 + nloc;
            float b0 = bias_s[nloc], b1 = bias_s[nloc + 1];
            float* p0 = g_xg + (size_t)row0 * NG + coln;
            float* p1 = g_xg + (size_t)(row0 + 8) * NG + coln;
            *(float2*)p0 = make_float2(c[mi][ni][0] + b0, c[mi][ni][1] + b1);
            *(float2*)p1 = make_float2(c[mi][ni][2] + b0, c[mi][ni][3] + b1);
        }
    }
}

// ===========================================================================
// Tensor-core persistent recurrence, two-phase intra-step pipeline:
// group 1 = xg + h chunks 0-3; group 2 = h chunks 4-7. MMA burst on chunks
// 0-3 overlaps group 2's transfer. Chunk order ascending => bit-identical.
// Active-prefix masking as in R12-R15.
// ===========================================================================
#define R_WHH 0                    // 32KB  Wh hi (8 chunk-tiles x 4KB)
#define R_WHL 32768                // 32KB  Wh lo
#define R_HH  65536                // 64KB  h hi (8 chunk-tiles x 8KB)
#define R_HL  131072               // 64KB  h lo
#define R_GS  196608               // float gs[32][68] = 8704B
#define R_CS  205312               // 512 floats
#define R_LS  207360               // 64 ints
#define R_XG  207616               // float xg_s[64][40] = 10240B
#define R_NB  217856               // int nbArr[512] = 2048B
#define R_SMEM 219904

__device__ __forceinline__ void grid_barrier_dir(int dir, unsigned target)
{
    __syncthreads();
    if (threadIdx.x == 0) {
        unsigned* ctr = &g_bar2[dir * 32];
        __threadfence();
        atomicAdd(ctr, 1u);
        for (;;) {
            unsigned v;
            asm volatile("ld.acquire.gpu.global.u32 %0, [%1];"
                         : "=r"(v) : "l"(ctr));
            if (v >= target) break;
            __nanosleep(32);
        }
    }
    __syncthreads();
}

__global__ void __launch_bounds__(256, 1)
lstm_layer_tc(const float* __restrict__ Whf, const float* __restrict__ Whb,
              const int* __restrict__ lengths, float* __restrict__ Y,
              int wsplit)
{
    extern __shared__ char smem[];
    const uint32_t sbase = smem_u32(smem);
    float* gs    = (float*)(smem + R_GS);
    float* cs    = (float*)(smem + R_CS);
    int*   ls    = (int*)(smem + R_LS);
    float* xg_s  = (float*)(smem + R_XG);
    int*   nbArr = (int*)(smem + R_NB);

    const int bid = blockIdx.x;
    const int dir = bid >> 6;
    const int n0  = (bid & 63) * 8;
    const float* Wh = dir ? Whb : Whf;

    const int tid  = threadIdx.x;
    const int wid  = tid >> 5;
    const int lane = tid & 31;

    // ---- one-time: Wh slice -> smem, split hi/lo, SW128-swizzled ----
    for (int idx = tid; idx < 8192; idx += 256) {
        int r  = idx >> 8;
        int kp = idx & 255;
        int j  = (r >> 3) * Hz + n0 + (r & 7);
        float2 v = *(const float2*)(Wh + (size_t)j * Hz + kp * 2);
        __nv_bfloat16 h0 = __float2bfloat16(v.x);
        __nv_bfloat16 h1 = __float2bfloat16(v.y);
        __nv_bfloat16 l0 = __float2bfloat16(v.x - __bfloat162float(h0));
        __nv_bfloat16 l1 = __float2bfloat16(v.y - __bfloat162float(h1));
        int c  = kp >> 5;
        int kb = (kp & 31) * 4;
        uint32_t off = c * 4096 + r * 128 + ((uint32_t)kb ^ (((uint32_t)r & 7) << 4));
        *(__nv_bfloat162*)(smem + R_WHH + off) = __halves2bfloat162(h0, h1);
        *(__nv_bfloat162*)(smem + R_WHL + off) = __halves2bfloat162(l0, l1);
    }
    for (int i = tid; i < 512; i += 256) cs[i] = 0.f;
    if (tid < 64) ls[tid] = lengths[tid];
    __syncthreads();
    // active-prefix table: nbArr[t] = #{b : len[b] > t}
    for (int t = tid; t < 512; t += 256) {
        int cnt = 0;
#pragma unroll 16
        for (int b = 0; b < 64; b++) cnt += (ls[b] > t) ? 1 : 0;
        nbArr[t] = cnt;
    }
    __syncthreads();

    // warp tiling: 4m x 2n; warp tile m16 x n16
    const int m0w = (wid & 3) * 16;
    const int n0w = (wid >> 2) * 16;
    const int a_row = m0w + (lane & 15);
    const uint32_t a_klane = (lane >> 4) * 16;
    const int b_row = n0w + ((lane >> 4) * 8) + (lane & 7);
    const uint32_t b_klane = ((lane >> 3) & 1) * 16;
    const uint32_t aOff = a_row * 128 + (((uint32_t)a_row & 7) << 4);
    const uint32_t bOff = b_row * 128 + (((uint32_t)b_row & 7) << 4);

    for (int s = 0; s < Tz; s++) {
        const int t   = dir ? (Tz - 1 - s) : s;
        const int par = s & 1;
        const int nb  = nbArr[t];
        const int nbr = (nb + 15) & ~15;
        const __nv_bfloat16* hh = g_hh[par] + dir * Bz * Hz;
        const __nv_bfloat16* hl = g_hl[par] + dir * Bz * Hz;
        __nv_bfloat16* hho = g_hh[par ^ 1] + dir * Bz * Hz;
        __nv_bfloat16* hlo = g_hl[par ^ 1] + dir * Bz * Hz;

        // group 1: xg slab (active rows) + h chunks 0-3 (hi+lo)
        {
            const float* xg0 = g_xg + ((size_t)t * Bz) * NG + (size_t)dir * G4 + n0;
#pragma unroll
            for (int i = 0; i < 2; i++) {
                int e = tid + i * 256;
                int b = e >> 3;
                if (b < nb) {
                    int g  = (e >> 1) & 3;
                    int hf = e & 1;
                    uint32_t dst = sbase + R_XG + (b * 40 + g * 8 + hf * 4) * 4;
                    CP_ASYNC16(dst, xg0 + (size_t)b * NG + g * Hz + hf * 4);
                }
            }
            for (int idx = tid; idx < nbr * 32; idx += 256) {
                int b = idx >> 5;
                int q = idx & 31;
                int c = q >> 3;           // 0..3
                int g = q & 7;
                uint32_t off = c * 8192 + b * 128 + (((uint32_t)g * 16) ^ (((uint32_t)b & 7) << 4));
                CP_ASYNC16(sbase + R_HH + off,
                           (const char*)(hh + (size_t)b * Hz + c * 64) + g * 16);
                CP_ASYNC16(sbase + R_HL + off,
                           (const char*)(hl + (size_t)b * Hz + c * 64) + g * 16);
            }
        }
        CP_COMMIT();
        // group 2: h chunks 4-7 (hi+lo)
        for (int idx = tid; idx < nbr * 32; idx += 256) {
            int b = idx >> 5;
            int q = idx & 31;
            int c = (q >> 3) + 4;         // 4..7
            int g = q & 7;
            uint32_t off = c * 8192 + b * 128 + (((uint32_t)g * 16) ^ (((uint32_t)b & 7) << 4));
            CP_ASYNC16(sbase + R_HH + off,
                       (const char*)(hh + (size_t)b * Hz + c * 64) + g * 16);
            CP_ASYNC16(sbase + R_HL + off,
                       (const char*)(hl + (size_t)b * Hz + c * 64) + g * 16);
        }
        CP_COMMIT();

        float c0[4] = {0.f, 0.f, 0.f, 0.f};
        float c1[4] = {0.f, 0.f, 0.f, 0.f};
        const bool wactive = (m0w < nbr);

        CP_WAIT1();
        __syncthreads();
        if (wactive) {
            for (int ch = 0; ch < 4; ch++) {
                const uint32_t ahB = sbase + R_HH + ch * 8192 + aOff;
                const uint32_t alB = sbase + R_HL + ch * 8192 + aOff;
                const uint32_t bhB = sbase + R_WHH + ch * 4096 + bOff;
                const uint32_t blB = bhB + 32768;
#pragma unroll
                for (int ks = 0; ks < 4; ks++) {
                    const uint32_t kA = ks * 32 + a_klane;
                    const uint32_t kB = ks * 32 + b_klane;
                    uint32_t ah[4], al[4], bhh[4], bll[4];
                    ldsm4(ah,  ahB ^ kA);
                    ldsm4(al,  alB ^ kA);
                    ldsm4(bhh, bhB ^ kB);
                    ldsm4(bll, blB ^ kB);
                    mma16816(c0, ah, bhh);
                    mma16816(c0, ah, bll);
                    mma16816(c0, al, bhh);
                    mma16816(c1, ah, bhh + 2);
                    mma16816(c1, ah, bll + 2);
                    mma16816(c1, al, bhh + 2);
                }
            }
        }
        CP_WAIT0();
        __syncthreads();
        if (wactive) {
            for (int ch = 4; ch < 8; ch++) {
                const uint32_t ahB = sbase + R_HH + ch * 8192 + aOff;
                const uint32_t alB = sbase + R_HL + ch * 8192 + aOff;
                const uint32_t bhB = sbase + R_WHH + ch * 4096 + bOff;
                const uint32_t blB = bhB + 32768;
#pragma unroll
                for (int ks = 0; ks < 4; ks++) {
                    const uint32_t kA = ks * 32 + a_klane;
                    const uint32_t kB = ks * 32 + b_klane;
                    uint32_t ah[4], al[4], bhh[4], bll[4];
                    ldsm4(ah,  ahB ^ kA);
                    ldsm4(al,  alB ^ kA);
                    ldsm4(bhh, bhB ^ kB);
                    ldsm4(bll, blB ^ kB);
                    mma16816(c0, ah, bhh);
                    mma16816(c0, ah, bll);
                    mma16816(c0, al, bhh);
                    mma16816(c1, ah, bhh + 2);
                    mma16816(c1, ah, bll + 2);
                    mma16816(c1, al, bhh + 2);
                }
            }
            // write fragments to gs[col(r)][row(b)]
            const int row0 = m0w + (lane >> 2);
            const int col0 = n0w + (lane & 3) * 2;
            gs[(col0)     * 68 + row0]     = c0[0];
            gs[(col0 + 1) * 68 + row0]     = c0[1];
            gs[(col0)     * 68 + row0 + 8] = c0[2];
            gs[(col0 + 1) * 68 + row0 + 8] = c0[3];
            gs[(col0 + 8) * 68 + row0]     = c1[0];
            gs[(col0 + 9) * 68 + row0]     = c1[1];
            gs[(col0 + 8) * 68 + row0 + 8] = c1[2];
            gs[(col0 + 9) * 68 + row0 + 8] = c1[3];
        }
        __syncthreads();

        // output phase: active rows only (b < nb => mask is always true)
        for (int o = tid; o < nb * 8; o += 256) {
            int nl = o & 7;
            int b  = o >> 3;
            int n  = n0 + nl;
            const float* xr = xg_s + b * 40;
            float gi = gs[(0 * 8 + nl) * 68 + b] + xr[0 * 8 + nl];
            float gf = gs[(1 * 8 + nl) * 68 + b] + xr[1 * 8 + nl];
            float gg = gs[(2 * 8 + nl) * 68 + b] + xr[2 * 8 + nl];
            float go = gs[(3 * 8 + nl) * 68 + b] + xr[3 * 8 + nl];
            float iv = 1.f / (1.f + expf(-gi));
            float fv = 1.f / (1.f + expf(-gf));
            float gv = tanhf(gg);
            float ov = 1.f / (1.f + expf(-go));
            float cn = fv * cs[o] + iv * gv;
            float hn = ov * tanhf(cn);
            cs[o] = cn;
            __nv_bfloat16 hhi = __float2bfloat16(hn);
            hho[b * Hz + n] = hhi;
            hlo[b * Hz + n] = __float2bfloat16(hn - __bfloat162float(hhi));
            if (wsplit) {
                size_t yo = ((size_t)t * Bz + b) * 1024 + (size_t)dir * Hz + n;
                __nv_bfloat16 yh = __float2bfloat16(hn);
                g_Ah[yo] = yh;
                g_Al[yo] = __float2bfloat16(hn - __bfloat162float(yh));
            } else {
                Y[((size_t)b * Tz + t) * (2 * Hz) + (size_t)dir * Hz + n] = hn;
            }
            // final state: last active step (fwd: t==len-1, bwd: t==0)
            if (t == (dir ? 0 : (ls[b] - 1))) {
                g_hf[dir * Bz * Hz + b * Hz + n] = hn;
                g_c [dir * Bz * Hz + b * Hz + n] = cn;
            }
        }

        if (s < Tz - 1) grid_barrier_dir(dir, (unsigned)(s + 1) * 64);
    }

    // self-resetting exit
    __threadfence();
    __syncthreads();
    if (tid == 0) {
        unsigned d = atomicAdd(&g_done, 1u);
        if (d == NCTA - 1) {
            atomicExch(&g_bar2[0], 0u);
            atomicExch(&g_bar2[32], 0u);
            atomicExch(&g_done, 0u);
            __threadfence();
        }
    }
}

// copy final states into d_out hN/cN sections
__global__ void copy_states(float* __restrict__ out_h, float* __restrict__ out_c)
{
    int i = blockIdx.x * blockDim.x + threadIdx.x;
    if (i < 2 * Bz * Hz) {
        out_h[i] = g_hf[i];
        out_c[i] = g_c[i];
    }
}

extern "C" void kernel_launch(void* const* d_in, const int* in_sizes, int n_in,
                              void* d_out, int out_size)
{
    const float* x      = (const float*)d_in[0];
    const int*  lengths = (const int*)  d_in[1];
    const float* Wi_f0 = (const float*)d_in[2];
    const float* Wh_f0 = (const float*)d_in[3];
    const float* b_f0  = (const float*)d_in[4];
    const float* Wi_b0 = (const float*)d_in[5];
    const float* Wh_b0 = (const float*)d_in[6];
    const float* b_b0  = (const float*)d_in[7];
    const float* Wi_f1 = (const float*)d_in[8];
    const float* Wh_f1 = (const float*)d_in[9];
    const float* b_f1  = (const float*)d_in[10];
    const float* Wi_b1 = (const float*)d_in[11];
    const float* Wh_b1 = (const float*)d_in[12];
    const float* b_b1  = (const float*)d_in[13];
    float* out = (float*)d_out;

    cudaFuncSetAttribute(lstm_layer_tc,
                         cudaFuncAttributeMaxDynamicSharedMemorySize, R_SMEM);
    cudaFuncSetAttribute(gemm_mma,
                         cudaFuncAttributeMaxDynamicSharedMemorySize, GM_SMEM);

    __nv_bfloat16 *ahp, *alp, *hhp, *hlp;
    cudaGetSymbolAddress((void**)&ahp,  g_Ah);
    cudaGetSymbolAddress((void**)&alp,  g_Al);
    cudaGetSymbolAddress((void**)&hhp,  g_hh);
    cudaGetSymbolAddress((void**)&hlp,  g_hl);

    const dim3 gemm_grid(NG / 256, Mz / 128);
    const int  copy_blocks = (2 * Bz * Hz + 255) / 256;
    const size_t hbbytes = sizeof(__nv_bfloat16) * 2 * 2 * Bz * Hz;

    // masked Y elements are never written by the recurrence: pre-zero them
    cudaMemsetAsync(out, 0, XOUT * sizeof(float));

    // ---- layer 0 (K = 512) ----
    cudaMemsetAsync(hhp, 0, hbbytes);
    cudaMemsetAsync(hlp, 0, hbbytes);
    split_x<<<dim3(Mz, 1), 128>>>(x, Dz, ahp, alp);
    split_w<<<dim3(NG, 1), 128>>>(Wi_f0, Wi_b0, Dz);
    gemm_mma<<<gemm_grid, 512, GM_SMEM>>>(Dz, b_f0, b_b0);
    // zero layer-1 A operand (masked y rows must read as 0)
    cudaMemsetAsync(ahp, 0, (size_t)Mz * 1024 * sizeof(__nv_bfloat16));
    cudaMemsetAsync(alp, 0, (size_t)Mz * 1024 * sizeof(__nv_bfloat16));
    lstm_layer_tc<<<NCTA, 256, R_SMEM>>>(Wh_f0, Wh_b0, lengths, out, 1);
    copy_states<<<copy_blocks, 256>>>(out + XOUT,
                                      out + XOUT + 4 * Bz * Hz);

    // ---- layer 1 (K = 1024; A operand written by layer-0 recurrence) ----
    cudaMemsetAsync(hhp, 0, hbbytes);
    cudaMemsetAsync(hlp, 0, hbbytes);
    split_w<<<dim3(NG, 2), 128>>>(Wi_f1, Wi_b1, 2 * Hz);
    gemm_mma<<<gemm_grid, 512, GM_SMEM>>>(2 * Hz, b_f1, b_b1);
    lstm_layer_tc<<<NCTA, 256, R_SMEM>>>(Wh_f1, Wh_b1, lengths, out, 0);
    copy_states<<<copy_blocks, 256>>>(out + XOUT + 2 * Bz * Hz,
                                      out + XOUT + 4 * Bz * Hz + 2 * Bz * Hz);
}

// round 17
// speedup vs baseline: 5.0946x; 1.2289x over previous
#include <cuda_runtime.h>
#include <cuda_bf16.h>
#include <math.h>
#include <stdint.h>

// Problem constants
#define Bz 64
#define Tz 512
#define Dz 512
#define Hz 512
#define G4 (4*Hz)        // 2048 gates per direction
#define NG (2*G4)        // 4096 gates both directions (fused GEMM N)
#define Mz (Bz*Tz)       // 32768 GEMM rows (upper bound; compacted M' <= Mz)
#define NCTA 128         // persistent recurrence CTAs
#define XOUT ((size_t)Bz*Tz*2*Hz)

// Scratch (static device globals — no allocation)
__device__ float g_xg[(size_t)Tz*Bz*NG];       // [compacted row][dir*2048 + gate*512 + n]
__device__ float g_hf[2*Bz*Hz];                // final h per layer ([dir][b][n])
__device__ float g_c[2*Bz*Hz];                 // final c per layer
__device__ unsigned g_bar2[64];                // per-dir barrier counters ([0],[32])
__device__ unsigned g_done;
// bf16 hi/lo split operands for tensor-core GEMM (K-major, COMPACTED rows)
__device__ __align__(16) __nv_bfloat16 g_Ah[(size_t)Mz*1024];
__device__ __align__(16) __nv_bfloat16 g_Al[(size_t)Mz*1024];
__device__ __align__(16) __nv_bfloat16 g_Bh[(size_t)NG*1024];
__device__ __align__(16) __nv_bfloat16 g_Bl[(size_t)NG*1024];
// bf16 hi/lo ping-pong h for the tensor-core recurrence
__device__ __align__(16) __nv_bfloat16 g_hh[2][2*Bz*Hz];
__device__ __align__(16) __nv_bfloat16 g_hl[2][2*Bz*Hz];

// ===========================================================================
// PTX helpers — only baseline (non-'a') features: mma.sync, ldmatrix, cp.async
// ===========================================================================
__device__ __forceinline__ uint32_t smem_u32(const void* p) {
    uint32_t a;
    asm("{ .reg .u64 t; cvta.to.shared.u64 t, %1; cvt.u32.u64 %0, t; }"
        : "=r"(a) : "l"(p));
    return a;
}
__device__ __forceinline__ void ldsm4(uint32_t* r, uint32_t addr) {
    asm volatile("ldmatrix.sync.aligned.m8n8.x4.shared.b16 {%0,%1,%2,%3}, [%4];"
                 : "=r"(r[0]), "=r"(r[1]), "=r"(r[2]), "=r"(r[3]) : "r"(addr));
}
__device__ __forceinline__ void mma16816(float* c, const uint32_t* a, const uint32_t* b) {
    asm volatile("mma.sync.aligned.m16n8k16.row.col.f32.bf16.bf16.f32 "
                 "{%0,%1,%2,%3}, {%4,%5,%6,%7}, {%8,%9}, {%0,%1,%2,%3};"
                 : "+f"(c[0]), "+f"(c[1]), "+f"(c[2]), "+f"(c[3])
                 : "r"(a[0]), "r"(a[1]), "r"(a[2]), "r"(a[3]),
                   "r"(b[0]), "r"(b[1]));
}
#define CP_ASYNC16(dst, src) \
    asm volatile("cp.async.cg.shared.global [%0], [%1], 16;" :: "r"(dst), "l"(src))
#define CP_COMMIT() asm volatile("cp.async.commit_group;" ::: "memory")
#define CP_WAIT1()  asm volatile("cp.async.wait_group 1;" ::: "memory")
#define CP_WAIT0()  asm volatile("cp.async.wait_group 0;" ::: "memory")

// ===========================================================================
// split_x: fp32 -> bf16 hi+lo, COMPACTED rows. Original row (b, t); active iff
// t < len[b]; compacted row = cum[b] + t (cum[b] = sum of len[b'<b]).
// ===========================================================================
__global__ void __launch_bounds__(128)
split_x(const float* __restrict__ src, int K, const int* __restrict__ lengths,
        __nv_bfloat16* __restrict__ dh, __nv_bfloat16* __restrict__ dl)
{
    const int m = blockIdx.x;
    const int b = m & 63;
    const int t = m >> 6;
    if (t >= lengths[b]) return;        // uniform over block
    int cum = 0;
    for (int bp = 0; bp < 64; bp++) cum += (bp < b) ? lengths[bp] : 0;
    const int row = cum + t;

    const int k = blockIdx.y * 512 + threadIdx.x * 4;
    float4 v = *(const float4*)(src + (size_t)b * Tz * K + (size_t)t * K + k);
    __nv_bfloat16 h0 = __float2bfloat16(v.x);
    __nv_bfloat16 h1 = __float2bfloat16(v.y);
    __nv_bfloat16 h2 = __float2bfloat16(v.z);
    __nv_bfloat16 h3 = __float2bfloat16(v.w);
    __nv_bfloat16 l0 = __float2bfloat16(v.x - __bfloat162float(h0));
    __nv_bfloat16 l1 = __float2bfloat16(v.y - __bfloat162float(h1));
    __nv_bfloat16 l2 = __float2bfloat16(v.z - __bfloat162float(h2));
    __nv_bfloat16 l3 = __float2bfloat16(v.w - __bfloat162float(h3));
    size_t o = (size_t)row * K + k;
    *(__nv_bfloat162*)(dh + o)     = __halves2bfloat162(h0, h1);
    *(__nv_bfloat162*)(dh + o + 2) = __halves2bfloat162(h2, h3);
    *(__nv_bfloat162*)(dl + o)     = __halves2bfloat162(l0, l1);
    *(__nv_bfloat162*)(dl + o + 2) = __halves2bfloat162(l2, l3);
}

__global__ void __launch_bounds__(128)
split_w(const float* __restrict__ Wf, const float* __restrict__ Wb, int K)
{
    const int n = blockIdx.x;
    const int k = blockIdx.y * 512 + threadIdx.x * 4;
    const float* src = (n < G4) ? (Wf + (size_t)n * K) : (Wb + (size_t)(n - G4) * K);
    float4 v = *(const float4*)(src + k);
    __nv_bfloat16 h0 = __float2bfloat16(v.x);
    __nv_bfloat16 h1 = __float2bfloat16(v.y);
    __nv_bfloat16 h2 = __float2bfloat16(v.z);
    __nv_bfloat16 h3 = __float2bfloat16(v.w);
    __nv_bfloat16 l0 = __float2bfloat16(v.x - __bfloat162float(h0));
    __nv_bfloat16 l1 = __float2bfloat16(v.y - __bfloat162float(h1));
    __nv_bfloat16 l2 = __float2bfloat16(v.z - __bfloat162float(h2));
    __nv_bfloat16 l3 = __float2bfloat16(v.w - __bfloat162float(h3));
    size_t o = (size_t)n * K + k;
    *(__nv_bfloat162*)(g_Bh + o)     = __halves2bfloat162(h0, h1);
    *(__nv_bfloat162*)(g_Bh + o + 2) = __halves2bfloat162(h2, h3);
    *(__nv_bfloat162*)(g_Bl + o)     = __halves2bfloat162(l0, l1);
    *(__nv_bfloat162*)(g_Bl + o + 2) = __halves2bfloat162(l2, l3);
}

// ===========================================================================
// bf16 mma.sync GEMM with 3-term compensation (structure = R13/R16 PASS)
// + compacted-M early exit: CTAs whose whole m-tile is >= M' return at birth.
// ===========================================================================
#define GM_AH   0
#define GM_AL   16384
#define GM_BH   32768
#define GM_BL   65536
#define GM_STAGE 98304
#define GM_BIAS (2*GM_STAGE)          // 196608
#define GM_SMEM (GM_BIAS + 1024)      // 197632 bytes

__global__ void __launch_bounds__(512, 1)
gemm_mma(int K, const float* __restrict__ bfp, const float* __restrict__ bbp,
         const int* __restrict__ lengths)
{
    extern __shared__ char smem[];
    const uint32_t sbase = smem_u32(smem);
    const int tid  = threadIdx.x;
    const int wid  = tid >> 5;
    const int lane = tid & 31;
    const int n0 = blockIdx.x * 256;
    const int m0 = blockIdx.y * 128;
    const int nchunks = K / 64;

    // compacted-M early exit (uniform)
    {
        int Msum = 0;
#pragma unroll 1
        for (int b = 0; b < 64; b++) Msum += lengths[b];
        if (m0 >= Msum) return;
    }

    float* bias_s = (float*)(smem + GM_BIAS);
    if (tid < 256) {
        int n = n0 + tid;
        bias_s[tid] = (n < G4) ? bfp[n] : bbp[n - G4];
    }

    const char* srcAh = (const char*)(g_Ah + (size_t)m0 * K);
    const char* srcAl = (const char*)(g_Al + (size_t)m0 * K);
    const char* srcBh = (const char*)(g_Bh + (size_t)n0 * K);
    const char* srcBl = (const char*)(g_Bl + (size_t)n0 * K);

    auto load_chunk = [&](int c, int st) {
        const uint32_t base = sbase + st * GM_STAGE;
        const size_t koff = (size_t)c * 128;
#pragma unroll
        for (int i = 0; i < 2; i++) {
            int idx = tid + i * 512;
            int row = idx >> 3;
            int g   = idx & 7;
            uint32_t off = row * 128 + ((g * 16) ^ ((row & 7) << 4));
            const size_t so = (size_t)row * K * 2 + koff + g * 16;
            CP_ASYNC16(base + GM_AH + off, srcAh + so);
            CP_ASYNC16(base + GM_AL + off, srcAl + so);
        }
#pragma unroll
        for (int i = 0; i < 4; i++) {
            int idx = tid + i * 512;
            int row = idx >> 3;
            int g   = idx & 7;
            uint32_t off = row * 128 + ((g * 16) ^ ((row & 7) << 4));
            const size_t so = (size_t)row * K * 2 + koff + g * 16;
            CP_ASYNC16(base + GM_BH + off, srcBh + so);
            CP_ASYNC16(base + GM_BL + off, srcBl + so);
        }
    };

    const int m0w = (wid & 1) * 64;
    const int n0w = (wid >> 1) * 32;

    uint32_t aBase[4];
    const int a_row_l = (lane & 15);
    const uint32_t a_klane = (lane >> 4) * 16;
#pragma unroll
    for (int mi = 0; mi < 4; mi++) {
        int row = m0w + mi * 16 + a_row_l;
        aBase[mi] = row * 128 + ((row & 7) << 4);
    }
    uint32_t bBase[2];
    const int b_row_l = ((lane >> 4) * 8) + (lane & 7);
    const uint32_t b_klane = ((lane >> 3) & 1) * 16;
#pragma unroll
    for (int nj = 0; nj < 2; nj++) {
        int row = n0w + nj * 16 + b_row_l;
        bBase[nj] = row * 128 + ((row & 7) << 4);
    }

    float c[4][4][4];
#pragma unroll
    for (int mi = 0; mi < 4; mi++)
#pragma unroll
        for (int ni = 0; ni < 4; ni++)
#pragma unroll
            for (int q = 0; q < 4; q++) c[mi][ni][q] = 0.f;

    load_chunk(0, 0); CP_COMMIT();
    if (nchunks > 1) { load_chunk(1, 1); CP_COMMIT(); }

    for (int ch = 0; ch < nchunks; ch++) {
        if (ch == nchunks - 1) CP_WAIT0(); else CP_WAIT1();
        __syncthreads();

        const uint32_t stb = sbase + (ch & 1) * GM_STAGE;
        const uint32_t bufA_h = stb + GM_AH;
        const uint32_t bufA_l = stb + GM_AL;
        const uint32_t bufB_h = stb + GM_BH;
        const uint32_t bufB_l = stb + GM_BL;

#pragma unroll
        for (int ks = 0; ks < 4; ks++) {
            const uint32_t kbA = ks * 32 + a_klane;
            const uint32_t kbB = ks * 32 + b_klane;
            uint32_t ah[4][4], al[4][4], bh[4][2], bl[4][2];
#pragma unroll
            for (int mi = 0; mi < 4; mi++) {
                ldsm4(ah[mi], (bufA_h + aBase[mi]) ^ kbA);
                ldsm4(al[mi], (bufA_l + aBase[mi]) ^ kbA);
            }
#pragma unroll
            for (int nj = 0; nj < 2; nj++) {
                uint32_t r[4];
                ldsm4(r, (bufB_h + bBase[nj]) ^ kbB);
                bh[nj * 2][0] = r[0]; bh[nj * 2][1] = r[1];
                bh[nj * 2 + 1][0] = r[2]; bh[nj * 2 + 1][1] = r[3];
                ldsm4(r, (bufB_l + bBase[nj]) ^ kbB);
                bl[nj * 2][0] = r[0]; bl[nj * 2][1] = r[1];
                bl[nj * 2 + 1][0] = r[2]; bl[nj * 2 + 1][1] = r[3];
            }
#pragma unroll
            for (int mi = 0; mi < 4; mi++)
#pragma unroll
                for (int ni = 0; ni < 4; ni++) {
                    mma16816(c[mi][ni], ah[mi], bh[ni]);
                    mma16816(c[mi][ni], ah[mi], bl[ni]);
                    mma16816(c[mi][ni], al[mi], bh[ni]);
                }
        }
        __syncthreads();
        if (ch + 2 < nchunks) { load_chunk(ch + 2, ch & 1); CP_COMMIT(); }
    }

    const int er = lane >> 2;
    const int ec = (lane & 3) * 2;
#pragma unroll
    for (int mi = 0; mi < 4; mi++) {
        int row0 = m0 + m0w + mi * 16 + er;
#pragma unroll
        for (int ni = 0; ni < 4; ni++) {
            int nloc = n0w + ni * 8 + ec;
            int coln = n0 + nloc;
            float b0 = bias_s[nloc], b1 = bias_s[nloc + 1];
            float* p0 = g_xg + (size_t)row0 * NG + coln;
            float* p1 = g_xg + (size_t)(row0 + 8) * NG + coln;
            *(float2*)p0 = make_float2(c[mi][ni][0] + b0, c[mi][ni][1] + b1);
            *(float2*)p1 = make_float2(c[mi][ni][2] + b0, c[mi][ni][3] + b1);
        }
    }
}

// ===========================================================================
// Tensor-core persistent recurrence (two-phase pipeline, active-prefix mask)
// + compacted xg addressing (row = cum[b] + t)
// + xg prefetch for step s+1 hoisted into the barrier-spin window.
// ===========================================================================
#define R_WHH 0                    // 32KB  Wh hi (8 chunk-tiles x 4KB)
#define R_WHL 32768                // 32KB  Wh lo
#define R_HH  65536                // 64KB  h hi (8 chunk-tiles x 8KB)
#define R_HL  131072               // 64KB  h lo
#define R_GS  196608               // float gs[32][68] = 8704B
#define R_CS  205312               // 512 floats
#define R_LS  207360               // 64 ints
#define R_XG  207616               // float xg_s[64][40] = 10240B
#define R_NB  217856               // int nbArr[512] = 2048B
#define R_CM  219904               // int cumArr[64] = 256B
#define R_SMEM 220160

__global__ void __launch_bounds__(256, 1)
lstm_layer_tc(const float* __restrict__ Whf, const float* __restrict__ Whb,
              const int* __restrict__ lengths, float* __restrict__ Y,
              int wsplit)
{
    extern __shared__ char smem[];
    const uint32_t sbase = smem_u32(smem);
    float* gs     = (float*)(smem + R_GS);
    float* cs     = (float*)(smem + R_CS);
    int*   ls     = (int*)(smem + R_LS);
    float* xg_s   = (float*)(smem + R_XG);
    int*   nbArr  = (int*)(smem + R_NB);
    int*   cumArr = (int*)(smem + R_CM);

    const int bid = blockIdx.x;
    const int dir = bid >> 6;
    const int n0  = (bid & 63) * 8;
    const float* Wh = dir ? Whb : Whf;

    const int tid  = threadIdx.x;
    const int wid  = tid >> 5;
    const int lane = tid & 31;

    // ---- one-time: Wh slice -> smem, split hi/lo, SW128-swizzled ----
    for (int idx = tid; idx < 8192; idx += 256) {
        int r  = idx >> 8;
        int kp = idx & 255;
        int j  = (r >> 3) * Hz + n0 + (r & 7);
        float2 v = *(const float2*)(Wh + (size_t)j * Hz + kp * 2);
        __nv_bfloat16 h0 = __float2bfloat16(v.x);
        __nv_bfloat16 h1 = __float2bfloat16(v.y);
        __nv_bfloat16 l0 = __float2bfloat16(v.x - __bfloat162float(h0));
        __nv_bfloat16 l1 = __float2bfloat16(v.y - __bfloat162float(h1));
        int c  = kp >> 5;
        int kb = (kp & 31) * 4;
        uint32_t off = c * 4096 + r * 128 + ((uint32_t)kb ^ (((uint32_t)r & 7) << 4));
        *(__nv_bfloat162*)(smem + R_WHH + off) = __halves2bfloat162(h0, h1);
        *(__nv_bfloat162*)(smem + R_WHL + off) = __halves2bfloat162(l0, l1);
    }
    for (int i = tid; i < 512; i += 256) cs[i] = 0.f;
    if (tid < 64) ls[tid] = lengths[tid];
    __syncthreads();
    // active-prefix table + compaction prefix
    for (int t = tid; t < 512; t += 256) {
        int cnt = 0;
#pragma unroll 16
        for (int b = 0; b < 64; b++) cnt += (ls[b] > t) ? 1 : 0;
        nbArr[t] = cnt;
    }
    if (tid < 64) {
        int c = 0;
        for (int bp = 0; bp < 64; bp++) c += (bp < tid) ? ls[bp] : 0;
        cumArr[tid] = c;
    }
    __syncthreads();

    // warp tiling: 4m x 2n; warp tile m16 x n16
    const int m0w = (wid & 3) * 16;
    const int n0w = (wid >> 2) * 16;
    const int a_row = m0w + (lane & 15);
    const uint32_t a_klane = (lane >> 4) * 16;
    const int b_row = n0w + ((lane >> 4) * 8) + (lane & 7);
    const uint32_t b_klane = ((lane >> 3) & 1) * 16;
    const uint32_t aOff = a_row * 128 + (((uint32_t)a_row & 7) << 4);
    const uint32_t bOff = b_row * 128 + (((uint32_t)b_row & 7) << 4);

    // xg prefetch: compacted row = cumArr[b] + t
    auto prefetch_xg = [&](int tt, int nbb) {
#pragma unroll
        for (int i = 0; i < 2; i++) {
            int e = tid + i * 256;
            int b = e >> 3;
            if (b < nbb) {
                int g  = (e >> 1) & 3;
                int hf = e & 1;
                uint32_t dst = sbase + R_XG + (b * 40 + g * 8 + hf * 4) * 4;
                const float* src = g_xg + (size_t)(cumArr[b] + tt) * NG
                                 + (size_t)dir * G4 + n0 + g * Hz + hf * 4;
                CP_ASYNC16(dst, src);
            }
        }
    };

    // prefetch xg for s = 0
    {
        int t0 = dir ? (Tz - 1) : 0;
        prefetch_xg(t0, nbArr[t0]);
    }
    CP_COMMIT();

    for (int s = 0; s < Tz; s++) {
        const int t   = dir ? (Tz - 1 - s) : s;
        const int par = s & 1;
        const int nb  = nbArr[t];
        const int nbr = (nb + 15) & ~15;
        const __nv_bfloat16* hh = g_hh[par] + dir * Bz * Hz;
        const __nv_bfloat16* hl = g_hl[par] + dir * Bz * Hz;
        __nv_bfloat16* hho = g_hh[par ^ 1] + dir * Bz * Hz;
        __nv_bfloat16* hlo = g_hl[par ^ 1] + dir * Bz * Hz;

        // group: h chunks 0-3 (hi+lo)
        for (int idx = tid; idx < nbr * 32; idx += 256) {
            int b = idx >> 5;
            int q = idx & 31;
            int c = q >> 3;               // 0..3
            int g = q & 7;
            uint32_t off = c * 8192 + b * 128 + (((uint32_t)g * 16) ^ (((uint32_t)b & 7) << 4));
            CP_ASYNC16(sbase + R_HH + off,
                       (const char*)(hh + (size_t)b * Hz + c * 64) + g * 16);
            CP_ASYNC16(sbase + R_HL + off,
                       (const char*)(hl + (size_t)b * Hz + c * 64) + g * 16);
        }
        CP_COMMIT();
        // group: h chunks 4-7 (hi+lo)
        for (int idx = tid; idx < nbr * 32; idx += 256) {
            int b = idx >> 5;
            int q = idx & 31;
            int c = (q >> 3) + 4;         // 4..7
            int g = q & 7;
            uint32_t off = c * 8192 + b * 128 + (((uint32_t)g * 16) ^ (((uint32_t)b & 7) << 4));
            CP_ASYNC16(sbase + R_HH + off,
                       (const char*)(hh + (size_t)b * Hz + c * 64) + g * 16);
            CP_ASYNC16(sbase + R_HL + off,
                       (const char*)(hl + (size_t)b * Hz + c * 64) + g * 16);
        }
        CP_COMMIT();

        float c0[4] = {0.f, 0.f, 0.f, 0.f};
        float c1[4] = {0.f, 0.f, 0.f, 0.f};
        const bool wactive = (m0w < nbr);

        CP_WAIT1();     // xg + h chunks 0-3 complete (h 4-7 may pend)
        __syncthreads();
        if (wactive) {
            for (int ch = 0; ch < 4; ch++) {
                const uint32_t ahB = sbase + R_HH + ch * 8192 + aOff;
                const uint32_t alB = sbase + R_HL + ch * 8192 + aOff;
                const uint32_t bhB = sbase + R_WHH + ch * 4096 + bOff;
                const uint32_t blB = bhB + 32768;
#pragma unroll
                for (int ks = 0; ks < 4; ks++) {
                    const uint32_t kA = ks * 32 + a_klane;
                    const uint32_t kB = ks * 32 + b_klane;
                    uint32_t ah[4], al[4], bhh[4], bll[4];
                    ldsm4(ah,  ahB ^ kA);
                    ldsm4(al,  alB ^ kA);
                    ldsm4(bhh, bhB ^ kB);
                    ldsm4(bll, blB ^ kB);
                    mma16816(c0, ah, bhh);
                    mma16816(c0, ah, bll);
                    mma16816(c0, al, bhh);
                    mma16816(c1, ah, bhh + 2);
                    mma16816(c1, ah, bll + 2);
                    mma16816(c1, al, bhh + 2);
                }
            }
        }
        CP_WAIT0();
        __syncthreads();
        if (wactive) {
            for (int ch = 4; ch < 8; ch++) {
                const uint32_t ahB = sbase + R_HH + ch * 8192 + aOff;
                const uint32_t alB = sbase + R_HL + ch * 8192 + aOff;
                const uint32_t bhB = sbase + R_WHH + ch * 4096 + bOff;
                const uint32_t blB = bhB + 32768;
#pragma unroll
                for (int ks = 0; ks < 4; ks++) {
                    const uint32_t kA = ks * 32 + a_klane;
                    const uint32_t kB = ks * 32 + b_klane;
                    uint32_t ah[4], al[4], bhh[4], bll[4];
                    ldsm4(ah,  ahB ^ kA);
                    ldsm4(al,  alB ^ kA);
                    ldsm4(bhh, bhB ^ kB);
                    ldsm4(bll, blB ^ kB);
                    mma16816(c0, ah, bhh);
                    mma16816(c0, ah, bll);
                    mma16816(c0, al, bhh);
                    mma16816(c1, ah, bhh + 2);
                    mma16816(c1, ah, bll + 2);
                    mma16816(c1, al, bhh + 2);
                }
            }
            // write fragments to gs[col(r)][row(b)]
            const int row0 = m0w + (lane >> 2);
            const int col0 = n0w + (lane & 3) * 2;
            gs[(col0)     * 68 + row0]     = c0[0];
            gs[(col0 + 1) * 68 + row0]     = c0[1];
            gs[(col0)     * 68 + row0 + 8] = c0[2];
            gs[(col0 + 1) * 68 + row0 + 8] = c0[3];
            gs[(col0 + 8) * 68 + row0]     = c1[0];
            gs[(col0 + 9) * 68 + row0]     = c1[1];
            gs[(col0 + 8) * 68 + row0 + 8] = c1[2];
            gs[(col0 + 9) * 68 + row0 + 8] = c1[3];
        }
        __syncthreads();

        // output phase: active rows only
        for (int o = tid; o < nb * 8; o += 256) {
            int nl = o & 7;
            int b  = o >> 3;
            int n  = n0 + nl;
            const float* xr = xg_s + b * 40;
            float gi = gs[(0 * 8 + nl) * 68 + b] + xr[0 * 8 + nl];
            float gf = gs[(1 * 8 + nl) * 68 + b] + xr[1 * 8 + nl];
            float gg = gs[(2 * 8 + nl) * 68 + b] + xr[2 * 8 + nl];
            float go = gs[(3 * 8 + nl) * 68 + b] + xr[3 * 8 + nl];
            float iv = 1.f / (1.f + expf(-gi));
            float fv = 1.f / (1.f + expf(-gf));
            float gv = tanhf(gg);
            float ov = 1.f / (1.f + expf(-go));
            float cn = fv * cs[o] + iv * gv;
            float hn = ov * tanhf(cn);
            cs[o] = cn;
            __nv_bfloat16 hhi = __float2bfloat16(hn);
            hho[b * Hz + n] = hhi;
            hlo[b * Hz + n] = __float2bfloat16(hn - __bfloat162float(hhi));
            if (wsplit) {
                size_t yo = (size_t)(cumArr[b] + t) * 1024 + (size_t)dir * Hz + n;
                __nv_bfloat16 yh = __float2bfloat16(hn);
                g_Ah[yo] = yh;
                g_Al[yo] = __float2bfloat16(hn - __bfloat162float(yh));
            } else {
                Y[((size_t)b * Tz + t) * (2 * Hz) + (size_t)dir * Hz + n] = hn;
            }
            if (t == (dir ? 0 : (ls[b] - 1))) {
                g_hf[dir * Bz * Hz + b * Hz + n] = hn;
                g_c [dir * Bz * Hz + b * Hz + n] = cn;
            }
        }
        __syncthreads();    // output phase done; xg_s free for next prefetch

        if (s < Tz - 1) {
            // prefetch xg for step s+1 during the barrier-spin window
            const int t2 = dir ? (Tz - 2 - s) : (s + 1);
            prefetch_xg(t2, nbArr[t2]);
            CP_COMMIT();
            if (tid == 0) {
                unsigned* ctr = &g_bar2[dir * 32];
                __threadfence();
                atomicAdd(ctr, 1u);
                const unsigned target = (unsigned)(s + 1) * 64;
                for (;;) {
                    unsigned v;
                    asm volatile("ld.acquire.gpu.global.u32 %0, [%1];"
                                 : "=r"(v) : "l"(ctr));
                    if (v >= target) break;
                    __nanosleep(32);
                }
            }
            __syncthreads();
        }
    }

    // self-resetting exit
    __threadfence();
    __syncthreads();
    if (tid == 0) {
        unsigned d = atomicAdd(&g_done, 1u);
        if (d == NCTA - 1) {
            atomicExch(&g_bar2[0], 0u);
            atomicExch(&g_bar2[32], 0u);
            atomicExch(&g_done, 0u);
            __threadfence();
        }
    }
}

// copy final states into d_out hN/cN sections
__global__ void copy_states(float* __restrict__ out_h, float* __restrict__ out_c)
{
    int i = blockIdx.x * blockDim.x + threadIdx.x;
    if (i < 2 * Bz * Hz) {
        out_h[i] = g_hf[i];
        out_c[i] = g_c[i];
    }
}

extern "C" void kernel_launch(void* const* d_in, const int* in_sizes, int n_in,
                              void* d_out, int out_size)
{
    const float* x      = (const float*)d_in[0];
    const int*  lengths = (const int*)  d_in[1];
    const float* Wi_f0 = (const float*)d_in[2];
    const float* Wh_f0 = (const float*)d_in[3];
    const float* b_f0  = (const float*)d_in[4];
    const float* Wi_b0 = (const float*)d_in[5];
    const float* Wh_b0 = (const float*)d_in[6];
    const float* b_b0  = (const float*)d_in[7];
    const float* Wi_f1 = (const float*)d_in[8];
    const float* Wh_f1 = (const float*)d_in[9];
    const float* b_f1  = (const float*)d_in[10];
    const float* Wi_b1 = (const float*)d_in[11];
    const float* Wh_b1 = (const float*)d_in[12];
    const float* b_b1  = (const float*)d_in[13];
    float* out = (float*)d_out;

    cudaFuncSetAttribute(lstm_layer_tc,
                         cudaFuncAttributeMaxDynamicSharedMemorySize, R_SMEM);
    cudaFuncSetAttribute(gemm_mma,
                         cudaFuncAttributeMaxDynamicSharedMemorySize, GM_SMEM);

    __nv_bfloat16 *ahp, *alp, *hhp, *hlp;
    cudaGetSymbolAddress((void**)&ahp,  g_Ah);
    cudaGetSymbolAddress((void**)&alp,  g_Al);
    cudaGetSymbolAddress((void**)&hhp,  g_hh);
    cudaGetSymbolAddress((void**)&hlp,  g_hl);

    const dim3 gemm_grid(NG / 256, Mz / 128);
    const int  copy_blocks = (2 * Bz * Hz + 255) / 256;
    const size_t hbbytes = sizeof(__nv_bfloat16) * 2 * 2 * Bz * Hz;

    // masked Y elements are never written by the recurrence: pre-zero them
    cudaMemsetAsync(out, 0, XOUT * sizeof(float));

    // ---- layer 0 (K = 512, compacted M) ----
    cudaMemsetAsync(hhp, 0, hbbytes);
    cudaMemsetAsync(hlp, 0, hbbytes);
    split_x<<<dim3(Mz, 1), 128>>>(x, Dz, lengths, ahp, alp);
    split_w<<<dim3(NG, 1), 128>>>(Wi_f0, Wi_b0, Dz);
    gemm_mma<<<gemm_grid, 512, GM_SMEM>>>(Dz, b_f0, b_b0, lengths);
    lstm_layer_tc<<<NCTA, 256, R_SMEM>>>(Wh_f0, Wh_b0, lengths, out, 1);
    copy_states<<<copy_blocks, 256>>>(out + XOUT,
                                      out + XOUT + 4 * Bz * Hz);

    // ---- layer 1 (K = 1024; compacted A written by layer-0 recurrence) ----
    cudaMemsetAsync(hhp, 0, hbbytes);
    cudaMemsetAsync(hlp, 0, hbbytes);
    split_w<<<dim3(NG, 2), 128>>>(Wi_f1, Wi_b1, 2 * Hz);
    gemm_mma<<<gemm_grid, 512, GM_SMEM>>>(2 * Hz, b_f1, b_b1, lengths);
    lstm_layer_tc<<<NCTA, 256, R_SMEM>>>(Wh_f1, Wh_b1, lengths, out, 0);
    copy_states<<<copy_blocks, 256>>>(out + XOUT + 2 * Bz * Hz,
                                      out + XOUT + 4 * Bz * Hz + 2 * Bz * Hz);
}